// round 2
// baseline (speedup 1.0000x reference)
#include <cuda_runtime.h>
#include <math.h>

#define BATCH 8
#define SEQ   2048
#define DIM   512
#define NCHUNK 16   // i-chunks for column stats

static const float LN_EPS_F = 1e-5f;
static const float EPS_F    = 1e-8f;

// ---------------- scratch (static device globals; no allocation) ----------------
__device__ float g_xn  [(size_t)BATCH * SEQ * DIM];
__device__ float g_cn  [(size_t)BATCH * SEQ * DIM];
__device__ float g_q   [(size_t)BATCH * SEQ * DIM];
__device__ float g_k   [(size_t)BATCH * SEQ * DIM];
__device__ float g_v   [(size_t)BATCH * SEQ * DIM];
__device__ float g_dots[(size_t)BATCH * SEQ * SEQ];
__device__ float g_pm  [BATCH * NCHUNK * SEQ];
__device__ float g_ps  [BATCH * NCHUNK * SEQ];
__device__ float g_cm  [BATCH * SEQ];
__device__ float g_csi [BATCH * SEQ];
__device__ float g_rinv[BATCH * SEQ];

// ---------------- LayerNorm: one block per row of 512 ----------------
__global__ void __launch_bounds__(128) ln_kernel(const float* __restrict__ x,
                                                 const float* __restrict__ g,
                                                 const float* __restrict__ b,
                                                 float* __restrict__ y) {
    int row = blockIdx.x;
    int t = threadIdx.x;  // 128 threads * 4 floats = 512
    const float4* xr = (const float4*)(x + (size_t)row * DIM);
    float4 v = xr[t];
    float s  = v.x + v.y + v.z + v.w;
    float ss = v.x*v.x + v.y*v.y + v.z*v.z + v.w*v.w;
    __shared__ float sh[8];
    #pragma unroll
    for (int o = 16; o > 0; o >>= 1) {
        s  += __shfl_down_sync(0xffffffffu, s, o);
        ss += __shfl_down_sync(0xffffffffu, ss, o);
    }
    if ((t & 31) == 0) { sh[t >> 5] = s; sh[4 + (t >> 5)] = ss; }
    __syncthreads();
    float fs  = sh[0] + sh[1] + sh[2] + sh[3];
    float fss = sh[4] + sh[5] + sh[6] + sh[7];
    float mu  = fs * (1.0f / DIM);
    float var = fss * (1.0f / DIM) - mu * mu;
    float rstd = rsqrtf(var + LN_EPS_F);
    float4 gv = ((const float4*)g)[t];
    float4 bv = ((const float4*)b)[t];
    float4 o;
    o.x = (v.x - mu) * rstd * gv.x + bv.x;
    o.y = (v.y - mu) * rstd * gv.y + bv.y;
    o.z = (v.z - mu) * rstd * gv.z + bv.z;
    o.w = (v.w - mu) * rstd * gv.w + bv.w;
    ((float4*)(y + (size_t)row * DIM))[t] = o;
}

// ---------------- generic 128x128x8 SGEMM, 256 threads, 8x8 per thread ----------------
// TB=false: C[M,N] = alpha * A[M,K] @ B[K,N]   (+bias[N]) (*rowscale[z*M+row])
// TB=true : C[M,N] = alpha * A[M,K] @ B[N,K]^T
// All dims assumed multiples of tile sizes (true for all calls here).
template <bool TB>
__global__ void __launch_bounds__(256) sgemm_kernel(
    const float* __restrict__ A, const float* __restrict__ B, float* __restrict__ C,
    int M, int N, int K,
    size_t sA, size_t sB, size_t sC,
    float alpha,
    const float* __restrict__ bias,
    const float* __restrict__ rowscale)
{
    int z = blockIdx.z;
    A += (size_t)z * sA;
    B += (size_t)z * sB;
    C += (size_t)z * sC;
    int bm = blockIdx.y * 128;
    int bn = blockIdx.x * 128;

    __shared__ float As[8][128];
    __shared__ float Bs[8][128];

    int t = threadIdx.x;
    int aRow = t >> 1, aCol = (t & 1) * 4;        // A tile: 128 rows x 8 k
    int bRow = t >> 5, bCol = (t & 31) * 4;       // B tile (NN): 8 k x 128 cols
    int ty = t >> 4, tx = t & 15;
    int m0 = ty * 8, n0 = tx * 8;

    float acc[8][8];
    #pragma unroll
    for (int i = 0; i < 8; i++)
        #pragma unroll
        for (int j = 0; j < 8; j++) acc[i][j] = 0.0f;

    for (int k0 = 0; k0 < K; k0 += 8) {
        float4 av = *(const float4*)(A + (size_t)(bm + aRow) * K + k0 + aCol);
        As[aCol + 0][aRow] = av.x;
        As[aCol + 1][aRow] = av.y;
        As[aCol + 2][aRow] = av.z;
        As[aCol + 3][aRow] = av.w;
        if (TB) {
            float4 bvv = *(const float4*)(B + (size_t)(bn + aRow) * K + k0 + aCol);
            Bs[aCol + 0][aRow] = bvv.x;
            Bs[aCol + 1][aRow] = bvv.y;
            Bs[aCol + 2][aRow] = bvv.z;
            Bs[aCol + 3][aRow] = bvv.w;
        } else {
            float4 bvv = *(const float4*)(B + (size_t)(k0 + bRow) * N + bn + bCol);
            *(float4*)&Bs[bRow][bCol] = bvv;
        }
        __syncthreads();
        #pragma unroll
        for (int kk = 0; kk < 8; kk++) {
            float a[8], bb[8];
            float4 a0 = *(const float4*)&As[kk][m0];
            float4 a1 = *(const float4*)&As[kk][m0 + 4];
            float4 b0 = *(const float4*)&Bs[kk][n0];
            float4 b1 = *(const float4*)&Bs[kk][n0 + 4];
            a[0]=a0.x; a[1]=a0.y; a[2]=a0.z; a[3]=a0.w;
            a[4]=a1.x; a[5]=a1.y; a[6]=a1.z; a[7]=a1.w;
            bb[0]=b0.x; bb[1]=b0.y; bb[2]=b0.z; bb[3]=b0.w;
            bb[4]=b1.x; bb[5]=b1.y; bb[6]=b1.z; bb[7]=b1.w;
            #pragma unroll
            for (int i = 0; i < 8; i++)
                #pragma unroll
                for (int j = 0; j < 8; j++)
                    acc[i][j] = fmaf(a[i], bb[j], acc[i][j]);
        }
        __syncthreads();
    }

    #pragma unroll
    for (int i = 0; i < 8; i++) {
        int row = bm + m0 + i;
        float rs = rowscale ? rowscale[(size_t)z * M + row] : 1.0f;
        #pragma unroll
        for (int j = 0; j < 8; j += 4) {
            float4 o;
            o.x = acc[i][j + 0] * alpha;
            o.y = acc[i][j + 1] * alpha;
            o.z = acc[i][j + 2] * alpha;
            o.w = acc[i][j + 3] * alpha;
            if (bias) {
                o.x += bias[bn + n0 + j + 0];
                o.y += bias[bn + n0 + j + 1];
                o.z += bias[bn + n0 + j + 2];
                o.w += bias[bn + n0 + j + 3];
            }
            o.x *= rs; o.y *= rs; o.z *= rs; o.w *= rs;
            *(float4*)(C + (size_t)row * N + bn + n0 + j) = o;
        }
    }
}

// ---------------- column stats stage 1: per (b, chunk, j) partial max & sumexp ----------------
__global__ void __launch_bounds__(128) colstats1_kernel() {
    int j = blockIdx.x * 128 + threadIdx.x;
    int c = blockIdx.y;
    int z = blockIdx.z;
    const float* p = g_dots + ((size_t)z * SEQ + (size_t)c * (SEQ / NCHUNK)) * SEQ + j;
    float m = -1e30f;
    #pragma unroll 4
    for (int r = 0; r < SEQ / NCHUNK; r++)
        m = fmaxf(m, p[(size_t)r * SEQ]);
    float s = 0.0f;
    #pragma unroll 4
    for (int r = 0; r < SEQ / NCHUNK; r++)
        s += __expf(p[(size_t)r * SEQ] - m);
    g_pm[((size_t)z * NCHUNK + c) * SEQ + j] = m;
    g_ps[((size_t)z * NCHUNK + c) * SEQ + j] = s;
}

// ---------------- column stats stage 2: combine chunks -> colmax, 1/colsum ----------------
__global__ void __launch_bounds__(256) colstats2_kernel() {
    int j = blockIdx.x * 256 + threadIdx.x;
    int z = blockIdx.y;
    float m = -1e30f;
    #pragma unroll
    for (int c = 0; c < NCHUNK; c++)
        m = fmaxf(m, g_pm[((size_t)z * NCHUNK + c) * SEQ + j]);
    float s = 0.0f;
    #pragma unroll
    for (int c = 0; c < NCHUNK; c++)
        s += g_ps[((size_t)z * NCHUNK + c) * SEQ + j] *
             __expf(g_pm[((size_t)z * NCHUNK + c) * SEQ + j] - m);
    g_cm [(size_t)z * SEQ + j] = m;
    g_csi[(size_t)z * SEQ + j] = 1.0f / s;
}

// ---------------- row pass: overwrite dots with Araw = softmax+EPS, compute 1/(rowsum+EPS) ----------------
__global__ void __launch_bounds__(256) rowpass_kernel() {
    int i = blockIdx.x;
    int z = blockIdx.y;
    int t = threadIdx.x;
    float* row = g_dots + ((size_t)z * SEQ + i) * SEQ;
    const float* cm = g_cm  + (size_t)z * SEQ;
    const float* ci = g_csi + (size_t)z * SEQ;
    float acc = 0.0f;
    #pragma unroll 2
    for (int j = t; j < SEQ; j += 256) {
        float a = __expf(row[j] - cm[j]) * ci[j] + EPS_F;
        acc += a;
        row[j] = a;
    }
    __shared__ float sh[8];
    #pragma unroll
    for (int o = 16; o > 0; o >>= 1)
        acc += __shfl_down_sync(0xffffffffu, acc, o);
    if ((t & 31) == 0) sh[t >> 5] = acc;
    __syncthreads();
    if (t == 0) {
        float s = 0.0f;
        #pragma unroll
        for (int w = 0; w < 8; w++) s += sh[w];
        g_rinv[(size_t)z * SEQ + i] = 1.0f / (s + EPS_F);
    }
}

// ---------------- launch ----------------
extern "C" void kernel_launch(void* const* d_in, const int* in_sizes, int n_in,
                              void* d_out, int out_size) {
    const float* inputs  = (const float*)d_in[0];
    const float* context = (const float*)d_in[1];
    const float* gin  = (const float*)d_in[2];
    const float* bin  = (const float*)d_in[3];
    const float* gctx = (const float*)d_in[4];
    const float* bctx = (const float*)d_in[5];
    const float* Wq = (const float*)d_in[6];
    const float* bq = (const float*)d_in[7];
    const float* Wk = (const float*)d_in[8];
    const float* bk = (const float*)d_in[9];
    const float* Wv = (const float*)d_in[10];
    const float* bv = (const float*)d_in[11];
    float* out = (float*)d_out;

    float *xn, *cn, *q, *k, *v, *dots, *rinv;
    cudaGetSymbolAddress((void**)&xn,   g_xn);
    cudaGetSymbolAddress((void**)&cn,   g_cn);
    cudaGetSymbolAddress((void**)&q,    g_q);
    cudaGetSymbolAddress((void**)&k,    g_k);
    cudaGetSymbolAddress((void**)&v,    g_v);
    cudaGetSymbolAddress((void**)&dots, g_dots);
    cudaGetSymbolAddress((void**)&rinv, g_rinv);

    // LayerNorms
    ln_kernel<<<BATCH * SEQ, 128>>>(inputs,  gin,  bin,  xn);
    ln_kernel<<<BATCH * SEQ, 128>>>(context, gctx, bctx, cn);

    // QKV projections: M=16384, N=512, K=512 (batch folded into M; W shared)
    {
        dim3 grid(DIM / 128, (BATCH * SEQ) / 128, 1);
        sgemm_kernel<false><<<grid, 256>>>(xn, Wq, q, BATCH * SEQ, DIM, DIM,
                                           0, 0, 0, 1.0f, bq, nullptr);
        sgemm_kernel<false><<<grid, 256>>>(cn, Wk, k, BATCH * SEQ, DIM, DIM,
                                           0, 0, 0, 1.0f, bk, nullptr);
        sgemm_kernel<false><<<grid, 256>>>(cn, Wv, v, BATCH * SEQ, DIM, DIM,
                                           0, 0, 0, 1.0f, bv, nullptr);
    }

    // dots = q @ k^T * scale   (batched)
    {
        float scale = 1.0f / sqrtf((float)DIM);
        dim3 grid(SEQ / 128, SEQ / 128, BATCH);
        sgemm_kernel<true><<<grid, 256>>>(q, k, dots, SEQ, SEQ, DIM,
                                          (size_t)SEQ * DIM, (size_t)SEQ * DIM,
                                          (size_t)SEQ * SEQ, scale, nullptr, nullptr);
    }

    // column softmax stats (over i for each (b,j))
    colstats1_kernel<<<dim3(SEQ / 128, NCHUNK, BATCH), 128>>>();
    colstats2_kernel<<<dim3(SEQ / 256, BATCH), 256>>>();

    // rowpass: dots -> Araw = softmax+EPS, rinv = 1/(rowsum+EPS)
    rowpass_kernel<<<dim3(SEQ, BATCH), 256>>>();

    // updates = rinv[i] * (Araw @ v)   (batched)
    {
        dim3 grid(DIM / 128, SEQ / 128, BATCH);
        sgemm_kernel<false><<<grid, 256>>>(dots, v, out, SEQ, DIM, SEQ,
                                           (size_t)SEQ * SEQ, (size_t)SEQ * DIM,
                                           (size_t)SEQ * DIM, 1.0f, nullptr, rinv);
    }
}

// round 4
// speedup vs baseline: 3.4323x; 3.4323x over previous
#include <cuda_runtime.h>
#include <cuda_fp16.h>
#include <math.h>
#include <stdint.h>

#define BATCH 8
#define SEQ   2048
#define DIM   512
#define NCHUNK 16
#define KC_QKV (3*DIM)   // 1536
#define KC_AV  (3*SEQ)   // 6144

static const float LN_EPS_F = 1e-5f;
static const float EPS_F    = 1e-8f;

// ---------------- scratch (static device globals; no allocation) ----------------
__device__ __align__(256) __half g_xncat[(size_t)BATCH * SEQ * KC_QKV];
__device__ __align__(256) __half g_cncat[(size_t)BATCH * SEQ * KC_QKV];
__device__ __align__(256) __half g_wqcat[(size_t)DIM * KC_QKV];
__device__ __align__(256) __half g_wkcat[(size_t)DIM * KC_QKV];
__device__ __align__(256) __half g_wvcat[(size_t)DIM * KC_QKV];
__device__ __align__(256) __half g_qcat [(size_t)BATCH * SEQ * KC_QKV];
__device__ __align__(256) __half g_kcat [(size_t)BATCH * SEQ * KC_QKV];
__device__ __align__(256) __half g_vtcat[(size_t)BATCH * DIM * KC_AV];
__device__ __align__(256) __half g_acat [(size_t)BATCH * SEQ * KC_AV];
__device__ __align__(256) float  g_dots [(size_t)BATCH * SEQ * SEQ];
__device__ float g_pm  [BATCH * NCHUNK * SEQ];
__device__ float g_ps  [BATCH * NCHUNK * SEQ];
__device__ float g_cm  [BATCH * SEQ];
__device__ float g_csi [BATCH * SEQ];
__device__ float g_rinv[BATCH * SEQ];

// ---------------- PTX helpers (baseline compute_103-safe) ----------------
__device__ __forceinline__ uint32_t smem_u32(const void* p) {
    uint32_t a;
    asm("{ .reg .u64 t; cvta.to.shared.u64 t, %1; cvt.u32.u64 %0, t; }" : "=r"(a) : "l"(p));
    return a;
}
__device__ __forceinline__ void cp_async16(uint32_t d, const void* g) {
    asm volatile("cp.async.cg.shared.global [%0], [%1], 16;" :: "r"(d), "l"(g));
}
__device__ __forceinline__ void cp_commit() {
    asm volatile("cp.async.commit_group;" ::: "memory");
}
template <int N>
__device__ __forceinline__ void cp_wait() {
    asm volatile("cp.async.wait_group %0;" :: "n"(N) : "memory");
}
__device__ __forceinline__ void ldsm4(uint32_t& r0, uint32_t& r1, uint32_t& r2, uint32_t& r3,
                                      uint32_t addr) {
    asm volatile("ldmatrix.sync.aligned.m8n8.x4.shared.b16 {%0,%1,%2,%3}, [%4];"
                 : "=r"(r0), "=r"(r1), "=r"(r2), "=r"(r3) : "r"(addr));
}
__device__ __forceinline__ void mma16816(float* c, const uint32_t* a, uint32_t b0, uint32_t b1) {
    asm volatile(
        "mma.sync.aligned.m16n8k16.row.col.f32.f16.f16.f32 "
        "{%0,%1,%2,%3}, {%4,%5,%6,%7}, {%8,%9}, {%0,%1,%2,%3};"
        : "+f"(c[0]), "+f"(c[1]), "+f"(c[2]), "+f"(c[3])
        : "r"(a[0]), "r"(a[1]), "r"(a[2]), "r"(a[3]), "r"(b0), "r"(b1));
}

__device__ __forceinline__ void split2h(float x, __half& h, __half& l) {
    h = __float2half_rn(x);
    l = __float2half_rn(x - __half2float(h));
}

// ---------------- HMMA split-fp16 GEMM ----------------
// C[M,N] = A[M,Kc] @ B[N,Kc]^T  (A,B fp16 K-major)
// pattern 0: outf[row*N+col] = (acc*alpha + bias_col[col] + bias_row[row]) * rowscale[z*M+row]
// pattern 1: outh row length 3N, segments [h|l|h]
// pattern 2: outh row length 3N, segments [h|h|l]
#define BK 32
#define STAGES 4
#define PADH 40              // halves per smem row (80 bytes)
#define A_STAGE (128 * PADH * 2)
#define STAGE_BYTES (2 * A_STAGE)
#define GEMM_DSMEM (STAGES * STAGE_BYTES)

__global__ void __launch_bounds__(256, 2) gemm_h(
    const __half* __restrict__ A, const __half* __restrict__ B,
    int M, int N, int Kc,
    size_t sA, size_t sB, size_t sC,
    float alpha,
    const float* __restrict__ bias_col, const float* __restrict__ bias_row,
    const float* __restrict__ rowscale,
    float* __restrict__ outf, __half* __restrict__ outh, int pattern)
{
    extern __shared__ char dyn[];
    uint32_t dynb = smem_u32(dyn);

    int z = blockIdx.z;
    const __half* Ab = A + (size_t)z * sA + (size_t)(blockIdx.y * 128) * Kc;
    const __half* Bb = B + (size_t)z * sB + (size_t)(blockIdx.x * 128) * Kc;
    int bm = blockIdx.y * 128;
    int bn = blockIdx.x * 128;

    int t = threadIdx.x;
    int wid = t >> 5, lane = t & 31;
    int wm = wid & 1;        // 2 warps over M (64 rows each)
    int wn = wid >> 1;       // 4 warps over N (32 cols each)

    float acc[4][4][4];
    #pragma unroll
    for (int i = 0; i < 4; i++)
        #pragma unroll
        for (int j = 0; j < 4; j++)
            #pragma unroll
            for (int r = 0; r < 4; r++) acc[i][j][r] = 0.0f;

    int nkb = Kc / BK;

    auto issue = [&](int kb) {
        int slot = kb & (STAGES - 1);
        uint32_t sa = dynb + slot * STAGE_BYTES;
        uint32_t sb = sa + A_STAGE;
        int kh = kb * BK;
        #pragma unroll
        for (int i = 0; i < 2; i++) {
            int idx = t + 256 * i;
            int row = idx >> 2, c = idx & 3;
            cp_async16(sa + row * 80 + c * 16, Ab + (size_t)row * Kc + kh + c * 8);
        }
        #pragma unroll
        for (int i = 0; i < 2; i++) {
            int idx = t + 256 * i;
            int row = idx >> 2, c = idx & 3;
            cp_async16(sb + row * 80 + c * 16, Bb + (size_t)row * Kc + kh + c * 8);
        }
    };

    issue(0); cp_commit();
    issue(1); cp_commit();
    issue(2); cp_commit();

    // fragment smem addresses (per-lane constants except slot/kstep offsets)
    uint32_t a_lane = (uint32_t)((wm * 64 + (lane & 15)) * 80 + ((lane >> 4) * 8) * 2);
    uint32_t b_lane = (uint32_t)(A_STAGE +
                       (wn * 32 + (lane & 7) + (lane >> 4) * 8) * 80 +
                       (((lane >> 3) & 1) * 8) * 2);

    for (int kb = 0; kb < nkb; kb++) {
        cp_wait<STAGES - 2>();
        __syncthreads();
        if (kb + STAGES - 1 < nkb) issue(kb + STAGES - 1);
        cp_commit();

        uint32_t sbase = dynb + (kb & (STAGES - 1)) * STAGE_BYTES;
        #pragma unroll
        for (int ks = 0; ks < 2; ks++) {
            uint32_t af[4][4];
            uint32_t bf[2][4];
            #pragma unroll
            for (int mi = 0; mi < 4; mi++)
                ldsm4(af[mi][0], af[mi][1], af[mi][2], af[mi][3],
                      sbase + a_lane + mi * (16 * 80) + ks * 32);
            #pragma unroll
            for (int g = 0; g < 2; g++)
                ldsm4(bf[g][0], bf[g][1], bf[g][2], bf[g][3],
                      sbase + b_lane + g * (16 * 80) + ks * 32);
            #pragma unroll
            for (int mi = 0; mi < 4; mi++)
                #pragma unroll
                for (int ni = 0; ni < 4; ni++)
                    mma16816(acc[mi][ni], af[mi],
                             bf[ni >> 1][(ni & 1) * 2], bf[ni >> 1][(ni & 1) * 2 + 1]);
        }
        __syncthreads();
    }

    // ---------------- epilogue ----------------
    int r_lane = lane >> 2;
    int c_lane = (lane & 3) * 2;
    #pragma unroll
    for (int mi = 0; mi < 4; mi++) {
        #pragma unroll
        for (int ni = 0; ni < 4; ni++) {
            int row = bm + wm * 64 + mi * 16 + r_lane;
            int col = bn + wn * 32 + ni * 8 + c_lane;
            float* a4 = acc[mi][ni];
            float bc0 = bias_col ? bias_col[col]     : 0.0f;
            float bc1 = bias_col ? bias_col[col + 1] : 0.0f;
            #pragma unroll
            for (int h = 0; h < 2; h++) {  // rows row, row+8
                int rr = row + h * 8;
                float br = bias_row ? bias_row[rr] : 0.0f;
                float v0 = a4[h * 2 + 0] * alpha + bc0 + br;
                float v1 = a4[h * 2 + 1] * alpha + bc1 + br;
                if (pattern == 0) {
                    float rs = rowscale ? rowscale[(size_t)z * M + rr] : 1.0f;
                    float2 o = make_float2(v0 * rs, v1 * rs);
                    *(float2*)(outf + (size_t)z * sC + (size_t)rr * N + col) = o;
                } else {
                    __half h0, l0, h1, l1;
                    split2h(v0, h0, l0);
                    split2h(v1, h1, l1);
                    __half* ob = outh + (size_t)z * sC + (size_t)rr * (3 * N) + col;
                    __half2 hh = __halves2half2(h0, h1);
                    __half2 ll = __halves2half2(l0, l1);
                    *(__half2*)(ob)         = hh;
                    *(__half2*)(ob + N)     = (pattern == 1) ? ll : hh;
                    *(__half2*)(ob + 2 * N) = (pattern == 1) ? hh : ll;
                }
            }
        }
    }
}

// ---------------- LayerNorm + split-cat pattern A: out [rows, 1536] fp16 ----
__global__ void __launch_bounds__(128) ln_cat_kernel(const float* __restrict__ x,
                                                     const float* __restrict__ g,
                                                     const float* __restrict__ b,
                                                     __half* __restrict__ y) {
    int row = blockIdx.x;
    int t = threadIdx.x;
    float4 v = ((const float4*)(x + (size_t)row * DIM))[t];
    float s  = v.x + v.y + v.z + v.w;
    float ss = v.x*v.x + v.y*v.y + v.z*v.z + v.w*v.w;
    __shared__ float sh[8];
    #pragma unroll
    for (int o = 16; o > 0; o >>= 1) {
        s  += __shfl_down_sync(0xffffffffu, s, o);
        ss += __shfl_down_sync(0xffffffffu, ss, o);
    }
    if ((t & 31) == 0) { sh[t >> 5] = s; sh[4 + (t >> 5)] = ss; }
    __syncthreads();
    float fs  = sh[0] + sh[1] + sh[2] + sh[3];
    float fss = sh[4] + sh[5] + sh[6] + sh[7];
    float mu  = fs * (1.0f / DIM);
    float var = fss * (1.0f / DIM) - mu * mu;
    float rstd = rsqrtf(var + LN_EPS_F);
    float4 gv = ((const float4*)g)[t];
    float4 bv = ((const float4*)b)[t];
    float o0 = (v.x - mu) * rstd * gv.x + bv.x;
    float o1 = (v.y - mu) * rstd * gv.y + bv.y;
    float o2 = (v.z - mu) * rstd * gv.z + bv.z;
    float o3 = (v.w - mu) * rstd * gv.w + bv.w;
    __half h0,h1,h2,h3,l0,l1,l2,l3;
    split2h(o0,h0,l0); split2h(o1,h1,l1); split2h(o2,h2,l2); split2h(o3,h3,l3);
    __half* yb = y + (size_t)row * KC_QKV + t * 4;
    ((__half2*)yb)[0] = __halves2half2(h0, h1);
    ((__half2*)yb)[1] = __halves2half2(h2, h3);
    ((__half2*)(yb + DIM))[0] = __halves2half2(l0, l1);
    ((__half2*)(yb + DIM))[1] = __halves2half2(l2, l3);
    ((__half2*)(yb + 2*DIM))[0] = __halves2half2(h0, h1);
    ((__half2*)(yb + 2*DIM))[1] = __halves2half2(h2, h3);
}

// ---------------- weight transpose + split-cat pattern B: W[512,512] -> [512,1536]
__global__ void __launch_bounds__(256) tsplit_kernel(const float* __restrict__ in,
                                                     __half* __restrict__ out) {
    __shared__ float tile[32][33];
    int r0 = blockIdx.y * 32, c0 = blockIdx.x * 32;
    int tx = threadIdx.x & 31, ty = threadIdx.x >> 5;
    #pragma unroll
    for (int i = ty; i < 32; i += 8)
        tile[i][tx] = in[(size_t)(r0 + i) * DIM + c0 + tx];
    __syncthreads();
    #pragma unroll
    for (int i = ty; i < 32; i += 8) {
        float v = tile[tx][i];
        __half h, l;
        split2h(v, h, l);
        __half* o = out + (size_t)(c0 + i) * KC_QKV + r0 + tx;
        o[0] = h;
        o[DIM] = h;
        o[2 * DIM] = l;
    }
}

// ---------------- column stats (softmax over i) ----------------
__global__ void __launch_bounds__(128) colstats1_kernel() {
    int j = blockIdx.x * 128 + threadIdx.x;
    int c = blockIdx.y;
    int z = blockIdx.z;
    const float* p = g_dots + ((size_t)z * SEQ + (size_t)c * (SEQ / NCHUNK)) * SEQ + j;
    float m = -1e30f;
    #pragma unroll 4
    for (int r = 0; r < SEQ / NCHUNK; r++)
        m = fmaxf(m, p[(size_t)r * SEQ]);
    float s = 0.0f;
    #pragma unroll 4
    for (int r = 0; r < SEQ / NCHUNK; r++)
        s += __expf(p[(size_t)r * SEQ] - m);
    g_pm[((size_t)z * NCHUNK + c) * SEQ + j] = m;
    g_ps[((size_t)z * NCHUNK + c) * SEQ + j] = s;
}

__global__ void __launch_bounds__(256) colstats2_kernel() {
    int j = blockIdx.x * 256 + threadIdx.x;
    int z = blockIdx.y;
    float m = -1e30f;
    #pragma unroll
    for (int c = 0; c < NCHUNK; c++)
        m = fmaxf(m, g_pm[((size_t)z * NCHUNK + c) * SEQ + j]);
    float s = 0.0f;
    #pragma unroll
    for (int c = 0; c < NCHUNK; c++)
        s += g_ps[((size_t)z * NCHUNK + c) * SEQ + j] *
             __expf(g_pm[((size_t)z * NCHUNK + c) * SEQ + j] - m);
    g_cm [(size_t)z * SEQ + j] = m;
    g_csi[(size_t)z * SEQ + j] = 1.0f / s;
}

// ---------------- row pass: Araw=softmax+EPS -> acat (pattern A), rinv -----
__global__ void __launch_bounds__(256) rowpass_kernel() {
    int i = blockIdx.x;
    int z = blockIdx.y;
    int t = threadIdx.x;
    const float* row = g_dots + ((size_t)z * SEQ + i) * SEQ;
    const float* cm = g_cm  + (size_t)z * SEQ;
    const float* ci = g_csi + (size_t)z * SEQ;
    __half* ab = g_acat + ((size_t)z * SEQ + i) * KC_AV;
    float acc = 0.0f;
    #pragma unroll 2
    for (int j = t; j < SEQ; j += 256) {
        float a = __expf(row[j] - cm[j]) * ci[j] + EPS_F;
        acc += a;
        __half h, l;
        split2h(a, h, l);
        ab[j] = h;
        ab[SEQ + j] = l;
        ab[2 * SEQ + j] = h;
    }
    __shared__ float sh[8];
    #pragma unroll
    for (int o = 16; o > 0; o >>= 1)
        acc += __shfl_down_sync(0xffffffffu, acc, o);
    if ((t & 31) == 0) sh[t >> 5] = acc;
    __syncthreads();
    if (t == 0) {
        float s = 0.0f;
        #pragma unroll
        for (int w = 0; w < 8; w++) s += sh[w];
        g_rinv[(size_t)z * SEQ + i] = 1.0f / (s + EPS_F);
    }
}

// ---------------- launch ----------------
extern "C" void kernel_launch(void* const* d_in, const int* in_sizes, int n_in,
                              void* d_out, int out_size) {
    const float* inputs  = (const float*)d_in[0];
    const float* context = (const float*)d_in[1];
    const float* gin  = (const float*)d_in[2];
    const float* bin  = (const float*)d_in[3];
    const float* gctx = (const float*)d_in[4];
    const float* bctx = (const float*)d_in[5];
    const float* Wq = (const float*)d_in[6];
    const float* bq = (const float*)d_in[7];
    const float* Wk = (const float*)d_in[8];
    const float* bk = (const float*)d_in[9];
    const float* Wv = (const float*)d_in[10];
    const float* bv = (const float*)d_in[11];
    float* out = (float*)d_out;

    __half *xncat, *cncat, *wqcat, *wkcat, *wvcat, *qcat, *kcat, *vtcat, *acat;
    float *dots, *rinv;
    cudaGetSymbolAddress((void**)&xncat, g_xncat);
    cudaGetSymbolAddress((void**)&cncat, g_cncat);
    cudaGetSymbolAddress((void**)&wqcat, g_wqcat);
    cudaGetSymbolAddress((void**)&wkcat, g_wkcat);
    cudaGetSymbolAddress((void**)&wvcat, g_wvcat);
    cudaGetSymbolAddress((void**)&qcat,  g_qcat);
    cudaGetSymbolAddress((void**)&kcat,  g_kcat);
    cudaGetSymbolAddress((void**)&vtcat, g_vtcat);
    cudaGetSymbolAddress((void**)&acat,  g_acat);
    cudaGetSymbolAddress((void**)&dots,  g_dots);
    cudaGetSymbolAddress((void**)&rinv,  g_rinv);

    cudaFuncSetAttribute(gemm_h, cudaFuncAttributeMaxDynamicSharedMemorySize, GEMM_DSMEM);

    // LayerNorm + split-cat (pattern A)
    ln_cat_kernel<<<BATCH * SEQ, 128>>>(inputs,  gin,  bin,  xncat);
    ln_cat_kernel<<<BATCH * SEQ, 128>>>(context, gctx, bctx, cncat);

    // weight transposes + split-cat (pattern B)
    {
        dim3 g(DIM / 32, DIM / 32, 1);
        tsplit_kernel<<<g, 256>>>(Wq, wqcat);
        tsplit_kernel<<<g, 256>>>(Wk, wkcat);
        tsplit_kernel<<<g, 256>>>(Wv, wvcat);
    }

    // q = LN(x)@Wq + bq -> split-cat pattern A directly (M=16384, N=512)
    {
        dim3 grid(DIM / 128, (BATCH * SEQ) / 128, 1);
        gemm_h<<<grid, 256, GEMM_DSMEM>>>(xncat, wqcat, BATCH * SEQ, DIM, KC_QKV,
                                          0, 0, 0, 1.0f, bq, nullptr, nullptr,
                                          nullptr, qcat, 1);
        // k -> pattern B
        gemm_h<<<grid, 256, GEMM_DSMEM>>>(cncat, wkcat, BATCH * SEQ, DIM, KC_QKV,
                                          0, 0, 0, 1.0f, bk, nullptr, nullptr,
                                          nullptr, kcat, 2);
    }

    // vt[d,j] = (c@Wv + bv)^T -> split-cat pattern B (M=512, N=2048, batched)
    {
        dim3 grid(SEQ / 128, DIM / 128, BATCH);
        gemm_h<<<grid, 256, GEMM_DSMEM>>>(wvcat, cncat, DIM, SEQ, KC_QKV,
                                          0, (size_t)SEQ * KC_QKV, (size_t)DIM * KC_AV,
                                          1.0f, nullptr, bv, nullptr,
                                          nullptr, vtcat, 2);
    }

    // dots = scale * q @ k^T (fp32 out, batched)
    {
        float scale = 1.0f / sqrtf((float)DIM);
        dim3 grid(SEQ / 128, SEQ / 128, BATCH);
        gemm_h<<<grid, 256, GEMM_DSMEM>>>(qcat, kcat, SEQ, SEQ, KC_QKV,
                                          (size_t)SEQ * KC_QKV, (size_t)SEQ * KC_QKV,
                                          (size_t)SEQ * SEQ, scale,
                                          nullptr, nullptr, nullptr,
                                          dots, nullptr, 0);
    }

    // softmax over i + rowpass -> acat (pattern A), rinv
    colstats1_kernel<<<dim3(SEQ / 128, NCHUNK, BATCH), 128>>>();
    colstats2_kernel<<<dim3(SEQ / 256, BATCH), 256>>>();
    rowpass_kernel<<<dim3(SEQ, BATCH), 256>>>();

    // out = rinv[i] * (acat @ vtcat^T) (M=2048, N=512, Kc=6144, batched)
    {
        dim3 grid(DIM / 128, SEQ / 128, BATCH);
        gemm_h<<<grid, 256, GEMM_DSMEM>>>(acat, vtcat, SEQ, DIM, KC_AV,
                                          (size_t)SEQ * KC_AV, (size_t)DIM * KC_AV,
                                          (size_t)SEQ * DIM, 1.0f,
                                          nullptr, nullptr, rinv,
                                          out, nullptr, 0);
    }
}

// round 5
// speedup vs baseline: 3.7147x; 1.0823x over previous
#include <cuda_runtime.h>
#include <cuda_fp16.h>
#include <math.h>
#include <stdint.h>

#define BATCH 8
#define SEQ   2048
#define DIM   512
#define NCHUNK 16
#define KC_QKV (3*DIM)   // 1536
#define KC_AV  (3*SEQ)   // 6144

static const float LN_EPS_F = 1e-5f;
static const float EPS_F    = 1e-8f;

// ---------------- scratch (static device globals; no allocation) ----------------
__device__ __align__(256) __half g_xncat[(size_t)BATCH * SEQ * KC_QKV];
__device__ __align__(256) __half g_cncat[(size_t)BATCH * SEQ * KC_QKV];
__device__ __align__(256) __half g_wqcat[(size_t)DIM * KC_QKV];
__device__ __align__(256) __half g_wkcat[(size_t)DIM * KC_QKV];
__device__ __align__(256) __half g_wvcat[(size_t)DIM * KC_QKV];
__device__ __align__(256) __half g_qcat [(size_t)BATCH * SEQ * KC_QKV];
__device__ __align__(256) __half g_kcat [(size_t)BATCH * SEQ * KC_QKV];
__device__ __align__(256) __half g_vtcat[(size_t)BATCH * DIM * KC_AV];
__device__ __align__(256) __half g_acat [(size_t)BATCH * SEQ * KC_AV];
__device__ __align__(256) float  g_dots [(size_t)BATCH * SEQ * SEQ];
__device__ float g_pm  [BATCH * NCHUNK * SEQ];
__device__ float g_ps  [BATCH * NCHUNK * SEQ];
__device__ float g_cm  [BATCH * SEQ];
__device__ float g_csi [BATCH * SEQ];
__device__ float g_rinv[BATCH * SEQ];

// ---------------- PTX helpers (baseline compute_103-safe) ----------------
__device__ __forceinline__ uint32_t smem_u32(const void* p) {
    uint32_t a;
    asm("{ .reg .u64 t; cvta.to.shared.u64 t, %1; cvt.u32.u64 %0, t; }" : "=r"(a) : "l"(p));
    return a;
}
__device__ __forceinline__ void cp_async16(uint32_t d, const void* g) {
    asm volatile("cp.async.cg.shared.global [%0], [%1], 16;" :: "r"(d), "l"(g));
}
__device__ __forceinline__ void cp_commit() {
    asm volatile("cp.async.commit_group;" ::: "memory");
}
template <int N>
__device__ __forceinline__ void cp_wait() {
    asm volatile("cp.async.wait_group %0;" :: "n"(N) : "memory");
}
__device__ __forceinline__ void ldsm4(uint32_t& r0, uint32_t& r1, uint32_t& r2, uint32_t& r3,
                                      uint32_t addr) {
    asm volatile("ldmatrix.sync.aligned.m8n8.x4.shared.b16 {%0,%1,%2,%3}, [%4];"
                 : "=r"(r0), "=r"(r1), "=r"(r2), "=r"(r3) : "r"(addr));
}
__device__ __forceinline__ void mma16816(float* c, const uint32_t* a, uint32_t b0, uint32_t b1) {
    asm volatile(
        "mma.sync.aligned.m16n8k16.row.col.f32.f16.f16.f32 "
        "{%0,%1,%2,%3}, {%4,%5,%6,%7}, {%8,%9}, {%0,%1,%2,%3};"
        : "+f"(c[0]), "+f"(c[1]), "+f"(c[2]), "+f"(c[3])
        : "r"(a[0]), "r"(a[1]), "r"(a[2]), "r"(a[3]), "r"(b0), "r"(b1));
}

__device__ __forceinline__ void split2h(float x, __half& h, __half& l) {
    h = __float2half_rn(x);
    l = __float2half_rn(x - __half2float(h));
}

// ---------------- HMMA split-fp16 GEMM ----------------
// C[M,N] = A[M,Kc] @ B[N,Kc]^T  (A,B fp16 K-major)
// pattern 0: outf[row*N+col] = (acc*alpha + bias_col[col] + bias_row[row]) * rowscale[z*M+row]
// pattern 1: outh row length 3N, segments [h|l|h]
// pattern 2: outh row length 3N, segments [h|h|l]
// docol: write per-128-row-chunk column (max, sumexp) stats into g_pm/g_ps
#define BK 32
#define STAGES 5
#define PADH 40              // halves per smem row (80 bytes)
#define A_STAGE (128 * PADH * 2)
#define STAGE_BYTES (2 * A_STAGE)
#define GEMM_DSMEM (STAGES * STAGE_BYTES)

__global__ void __launch_bounds__(256, 2) gemm_h(
    const __half* __restrict__ A, const __half* __restrict__ B,
    int M, int N, int Kc,
    size_t sA, size_t sB, size_t sC,
    float alpha,
    const float* __restrict__ bias_col, const float* __restrict__ bias_row,
    const float* __restrict__ rowscale,
    float* __restrict__ outf, __half* __restrict__ outh, int pattern, int docol)
{
    extern __shared__ char dyn[];
    uint32_t dynb = smem_u32(dyn);

    int z = blockIdx.z;
    const __half* Ab = A + (size_t)z * sA + (size_t)(blockIdx.y * 128) * Kc;
    const __half* Bb = B + (size_t)z * sB + (size_t)(blockIdx.x * 128) * Kc;
    int bm = blockIdx.y * 128;
    int bn = blockIdx.x * 128;

    int t = threadIdx.x;
    int wid = t >> 5, lane = t & 31;
    int wm = wid & 1;        // 2 warps over M (64 rows each)
    int wn = wid >> 1;       // 4 warps over N (32 cols each)

    float acc[4][4][4];
    #pragma unroll
    for (int i = 0; i < 4; i++)
        #pragma unroll
        for (int j = 0; j < 4; j++)
            #pragma unroll
            for (int r = 0; r < 4; r++) acc[i][j][r] = 0.0f;

    int nkb = Kc / BK;

    auto issue = [&](int kb) {
        int slot = kb % STAGES;
        uint32_t sa = dynb + slot * STAGE_BYTES;
        uint32_t sb = sa + A_STAGE;
        int kh = kb * BK;
        #pragma unroll
        for (int i = 0; i < 2; i++) {
            int idx = t + 256 * i;
            int row = idx >> 2, c = idx & 3;
            cp_async16(sa + row * 80 + c * 16, Ab + (size_t)row * Kc + kh + c * 8);
        }
        #pragma unroll
        for (int i = 0; i < 2; i++) {
            int idx = t + 256 * i;
            int row = idx >> 2, c = idx & 3;
            cp_async16(sb + row * 80 + c * 16, Bb + (size_t)row * Kc + kh + c * 8);
        }
    };

    issue(0); cp_commit();
    issue(1); cp_commit();
    issue(2); cp_commit();
    issue(3); cp_commit();

    uint32_t a_lane = (uint32_t)((wm * 64 + (lane & 15)) * 80 + ((lane >> 4) * 8) * 2);
    uint32_t b_lane = (uint32_t)(A_STAGE +
                       (wn * 32 + (lane & 7) + (lane >> 4) * 8) * 80 +
                       (((lane >> 3) & 1) * 8) * 2);

    cp_wait<2>();          // slots 0 and 1 ready
    __syncthreads();

    uint32_t af[2][4][4];  // A fragments, double buffered
    uint32_t bf[2][4];     // B fragments, single buffered

    // load A frags for (kb=0, ks=0)
    {
        uint32_t sb0 = dynb;
        #pragma unroll
        for (int mi = 0; mi < 4; mi++)
            ldsm4(af[0][mi][0], af[0][mi][1], af[0][mi][2], af[0][mi][3],
                  sb0 + a_lane + mi * (16 * 80));
    }

    int p = 0;
    for (int kb = 0; kb < nkb; kb++) {
        if (kb + 4 < nkb) issue(kb + 4);
        cp_commit();
        uint32_t scur = dynb + (kb % STAGES) * STAGE_BYTES;
        uint32_t snxt = dynb + ((kb + 1) % STAGES) * STAGE_BYTES;

        // ---- ks = 0 ----
        #pragma unroll
        for (int g = 0; g < 2; g++)
            ldsm4(bf[g][0], bf[g][1], bf[g][2], bf[g][3],
                  scur + b_lane + g * (16 * 80));
        #pragma unroll
        for (int mi = 0; mi < 4; mi++)   // prefetch A for ks=1
            ldsm4(af[p^1][mi][0], af[p^1][mi][1], af[p^1][mi][2], af[p^1][mi][3],
                  scur + a_lane + mi * (16 * 80) + 32);
        #pragma unroll
        for (int mi = 0; mi < 4; mi++)
            #pragma unroll
            for (int ni = 0; ni < 4; ni++)
                mma16816(acc[mi][ni], af[p][mi],
                         bf[ni >> 1][(ni & 1) * 2], bf[ni >> 1][(ni & 1) * 2 + 1]);
        p ^= 1;

        // ---- ks = 1 ----
        #pragma unroll
        for (int g = 0; g < 2; g++)
            ldsm4(bf[g][0], bf[g][1], bf[g][2], bf[g][3],
                  scur + b_lane + g * (16 * 80) + 32);
        if (kb + 1 < nkb) {
            #pragma unroll
            for (int mi = 0; mi < 4; mi++)  // prefetch A for next stage ks=0
                ldsm4(af[p^1][mi][0], af[p^1][mi][1], af[p^1][mi][2], af[p^1][mi][3],
                      snxt + a_lane + mi * (16 * 80));
        }
        #pragma unroll
        for (int mi = 0; mi < 4; mi++)
            #pragma unroll
            for (int ni = 0; ni < 4; ni++)
                mma16816(acc[mi][ni], af[p][mi],
                         bf[ni >> 1][(ni & 1) * 2], bf[ni >> 1][(ni & 1) * 2 + 1]);
        p ^= 1;

        cp_wait<2>();
        __syncthreads();
    }

    // ---------------- store epilogue ----------------
    int r_lane = lane >> 2;
    int c_lane = (lane & 3) * 2;
    #pragma unroll
    for (int mi = 0; mi < 4; mi++) {
        #pragma unroll
        for (int ni = 0; ni < 4; ni++) {
            int row = bm + wm * 64 + mi * 16 + r_lane;
            int col = bn + wn * 32 + ni * 8 + c_lane;
            float* a4 = acc[mi][ni];
            float bc0 = bias_col ? bias_col[col]     : 0.0f;
            float bc1 = bias_col ? bias_col[col + 1] : 0.0f;
            #pragma unroll
            for (int h = 0; h < 2; h++) {
                int rr = row + h * 8;
                float br = bias_row ? bias_row[rr] : 0.0f;
                float v0 = a4[h * 2 + 0] * alpha + bc0 + br;
                float v1 = a4[h * 2 + 1] * alpha + bc1 + br;
                if (pattern == 0) {
                    float rs = rowscale ? rowscale[(size_t)z * M + rr] : 1.0f;
                    float2 o = make_float2(v0 * rs, v1 * rs);
                    *(float2*)(outf + (size_t)z * sC + (size_t)rr * N + col) = o;
                } else {
                    __half h0, l0, h1, l1;
                    split2h(v0, h0, l0);
                    split2h(v1, h1, l1);
                    __half* ob = outh + (size_t)z * sC + (size_t)rr * (3 * N) + col;
                    __half2 hh = __halves2half2(h0, h1);
                    __half2 ll = __halves2half2(l0, l1);
                    *(__half2*)(ob)         = hh;
                    *(__half2*)(ob + N)     = (pattern == 1) ? ll : hh;
                    *(__half2*)(ob + 2 * N) = (pattern == 1) ? hh : ll;
                }
            }
        }
    }

    // ---------------- fused column stats (dots only) ----------------
    if (docol) {
        cp_wait<0>();
        __syncthreads();           // smem slots now reusable
        float* smx = (float*)dyn;           // [2][128]
        float* ssm = (float*)dyn + 256;     // [2][128]

        float cmax[4][2], csum[4][2];
        #pragma unroll
        for (int ni = 0; ni < 4; ni++) {
            #pragma unroll
            for (int c = 0; c < 2; c++) {
                float m = -1e30f;
                #pragma unroll
                for (int mi = 0; mi < 4; mi++)
                    #pragma unroll
                    for (int h = 0; h < 2; h++)
                        m = fmaxf(m, acc[mi][ni][h * 2 + c] * alpha);
                float s = 0.0f;
                #pragma unroll
                for (int mi = 0; mi < 4; mi++)
                    #pragma unroll
                    for (int h = 0; h < 2; h++)
                        s += __expf(acc[mi][ni][h * 2 + c] * alpha - m);
                cmax[ni][c] = m;
                csum[ni][c] = s;
            }
        }
        #pragma unroll
        for (int o = 4; o < 32; o <<= 1) {
            #pragma unroll
            for (int ni = 0; ni < 4; ni++)
                #pragma unroll
                for (int c = 0; c < 2; c++) {
                    float mo = __shfl_xor_sync(0xffffffffu, cmax[ni][c], o);
                    float so = __shfl_xor_sync(0xffffffffu, csum[ni][c], o);
                    float m = fmaxf(cmax[ni][c], mo);
                    csum[ni][c] = csum[ni][c] * __expf(cmax[ni][c] - m) +
                                  so * __expf(mo - m);
                    cmax[ni][c] = m;
                }
        }
        if ((lane >> 2) == 0) {
            #pragma unroll
            for (int ni = 0; ni < 4; ni++)
                #pragma unroll
                for (int c = 0; c < 2; c++) {
                    int col = wn * 32 + ni * 8 + (lane & 3) * 2 + c;
                    smx[wm * 128 + col] = cmax[ni][c];
                    ssm[wm * 128 + col] = csum[ni][c];
                }
        }
        __syncthreads();
        if (t < 128) {
            float m0 = smx[t], m1 = smx[128 + t];
            float s0 = ssm[t], s1 = ssm[128 + t];
            float m = fmaxf(m0, m1);
            float s = s0 * __expf(m0 - m) + s1 * __expf(m1 - m);
            size_t o = ((size_t)z * NCHUNK + blockIdx.y) * SEQ + bn + t;
            g_pm[o] = m;
            g_ps[o] = s;
        }
    }
}

// ---------------- LayerNorm + split-cat pattern A: out [rows, 1536] fp16 ----
__global__ void __launch_bounds__(128) ln_cat_kernel(const float* __restrict__ x,
                                                     const float* __restrict__ g,
                                                     const float* __restrict__ b,
                                                     __half* __restrict__ y) {
    int row = blockIdx.x;
    int t = threadIdx.x;
    float4 v = ((const float4*)(x + (size_t)row * DIM))[t];
    float s  = v.x + v.y + v.z + v.w;
    float ss = v.x*v.x + v.y*v.y + v.z*v.z + v.w*v.w;
    __shared__ float sh[8];
    #pragma unroll
    for (int o = 16; o > 0; o >>= 1) {
        s  += __shfl_down_sync(0xffffffffu, s, o);
        ss += __shfl_down_sync(0xffffffffu, ss, o);
    }
    if ((t & 31) == 0) { sh[t >> 5] = s; sh[4 + (t >> 5)] = ss; }
    __syncthreads();
    float fs  = sh[0] + sh[1] + sh[2] + sh[3];
    float fss = sh[4] + sh[5] + sh[6] + sh[7];
    float mu  = fs * (1.0f / DIM);
    float var = fss * (1.0f / DIM) - mu * mu;
    float rstd = rsqrtf(var + LN_EPS_F);
    float4 gv = ((const float4*)g)[t];
    float4 bv = ((const float4*)b)[t];
    float o0 = (v.x - mu) * rstd * gv.x + bv.x;
    float o1 = (v.y - mu) * rstd * gv.y + bv.y;
    float o2 = (v.z - mu) * rstd * gv.z + bv.z;
    float o3 = (v.w - mu) * rstd * gv.w + bv.w;
    __half h0,h1,h2,h3,l0,l1,l2,l3;
    split2h(o0,h0,l0); split2h(o1,h1,l1); split2h(o2,h2,l2); split2h(o3,h3,l3);
    __half* yb = y + (size_t)row * KC_QKV + t * 4;
    ((__half2*)yb)[0] = __halves2half2(h0, h1);
    ((__half2*)yb)[1] = __halves2half2(h2, h3);
    ((__half2*)(yb + DIM))[0] = __halves2half2(l0, l1);
    ((__half2*)(yb + DIM))[1] = __halves2half2(l2, l3);
    ((__half2*)(yb + 2*DIM))[0] = __halves2half2(h0, h1);
    ((__half2*)(yb + 2*DIM))[1] = __halves2half2(h2, h3);
}

// ---------------- weight transpose + split-cat pattern B: W[512,512] -> [512,1536]
__global__ void __launch_bounds__(256) tsplit_kernel(const float* __restrict__ in,
                                                     __half* __restrict__ out) {
    __shared__ float tile[32][33];
    int r0 = blockIdx.y * 32, c0 = blockIdx.x * 32;
    int tx = threadIdx.x & 31, ty = threadIdx.x >> 5;
    #pragma unroll
    for (int i = ty; i < 32; i += 8)
        tile[i][tx] = in[(size_t)(r0 + i) * DIM + c0 + tx];
    __syncthreads();
    #pragma unroll
    for (int i = ty; i < 32; i += 8) {
        float v = tile[tx][i];
        __half h, l;
        split2h(v, h, l);
        __half* o = out + (size_t)(c0 + i) * KC_QKV + r0 + tx;
        o[0] = h;
        o[DIM] = h;
        o[2 * DIM] = l;
    }
}

// ---------------- column stats combine -> colmax, 1/colsum ----------------
__global__ void __launch_bounds__(256) colstats2_kernel() {
    int j = blockIdx.x * 256 + threadIdx.x;
    int z = blockIdx.y;
    float m = -1e30f;
    #pragma unroll
    for (int c = 0; c < NCHUNK; c++)
        m = fmaxf(m, g_pm[((size_t)z * NCHUNK + c) * SEQ + j]);
    float s = 0.0f;
    #pragma unroll
    for (int c = 0; c < NCHUNK; c++)
        s += g_ps[((size_t)z * NCHUNK + c) * SEQ + j] *
             __expf(g_pm[((size_t)z * NCHUNK + c) * SEQ + j] - m);
    g_cm [(size_t)z * SEQ + j] = m;
    g_csi[(size_t)z * SEQ + j] = 1.0f / s;
}

// ---------------- row pass: Araw=softmax+EPS -> acat (pattern A), rinv -----
__global__ void __launch_bounds__(256) rowpass_kernel() {
    int i = blockIdx.x;
    int z = blockIdx.y;
    int t = threadIdx.x;
    const float* row = g_dots + ((size_t)z * SEQ + i) * SEQ;
    const float* cm = g_cm  + (size_t)z * SEQ;
    const float* ci = g_csi + (size_t)z * SEQ;
    __half* ab = g_acat + ((size_t)z * SEQ + i) * KC_AV;
    float acc = 0.0f;
    #pragma unroll 2
    for (int j2 = t; j2 < SEQ / 2; j2 += 256) {
        int j = j2 * 2;
        float2 d = *(const float2*)(row + j);
        float2 m2 = *(const float2*)(cm + j);
        float2 c2 = *(const float2*)(ci + j);
        float a0 = __expf(d.x - m2.x) * c2.x + EPS_F;
        float a1 = __expf(d.y - m2.y) * c2.y + EPS_F;
        acc += a0 + a1;
        __half h0, l0, h1, l1;
        split2h(a0, h0, l0);
        split2h(a1, h1, l1);
        __half2 hh = __halves2half2(h0, h1);
        __half2 ll = __halves2half2(l0, l1);
        *(__half2*)(ab + j)           = hh;
        *(__half2*)(ab + SEQ + j)     = ll;
        *(__half2*)(ab + 2 * SEQ + j) = hh;
    }
    __shared__ float sh[8];
    #pragma unroll
    for (int o = 16; o > 0; o >>= 1)
        acc += __shfl_down_sync(0xffffffffu, acc, o);
    if ((t & 31) == 0) sh[t >> 5] = acc;
    __syncthreads();
    if (t == 0) {
        float s = 0.0f;
        #pragma unroll
        for (int w = 0; w < 8; w++) s += sh[w];
        g_rinv[(size_t)z * SEQ + i] = 1.0f / (s + EPS_F);
    }
}

// ---------------- launch ----------------
extern "C" void kernel_launch(void* const* d_in, const int* in_sizes, int n_in,
                              void* d_out, int out_size) {
    const float* inputs  = (const float*)d_in[0];
    const float* context = (const float*)d_in[1];
    const float* gin  = (const float*)d_in[2];
    const float* bin  = (const float*)d_in[3];
    const float* gctx = (const float*)d_in[4];
    const float* bctx = (const float*)d_in[5];
    const float* Wq = (const float*)d_in[6];
    const float* bq = (const float*)d_in[7];
    const float* Wk = (const float*)d_in[8];
    const float* bk = (const float*)d_in[9];
    const float* Wv = (const float*)d_in[10];
    const float* bv = (const float*)d_in[11];
    float* out = (float*)d_out;

    __half *xncat, *cncat, *wqcat, *wkcat, *wvcat, *qcat, *kcat, *vtcat, *acat;
    float *dots, *rinv;
    cudaGetSymbolAddress((void**)&xncat, g_xncat);
    cudaGetSymbolAddress((void**)&cncat, g_cncat);
    cudaGetSymbolAddress((void**)&wqcat, g_wqcat);
    cudaGetSymbolAddress((void**)&wkcat, g_wkcat);
    cudaGetSymbolAddress((void**)&wvcat, g_wvcat);
    cudaGetSymbolAddress((void**)&qcat,  g_qcat);
    cudaGetSymbolAddress((void**)&kcat,  g_kcat);
    cudaGetSymbolAddress((void**)&vtcat, g_vtcat);
    cudaGetSymbolAddress((void**)&acat,  g_acat);
    cudaGetSymbolAddress((void**)&dots,  g_dots);
    cudaGetSymbolAddress((void**)&rinv,  g_rinv);

    cudaFuncSetAttribute(gemm_h, cudaFuncAttributeMaxDynamicSharedMemorySize, GEMM_DSMEM);

    // LayerNorm + split-cat (pattern A)
    ln_cat_kernel<<<BATCH * SEQ, 128>>>(inputs,  gin,  bin,  xncat);
    ln_cat_kernel<<<BATCH * SEQ, 128>>>(context, gctx, bctx, cncat);

    // weight transposes + split-cat (pattern B)
    {
        dim3 g(DIM / 32, DIM / 32, 1);
        tsplit_kernel<<<g, 256>>>(Wq, wqcat);
        tsplit_kernel<<<g, 256>>>(Wk, wkcat);
        tsplit_kernel<<<g, 256>>>(Wv, wvcat);
    }

    // q = LN(x)@Wq + bq -> split-cat pattern A (M=16384, N=512)
    {
        dim3 grid(DIM / 128, (BATCH * SEQ) / 128, 1);
        gemm_h<<<grid, 256, GEMM_DSMEM>>>(xncat, wqcat, BATCH * SEQ, DIM, KC_QKV,
                                          0, 0, 0, 1.0f, bq, nullptr, nullptr,
                                          nullptr, qcat, 1, 0);
        gemm_h<<<grid, 256, GEMM_DSMEM>>>(cncat, wkcat, BATCH * SEQ, DIM, KC_QKV,
                                          0, 0, 0, 1.0f, bk, nullptr, nullptr,
                                          nullptr, kcat, 2, 0);
    }

    // vt[d,j] = (c@Wv + bv)^T -> split-cat pattern B (M=512, N=2048, batched)
    {
        dim3 grid(SEQ / 128, DIM / 128, BATCH);
        gemm_h<<<grid, 256, GEMM_DSMEM>>>(wvcat, cncat, DIM, SEQ, KC_QKV,
                                          0, (size_t)SEQ * KC_QKV, (size_t)DIM * KC_AV,
                                          1.0f, nullptr, bv, nullptr,
                                          nullptr, vtcat, 2, 0);
    }

    // dots = scale * q @ k^T (fp32 out, batched) + fused column stats
    {
        float scale = 1.0f / sqrtf((float)DIM);
        dim3 grid(SEQ / 128, SEQ / 128, BATCH);
        gemm_h<<<grid, 256, GEMM_DSMEM>>>(qcat, kcat, SEQ, SEQ, KC_QKV,
                                          (size_t)SEQ * KC_QKV, (size_t)SEQ * KC_QKV,
                                          (size_t)SEQ * SEQ, scale,
                                          nullptr, nullptr, nullptr,
                                          dots, nullptr, 0, 1);
    }

    // softmax combine + rowpass -> acat (pattern A), rinv
    colstats2_kernel<<<dim3(SEQ / 256, BATCH), 256>>>();
    rowpass_kernel<<<dim3(SEQ, BATCH), 256>>>();

    // out = rinv[i] * (acat @ vtcat^T) (M=2048, N=512, Kc=6144, batched)
    {
        dim3 grid(DIM / 128, SEQ / 128, BATCH);
        gemm_h<<<grid, 256, GEMM_DSMEM>>>(acat, vtcat, SEQ, DIM, KC_AV,
                                          (size_t)SEQ * KC_AV, (size_t)DIM * KC_AV,
                                          (size_t)SEQ * DIM, 1.0f,
                                          nullptr, nullptr, rinv,
                                          out, nullptr, 0, 0);
    }
}

// round 6
// speedup vs baseline: 4.7021x; 1.2658x over previous
#include <cuda_runtime.h>
#include <cuda_fp16.h>
#include <math.h>
#include <stdint.h>

#define BATCH 8
#define SEQ   2048
#define DIM   512
#define NCHUNK 16
#define KC_QKV  (2*DIM)   // 1024: [xh|xl] . [Wh|Wh]
#define KC_DOTS (3*DIM)   // 1536: [qh|ql|qh] . [kh|kh|kl]
#define KC_AV   (2*SEQ)   // 4096: [Ph|Pl] . [Vh|Vh]

static const float LN_EPS_F = 1e-5f;
static const float EPS_F    = 1e-8f;

// ---------------- scratch (static device globals; no allocation) ----------------
__device__ __align__(256) __half g_xncat[(size_t)BATCH * SEQ * KC_QKV];
__device__ __align__(256) __half g_cncat[(size_t)BATCH * SEQ * KC_QKV];
__device__ __align__(256) __half g_wqcat[(size_t)DIM * KC_QKV];
__device__ __align__(256) __half g_wkcat[(size_t)DIM * KC_QKV];
__device__ __align__(256) __half g_wvcat[(size_t)DIM * KC_QKV];
__device__ __align__(256) __half g_qcat [(size_t)BATCH * SEQ * KC_DOTS];
__device__ __align__(256) __half g_kcat [(size_t)BATCH * SEQ * KC_DOTS];
__device__ __align__(256) __half g_vtcat[(size_t)BATCH * DIM * KC_AV];
__device__ __align__(256) __half g_acat [(size_t)BATCH * SEQ * KC_AV];
__device__ __align__(256) float  g_dots [(size_t)BATCH * SEQ * SEQ];
__device__ float g_pm  [BATCH * NCHUNK * SEQ];
__device__ float g_ps  [BATCH * NCHUNK * SEQ];
__device__ float g_cm  [BATCH * SEQ];
__device__ float g_csi [BATCH * SEQ];
__device__ float g_rinv[BATCH * SEQ];

// ---------------- PTX helpers (baseline compute_103-safe) ----------------
__device__ __forceinline__ uint32_t smem_u32(const void* p) {
    uint32_t a;
    asm("{ .reg .u64 t; cvta.to.shared.u64 t, %1; cvt.u32.u64 %0, t; }" : "=r"(a) : "l"(p));
    return a;
}
__device__ __forceinline__ void cp_async16(uint32_t d, const void* g) {
    asm volatile("cp.async.cg.shared.global [%0], [%1], 16;" :: "r"(d), "l"(g));
}
__device__ __forceinline__ void cp_commit() {
    asm volatile("cp.async.commit_group;" ::: "memory");
}
template <int N>
__device__ __forceinline__ void cp_wait() {
    asm volatile("cp.async.wait_group %0;" :: "n"(N) : "memory");
}
__device__ __forceinline__ void ldsm4(uint32_t& r0, uint32_t& r1, uint32_t& r2, uint32_t& r3,
                                      uint32_t addr) {
    asm volatile("ldmatrix.sync.aligned.m8n8.x4.shared.b16 {%0,%1,%2,%3}, [%4];"
                 : "=r"(r0), "=r"(r1), "=r"(r2), "=r"(r3) : "r"(addr));
}
__device__ __forceinline__ void mma16816(float* c, const uint32_t* a, uint32_t b0, uint32_t b1) {
    asm volatile(
        "mma.sync.aligned.m16n8k16.row.col.f32.f16.f16.f32 "
        "{%0,%1,%2,%3}, {%4,%5,%6,%7}, {%8,%9}, {%0,%1,%2,%3};"
        : "+f"(c[0]), "+f"(c[1]), "+f"(c[2]), "+f"(c[3])
        : "r"(a[0]), "r"(a[1]), "r"(a[2]), "r"(a[3]), "r"(b0), "r"(b1));
}

__device__ __forceinline__ void split2h(float x, __half& h, __half& l) {
    h = __float2half_rn(x);
    l = __float2half_rn(x - __half2float(h));
}

// ---------------- HMMA split-fp16 GEMM ----------------
// C[M,N] = A[M,Kc] @ B[N,Kc]^T  (A,B fp16 K-major)
// pattern 0: outf = (acc*alpha + bias_col[col] + bias_row[row]) * rowscale[z*M+row]
// pattern 1: outh row length 3N, segments [h|l|h]
// pattern 2: outh row length 3N, segments [h|h|l]
// pattern 3: outh row length 2N, segments [h|h]
// docol: write per-128-row-chunk column (max, sumexp) stats into g_pm/g_ps
#define BK 32
#define STAGES 5
#define A_STAGE (128 * 40 * 2)
#define STAGE_BYTES (2 * A_STAGE)
#define GEMM_DSMEM (STAGES * STAGE_BYTES)

__global__ void __launch_bounds__(256, 2) gemm_h(
    const __half* __restrict__ A, const __half* __restrict__ B,
    int M, int N, int Kc,
    size_t sA, size_t sB, size_t sC,
    float alpha,
    const float* __restrict__ bias_col, const float* __restrict__ bias_row,
    const float* __restrict__ rowscale,
    float* __restrict__ outf, __half* __restrict__ outh, int pattern, int docol)
{
    extern __shared__ char dyn[];
    uint32_t dynb = smem_u32(dyn);

    int z = blockIdx.z;
    const __half* Ab = A + (size_t)z * sA + (size_t)(blockIdx.y * 128) * Kc;
    const __half* Bb = B + (size_t)z * sB + (size_t)(blockIdx.x * 128) * Kc;
    int bm = blockIdx.y * 128;
    int bn = blockIdx.x * 128;

    int t = threadIdx.x;
    int wid = t >> 5, lane = t & 31;
    int wm = wid & 1;        // 2 warps over M (64 rows each)
    int wn = wid >> 1;       // 4 warps over N (32 cols each)

    float acc[4][4][4];
    #pragma unroll
    for (int i = 0; i < 4; i++)
        #pragma unroll
        for (int j = 0; j < 4; j++)
            #pragma unroll
            for (int r = 0; r < 4; r++) acc[i][j][r] = 0.0f;

    int nkb = Kc / BK;

    auto issue = [&](int kb) {
        int slot = kb % STAGES;
        uint32_t sa = dynb + slot * STAGE_BYTES;
        uint32_t sb = sa + A_STAGE;
        int kh = kb * BK;
        #pragma unroll
        for (int i = 0; i < 2; i++) {
            int idx = t + 256 * i;
            int row = idx >> 2, c = idx & 3;
            cp_async16(sa + row * 80 + c * 16, Ab + (size_t)row * Kc + kh + c * 8);
        }
        #pragma unroll
        for (int i = 0; i < 2; i++) {
            int idx = t + 256 * i;
            int row = idx >> 2, c = idx & 3;
            cp_async16(sb + row * 80 + c * 16, Bb + (size_t)row * Kc + kh + c * 8);
        }
    };

    issue(0); cp_commit();
    issue(1); cp_commit();
    issue(2); cp_commit();
    issue(3); cp_commit();

    uint32_t a_lane = (uint32_t)((wm * 64 + (lane & 15)) * 80 + ((lane >> 4) * 8) * 2);
    uint32_t b_lane = (uint32_t)(A_STAGE +
                       (wn * 32 + (lane & 7) + (lane >> 4) * 8) * 80 +
                       (((lane >> 3) & 1) * 8) * 2);

    cp_wait<2>();          // slots 0 and 1 ready
    __syncthreads();

    uint32_t af[2][4][4];  // A fragments, double buffered
    uint32_t bf[2][4];     // B fragments, single buffered

    {
        uint32_t sb0 = dynb;
        #pragma unroll
        for (int mi = 0; mi < 4; mi++)
            ldsm4(af[0][mi][0], af[0][mi][1], af[0][mi][2], af[0][mi][3],
                  sb0 + a_lane + mi * (16 * 80));
    }

    int p = 0;
    for (int kb = 0; kb < nkb; kb++) {
        if (kb + 4 < nkb) issue(kb + 4);
        cp_commit();
        uint32_t scur = dynb + (kb % STAGES) * STAGE_BYTES;
        uint32_t snxt = dynb + ((kb + 1) % STAGES) * STAGE_BYTES;

        // ---- ks = 0 ----
        #pragma unroll
        for (int g = 0; g < 2; g++)
            ldsm4(bf[g][0], bf[g][1], bf[g][2], bf[g][3],
                  scur + b_lane + g * (16 * 80));
        #pragma unroll
        for (int mi = 0; mi < 4; mi++)   // prefetch A for ks=1
            ldsm4(af[p^1][mi][0], af[p^1][mi][1], af[p^1][mi][2], af[p^1][mi][3],
                  scur + a_lane + mi * (16 * 80) + 32);
        #pragma unroll
        for (int mi = 0; mi < 4; mi++)
            #pragma unroll
            for (int ni = 0; ni < 4; ni++)
                mma16816(acc[mi][ni], af[p][mi],
                         bf[ni >> 1][(ni & 1) * 2], bf[ni >> 1][(ni & 1) * 2 + 1]);
        p ^= 1;

        // ---- ks = 1 ----
        #pragma unroll
        for (int g = 0; g < 2; g++)
            ldsm4(bf[g][0], bf[g][1], bf[g][2], bf[g][3],
                  scur + b_lane + g * (16 * 80) + 32);
        if (kb + 1 < nkb) {
            #pragma unroll
            for (int mi = 0; mi < 4; mi++)  // prefetch A for next stage ks=0
                ldsm4(af[p^1][mi][0], af[p^1][mi][1], af[p^1][mi][2], af[p^1][mi][3],
                      snxt + a_lane + mi * (16 * 80));
        }
        #pragma unroll
        for (int mi = 0; mi < 4; mi++)
            #pragma unroll
            for (int ni = 0; ni < 4; ni++)
                mma16816(acc[mi][ni], af[p][mi],
                         bf[ni >> 1][(ni & 1) * 2], bf[ni >> 1][(ni & 1) * 2 + 1]);
        p ^= 1;

        cp_wait<2>();
        __syncthreads();
    }

    // ---------------- store epilogue ----------------
    int r_lane = lane >> 2;
    int c_lane = (lane & 3) * 2;
    #pragma unroll
    for (int mi = 0; mi < 4; mi++) {
        #pragma unroll
        for (int ni = 0; ni < 4; ni++) {
            int row = bm + wm * 64 + mi * 16 + r_lane;
            int col = bn + wn * 32 + ni * 8 + c_lane;
            float* a4 = acc[mi][ni];
            float bc0 = bias_col ? bias_col[col]     : 0.0f;
            float bc1 = bias_col ? bias_col[col + 1] : 0.0f;
            #pragma unroll
            for (int h = 0; h < 2; h++) {
                int rr = row + h * 8;
                float br = bias_row ? bias_row[rr] : 0.0f;
                float v0 = a4[h * 2 + 0] * alpha + bc0 + br;
                float v1 = a4[h * 2 + 1] * alpha + bc1 + br;
                if (pattern == 0) {
                    float rs = rowscale ? rowscale[(size_t)z * M + rr] : 1.0f;
                    float2 o = make_float2(v0 * rs, v1 * rs);
                    *(float2*)(outf + (size_t)z * sC + (size_t)rr * N + col) = o;
                } else if (pattern == 3) {
                    __half2 hh = __halves2half2(__float2half_rn(v0), __float2half_rn(v1));
                    __half* ob = outh + (size_t)z * sC + (size_t)rr * (2 * N) + col;
                    *(__half2*)(ob)     = hh;
                    *(__half2*)(ob + N) = hh;
                } else {
                    __half h0, l0, h1, l1;
                    split2h(v0, h0, l0);
                    split2h(v1, h1, l1);
                    __half* ob = outh + (size_t)z * sC + (size_t)rr * (3 * N) + col;
                    __half2 hh = __halves2half2(h0, h1);
                    __half2 ll = __halves2half2(l0, l1);
                    *(__half2*)(ob)         = hh;
                    *(__half2*)(ob + N)     = (pattern == 1) ? ll : hh;
                    *(__half2*)(ob + 2 * N) = (pattern == 1) ? hh : ll;
                }
            }
        }
    }

    // ---------------- fused column stats (dots only) ----------------
    if (docol) {
        cp_wait<0>();
        __syncthreads();
        float* smx = (float*)dyn;
        float* ssm = (float*)dyn + 256;

        float cmax[4][2], csum[4][2];
        #pragma unroll
        for (int ni = 0; ni < 4; ni++) {
            #pragma unroll
            for (int c = 0; c < 2; c++) {
                float m = -1e30f;
                #pragma unroll
                for (int mi = 0; mi < 4; mi++)
                    #pragma unroll
                    for (int h = 0; h < 2; h++)
                        m = fmaxf(m, acc[mi][ni][h * 2 + c] * alpha);
                float s = 0.0f;
                #pragma unroll
                for (int mi = 0; mi < 4; mi++)
                    #pragma unroll
                    for (int h = 0; h < 2; h++)
                        s += __expf(acc[mi][ni][h * 2 + c] * alpha - m);
                cmax[ni][c] = m;
                csum[ni][c] = s;
            }
        }
        #pragma unroll
        for (int o = 4; o < 32; o <<= 1) {
            #pragma unroll
            for (int ni = 0; ni < 4; ni++)
                #pragma unroll
                for (int c = 0; c < 2; c++) {
                    float mo = __shfl_xor_sync(0xffffffffu, cmax[ni][c], o);
                    float so = __shfl_xor_sync(0xffffffffu, csum[ni][c], o);
                    float m = fmaxf(cmax[ni][c], mo);
                    csum[ni][c] = csum[ni][c] * __expf(cmax[ni][c] - m) +
                                  so * __expf(mo - m);
                    cmax[ni][c] = m;
                }
        }
        if ((lane >> 2) == 0) {
            #pragma unroll
            for (int ni = 0; ni < 4; ni++)
                #pragma unroll
                for (int c = 0; c < 2; c++) {
                    int col = wn * 32 + ni * 8 + (lane & 3) * 2 + c;
                    smx[wm * 128 + col] = cmax[ni][c];
                    ssm[wm * 128 + col] = csum[ni][c];
                }
        }
        __syncthreads();
        if (t < 128) {
            float m0 = smx[t], m1 = smx[128 + t];
            float s0 = ssm[t], s1 = ssm[128 + t];
            float m = fmaxf(m0, m1);
            float s = s0 * __expf(m0 - m) + s1 * __expf(m1 - m);
            size_t o = ((size_t)z * NCHUNK + blockIdx.y) * SEQ + bn + t;
            g_pm[o] = m;
            g_ps[o] = s;
        }
    }
}

// ---------------- LayerNorm + split [h|l]: out [rows, 1024] fp16 ----
__global__ void __launch_bounds__(128) ln_cat_kernel(const float* __restrict__ x,
                                                     const float* __restrict__ g,
                                                     const float* __restrict__ b,
                                                     __half* __restrict__ y) {
    int row = blockIdx.x;
    int t = threadIdx.x;
    float4 v = ((const float4*)(x + (size_t)row * DIM))[t];
    float s  = v.x + v.y + v.z + v.w;
    float ss = v.x*v.x + v.y*v.y + v.z*v.z + v.w*v.w;
    __shared__ float sh[8];
    #pragma unroll
    for (int o = 16; o > 0; o >>= 1) {
        s  += __shfl_down_sync(0xffffffffu, s, o);
        ss += __shfl_down_sync(0xffffffffu, ss, o);
    }
    if ((t & 31) == 0) { sh[t >> 5] = s; sh[4 + (t >> 5)] = ss; }
    __syncthreads();
    float fs  = sh[0] + sh[1] + sh[2] + sh[3];
    float fss = sh[4] + sh[5] + sh[6] + sh[7];
    float mu  = fs * (1.0f / DIM);
    float var = fss * (1.0f / DIM) - mu * mu;
    float rstd = rsqrtf(var + LN_EPS_F);
    float4 gv = ((const float4*)g)[t];
    float4 bv = ((const float4*)b)[t];
    float o0 = (v.x - mu) * rstd * gv.x + bv.x;
    float o1 = (v.y - mu) * rstd * gv.y + bv.y;
    float o2 = (v.z - mu) * rstd * gv.z + bv.z;
    float o3 = (v.w - mu) * rstd * gv.w + bv.w;
    __half h0,h1,h2,h3,l0,l1,l2,l3;
    split2h(o0,h0,l0); split2h(o1,h1,l1); split2h(o2,h2,l2); split2h(o3,h3,l3);
    __half* yb = y + (size_t)row * KC_QKV + t * 4;
    ((__half2*)yb)[0] = __halves2half2(h0, h1);
    ((__half2*)yb)[1] = __halves2half2(h2, h3);
    ((__half2*)(yb + DIM))[0] = __halves2half2(l0, l1);
    ((__half2*)(yb + DIM))[1] = __halves2half2(l2, l3);
}

// ---------------- weight transpose [Wh|Wh]: W[512,512] -> [512,1024] ----
__global__ void __launch_bounds__(256) tsplit_kernel(const float* __restrict__ in,
                                                     __half* __restrict__ out) {
    __shared__ float tile[32][33];
    int r0 = blockIdx.y * 32, c0 = blockIdx.x * 32;
    int tx = threadIdx.x & 31, ty = threadIdx.x >> 5;
    #pragma unroll
    for (int i = ty; i < 32; i += 8)
        tile[i][tx] = in[(size_t)(r0 + i) * DIM + c0 + tx];
    __syncthreads();
    #pragma unroll
    for (int i = ty; i < 32; i += 8) {
        __half h = __float2half_rn(tile[tx][i]);
        __half* o = out + (size_t)(c0 + i) * KC_QKV + r0 + tx;
        o[0] = h;
        o[DIM] = h;
    }
}

// ---------------- column stats combine -> colmax, 1/colsum ----------------
__global__ void __launch_bounds__(256) colstats2_kernel() {
    int j = blockIdx.x * 256 + threadIdx.x;
    int z = blockIdx.y;
    float m = -1e30f;
    #pragma unroll
    for (int c = 0; c < NCHUNK; c++)
        m = fmaxf(m, g_pm[((size_t)z * NCHUNK + c) * SEQ + j]);
    float s = 0.0f;
    #pragma unroll
    for (int c = 0; c < NCHUNK; c++)
        s += g_ps[((size_t)z * NCHUNK + c) * SEQ + j] *
             __expf(g_pm[((size_t)z * NCHUNK + c) * SEQ + j] - m);
    g_cm [(size_t)z * SEQ + j] = m;
    g_csi[(size_t)z * SEQ + j] = 1.0f / s;
}

// ---------------- row pass: Araw=softmax+EPS -> acat [Ph|Pl], rinv -----
__global__ void __launch_bounds__(256) rowpass_kernel() {
    int i = blockIdx.x;
    int z = blockIdx.y;
    int t = threadIdx.x;
    const float* row = g_dots + ((size_t)z * SEQ + i) * SEQ;
    const float* cm = g_cm  + (size_t)z * SEQ;
    const float* ci = g_csi + (size_t)z * SEQ;
    __half* ab = g_acat + ((size_t)z * SEQ + i) * KC_AV;
    float acc = 0.0f;
    #pragma unroll 2
    for (int j2 = t; j2 < SEQ / 2; j2 += 256) {
        int j = j2 * 2;
        float2 d = *(const float2*)(row + j);
        float2 m2 = *(const float2*)(cm + j);
        float2 c2 = *(const float2*)(ci + j);
        float a0 = __expf(d.x - m2.x) * c2.x + EPS_F;
        float a1 = __expf(d.y - m2.y) * c2.y + EPS_F;
        acc += a0 + a1;
        __half h0, l0, h1, l1;
        split2h(a0, h0, l0);
        split2h(a1, h1, l1);
        *(__half2*)(ab + j)       = __halves2half2(h0, h1);
        *(__half2*)(ab + SEQ + j) = __halves2half2(l0, l1);
    }
    __shared__ float sh[8];
    #pragma unroll
    for (int o = 16; o > 0; o >>= 1)
        acc += __shfl_down_sync(0xffffffffu, acc, o);
    if ((t & 31) == 0) sh[t >> 5] = acc;
    __syncthreads();
    if (t == 0) {
        float s = 0.0f;
        #pragma unroll
        for (int w = 0; w < 8; w++) s += sh[w];
        g_rinv[(size_t)z * SEQ + i] = 1.0f / (s + EPS_F);
    }
}

// ---------------- launch ----------------
extern "C" void kernel_launch(void* const* d_in, const int* in_sizes, int n_in,
                              void* d_out, int out_size) {
    const float* inputs  = (const float*)d_in[0];
    const float* context = (const float*)d_in[1];
    const float* gin  = (const float*)d_in[2];
    const float* bin  = (const float*)d_in[3];
    const float* gctx = (const float*)d_in[4];
    const float* bctx = (const float*)d_in[5];
    const float* Wq = (const float*)d_in[6];
    const float* bq = (const float*)d_in[7];
    const float* Wk = (const float*)d_in[8];
    const float* bk = (const float*)d_in[9];
    const float* Wv = (const float*)d_in[10];
    const float* bv = (const float*)d_in[11];
    float* out = (float*)d_out;

    __half *xncat, *cncat, *wqcat, *wkcat, *wvcat, *qcat, *kcat, *vtcat, *acat;
    float *dots, *rinv;
    cudaGetSymbolAddress((void**)&xncat, g_xncat);
    cudaGetSymbolAddress((void**)&cncat, g_cncat);
    cudaGetSymbolAddress((void**)&wqcat, g_wqcat);
    cudaGetSymbolAddress((void**)&wkcat, g_wkcat);
    cudaGetSymbolAddress((void**)&wvcat, g_wvcat);
    cudaGetSymbolAddress((void**)&qcat,  g_qcat);
    cudaGetSymbolAddress((void**)&kcat,  g_kcat);
    cudaGetSymbolAddress((void**)&vtcat, g_vtcat);
    cudaGetSymbolAddress((void**)&acat,  g_acat);
    cudaGetSymbolAddress((void**)&dots,  g_dots);
    cudaGetSymbolAddress((void**)&rinv,  g_rinv);

    cudaFuncSetAttribute(gemm_h, cudaFuncAttributeMaxDynamicSharedMemorySize, GEMM_DSMEM);

    // LayerNorm + split [h|l]
    ln_cat_kernel<<<BATCH * SEQ, 128>>>(inputs,  gin,  bin,  xncat);
    ln_cat_kernel<<<BATCH * SEQ, 128>>>(context, gctx, bctx, cncat);

    // weight transposes [Wh|Wh]
    {
        dim3 g(DIM / 32, DIM / 32, 1);
        tsplit_kernel<<<g, 256>>>(Wq, wqcat);
        tsplit_kernel<<<g, 256>>>(Wk, wkcat);
        tsplit_kernel<<<g, 256>>>(Wv, wvcat);
    }

    // q = LN(x)@Wq + bq -> [h|l|h] (M=16384, N=512, Kc=1024)
    {
        dim3 grid(DIM / 128, (BATCH * SEQ) / 128, 1);
        gemm_h<<<grid, 256, GEMM_DSMEM>>>(xncat, wqcat, BATCH * SEQ, DIM, KC_QKV,
                                          0, 0, 0, 1.0f, bq, nullptr, nullptr,
                                          nullptr, qcat, 1, 0);
        gemm_h<<<grid, 256, GEMM_DSMEM>>>(cncat, wkcat, BATCH * SEQ, DIM, KC_QKV,
                                          0, 0, 0, 1.0f, bk, nullptr, nullptr,
                                          nullptr, kcat, 2, 0);
    }

    // vt[d,j] = (c@Wv + bv)^T -> [Vh|Vh] (M=512, N=2048, Kc=1024, batched)
    {
        dim3 grid(SEQ / 128, DIM / 128, BATCH);
        gemm_h<<<grid, 256, GEMM_DSMEM>>>(wvcat, cncat, DIM, SEQ, KC_QKV,
                                          0, (size_t)SEQ * KC_QKV, (size_t)DIM * KC_AV,
                                          1.0f, nullptr, bv, nullptr,
                                          nullptr, vtcat, 3, 0);
    }

    // dots = scale * q @ k^T (fp32 out, Kc=1536, batched) + fused column stats
    {
        float scale = 1.0f / sqrtf((float)DIM);
        dim3 grid(SEQ / 128, SEQ / 128, BATCH);
        gemm_h<<<grid, 256, GEMM_DSMEM>>>(qcat, kcat, SEQ, SEQ, KC_DOTS,
                                          (size_t)SEQ * KC_DOTS, (size_t)SEQ * KC_DOTS,
                                          (size_t)SEQ * SEQ, scale,
                                          nullptr, nullptr, nullptr,
                                          dots, nullptr, 0, 1);
    }

    // softmax combine + rowpass -> acat [Ph|Pl], rinv
    colstats2_kernel<<<dim3(SEQ / 256, BATCH), 256>>>();
    rowpass_kernel<<<dim3(SEQ, BATCH), 256>>>();

    // out = rinv[i] * (acat @ vtcat^T) (M=2048, N=512, Kc=4096, batched)
    {
        dim3 grid(DIM / 128, SEQ / 128, BATCH);
        gemm_h<<<grid, 256, GEMM_DSMEM>>>(acat, vtcat, SEQ, DIM, KC_AV,
                                          (size_t)SEQ * KC_AV, (size_t)DIM * KC_AV,
                                          (size_t)SEQ * DIM, 1.0f,
                                          nullptr, nullptr, rinv,
                                          out, nullptr, 0, 0);
    }
}

// round 7
// speedup vs baseline: 5.3405x; 1.1358x over previous
#include <cuda_runtime.h>
#include <cuda_fp16.h>
#include <math.h>
#include <stdint.h>

#define BATCH 8
#define SEQ   2048
#define DIM   512
#define NCHUNK 16
#define KC_QKV  (2*DIM)   // 1024: [xh|xl] . [Wh|Wh]
#define KC_DOTS (2*DIM)   // 1024: [qh|ql] . [kh|kh]
#define KC_AV   (2*SEQ)   // 4096: [Ph|Pl] . [Vh|Vh]

static const float LN_EPS_F = 1e-5f;
static const float EPS_F    = 1e-8f;

// ---------------- scratch (static device globals; no allocation) ----------------
__device__ __align__(256) __half g_xncat[(size_t)BATCH * SEQ * KC_QKV];
__device__ __align__(256) __half g_cncat[(size_t)BATCH * SEQ * KC_QKV];
__device__ __align__(256) __half g_wqcat[(size_t)DIM * KC_QKV];
__device__ __align__(256) __half g_wkcat[(size_t)DIM * KC_QKV];
__device__ __align__(256) __half g_wvcat[(size_t)DIM * KC_QKV];
__device__ __align__(256) __half g_qcat [(size_t)BATCH * SEQ * KC_DOTS];
__device__ __align__(256) __half g_kcat [(size_t)BATCH * SEQ * KC_DOTS];
__device__ __align__(256) __half g_vtcat[(size_t)BATCH * DIM * KC_AV];
__device__ __align__(256) __half g_acat [(size_t)BATCH * SEQ * KC_AV];
__device__ __align__(256) float  g_dots [(size_t)BATCH * SEQ * SEQ];
__device__ float g_pm  [BATCH * NCHUNK * SEQ];
__device__ float g_ps  [BATCH * NCHUNK * SEQ];
__device__ float g_cm  [BATCH * SEQ];
__device__ float g_csi [BATCH * SEQ];
__device__ float g_rinv[BATCH * SEQ];

// ---------------- PTX helpers (baseline compute_103-safe) ----------------
__device__ __forceinline__ uint32_t smem_u32(const void* p) {
    uint32_t a;
    asm("{ .reg .u64 t; cvta.to.shared.u64 t, %1; cvt.u32.u64 %0, t; }" : "=r"(a) : "l"(p));
    return a;
}
__device__ __forceinline__ void cp_async16(uint32_t d, const void* g) {
    asm volatile("cp.async.cg.shared.global [%0], [%1], 16;" :: "r"(d), "l"(g));
}
__device__ __forceinline__ void cp_commit() {
    asm volatile("cp.async.commit_group;" ::: "memory");
}
template <int N>
__device__ __forceinline__ void cp_wait() {
    asm volatile("cp.async.wait_group %0;" :: "n"(N) : "memory");
}
__device__ __forceinline__ void ldsm4(uint32_t& r0, uint32_t& r1, uint32_t& r2, uint32_t& r3,
                                      uint32_t addr) {
    asm volatile("ldmatrix.sync.aligned.m8n8.x4.shared.b16 {%0,%1,%2,%3}, [%4];"
                 : "=r"(r0), "=r"(r1), "=r"(r2), "=r"(r3) : "r"(addr));
}
__device__ __forceinline__ void mma16816(float* c, const uint32_t* a, uint32_t b0, uint32_t b1) {
    asm volatile(
        "mma.sync.aligned.m16n8k16.row.col.f32.f16.f16.f32 "
        "{%0,%1,%2,%3}, {%4,%5,%6,%7}, {%8,%9}, {%0,%1,%2,%3};"
        : "+f"(c[0]), "+f"(c[1]), "+f"(c[2]), "+f"(c[3])
        : "r"(a[0]), "r"(a[1]), "r"(a[2]), "r"(a[3]), "r"(b0), "r"(b1));
}

__device__ __forceinline__ void split2h(float x, __half& h, __half& l) {
    h = __float2half_rn(x);
    l = __float2half_rn(x - __half2float(h));
}

// ---------------- HMMA split-fp16 GEMM ----------------
// C[M,N] = A[M,Kc] @ B[N,Kc]^T  (A,B fp16 K-major)
// pattern 0: outf = (acc*alpha + bias_col[col] + bias_row[row]) * rowscale[z*M+row]
// pattern 3: outh row length 2N, segments [h|h]
// pattern 4: outh row length 2N, segments [h|l]
// docol: write per-128-row-chunk column (max, sumexp) stats into g_pm/g_ps
#define BK 32
#define STAGES 5
#define A_STAGE (128 * 40 * 2)
#define STAGE_BYTES (2 * A_STAGE)
#define GEMM_DSMEM (STAGES * STAGE_BYTES)

__global__ void __launch_bounds__(256, 2) gemm_h(
    const __half* __restrict__ A, const __half* __restrict__ B,
    int M, int N, int Kc,
    size_t sA, size_t sB, size_t sC,
    float alpha,
    const float* __restrict__ bias_col, const float* __restrict__ bias_row,
    const float* __restrict__ rowscale,
    float* __restrict__ outf, __half* __restrict__ outh, int pattern, int docol)
{
    extern __shared__ char dyn[];
    uint32_t dynb = smem_u32(dyn);

    int z = blockIdx.z;
    const __half* Ab = A + (size_t)z * sA + (size_t)(blockIdx.y * 128) * Kc;
    const __half* Bb = B + (size_t)z * sB + (size_t)(blockIdx.x * 128) * Kc;
    int bm = blockIdx.y * 128;
    int bn = blockIdx.x * 128;

    int t = threadIdx.x;
    int wid = t >> 5, lane = t & 31;
    int wm = wid & 1;        // 2 warps over M (64 rows each)
    int wn = wid >> 1;       // 4 warps over N (32 cols each)

    float acc[4][4][4];
    #pragma unroll
    for (int i = 0; i < 4; i++)
        #pragma unroll
        for (int j = 0; j < 4; j++)
            #pragma unroll
            for (int r = 0; r < 4; r++) acc[i][j][r] = 0.0f;

    int nkb = Kc / BK;

    auto issue = [&](int kb) {
        int slot = kb % STAGES;
        uint32_t sa = dynb + slot * STAGE_BYTES;
        uint32_t sb = sa + A_STAGE;
        int kh = kb * BK;
        #pragma unroll
        for (int i = 0; i < 2; i++) {
            int idx = t + 256 * i;
            int row = idx >> 2, c = idx & 3;
            cp_async16(sa + row * 80 + c * 16, Ab + (size_t)row * Kc + kh + c * 8);
        }
        #pragma unroll
        for (int i = 0; i < 2; i++) {
            int idx = t + 256 * i;
            int row = idx >> 2, c = idx & 3;
            cp_async16(sb + row * 80 + c * 16, Bb + (size_t)row * Kc + kh + c * 8);
        }
    };

    issue(0); cp_commit();
    issue(1); cp_commit();
    issue(2); cp_commit();
    issue(3); cp_commit();

    uint32_t a_lane = (uint32_t)((wm * 64 + (lane & 15)) * 80 + ((lane >> 4) * 8) * 2);
    uint32_t b_lane = (uint32_t)(A_STAGE +
                       (wn * 32 + (lane & 7) + (lane >> 4) * 8) * 80 +
                       (((lane >> 3) & 1) * 8) * 2);

    cp_wait<2>();          // slots 0 and 1 ready
    __syncthreads();

    uint32_t af[2][4][4];  // A fragments, double buffered
    uint32_t bf[2][4];     // B fragments, single buffered

    {
        uint32_t sb0 = dynb;
        #pragma unroll
        for (int mi = 0; mi < 4; mi++)
            ldsm4(af[0][mi][0], af[0][mi][1], af[0][mi][2], af[0][mi][3],
                  sb0 + a_lane + mi * (16 * 80));
    }

    int p = 0;
    for (int kb = 0; kb < nkb; kb++) {
        if (kb + 4 < nkb) issue(kb + 4);
        cp_commit();
        uint32_t scur = dynb + (kb % STAGES) * STAGE_BYTES;
        uint32_t snxt = dynb + ((kb + 1) % STAGES) * STAGE_BYTES;

        // ---- ks = 0 ----
        #pragma unroll
        for (int g = 0; g < 2; g++)
            ldsm4(bf[g][0], bf[g][1], bf[g][2], bf[g][3],
                  scur + b_lane + g * (16 * 80));
        #pragma unroll
        for (int mi = 0; mi < 4; mi++)   // prefetch A for ks=1
            ldsm4(af[p^1][mi][0], af[p^1][mi][1], af[p^1][mi][2], af[p^1][mi][3],
                  scur + a_lane + mi * (16 * 80) + 32);
        #pragma unroll
        for (int mi = 0; mi < 4; mi++)
            #pragma unroll
            for (int ni = 0; ni < 4; ni++)
                mma16816(acc[mi][ni], af[p][mi],
                         bf[ni >> 1][(ni & 1) * 2], bf[ni >> 1][(ni & 1) * 2 + 1]);
        p ^= 1;

        // ---- ks = 1 ----
        #pragma unroll
        for (int g = 0; g < 2; g++)
            ldsm4(bf[g][0], bf[g][1], bf[g][2], bf[g][3],
                  scur + b_lane + g * (16 * 80) + 32);
        if (kb + 1 < nkb) {
            #pragma unroll
            for (int mi = 0; mi < 4; mi++)  // prefetch A for next stage ks=0
                ldsm4(af[p^1][mi][0], af[p^1][mi][1], af[p^1][mi][2], af[p^1][mi][3],
                      snxt + a_lane + mi * (16 * 80));
        }
        #pragma unroll
        for (int mi = 0; mi < 4; mi++)
            #pragma unroll
            for (int ni = 0; ni < 4; ni++)
                mma16816(acc[mi][ni], af[p][mi],
                         bf[ni >> 1][(ni & 1) * 2], bf[ni >> 1][(ni & 1) * 2 + 1]);
        p ^= 1;

        cp_wait<2>();
        __syncthreads();
    }

    // ---------------- store epilogue ----------------
    int r_lane = lane >> 2;
    int c_lane = (lane & 3) * 2;
    #pragma unroll
    for (int mi = 0; mi < 4; mi++) {
        #pragma unroll
        for (int ni = 0; ni < 4; ni++) {
            int row = bm + wm * 64 + mi * 16 + r_lane;
            int col = bn + wn * 32 + ni * 8 + c_lane;
            float* a4 = acc[mi][ni];
            float bc0 = bias_col ? bias_col[col]     : 0.0f;
            float bc1 = bias_col ? bias_col[col + 1] : 0.0f;
            #pragma unroll
            for (int h = 0; h < 2; h++) {
                int rr = row + h * 8;
                float br = bias_row ? bias_row[rr] : 0.0f;
                float v0 = a4[h * 2 + 0] * alpha + bc0 + br;
                float v1 = a4[h * 2 + 1] * alpha + bc1 + br;
                if (pattern == 0) {
                    float rs = rowscale ? rowscale[(size_t)z * M + rr] : 1.0f;
                    float2 o = make_float2(v0 * rs, v1 * rs);
                    *(float2*)(outf + (size_t)z * sC + (size_t)rr * N + col) = o;
                } else if (pattern == 3) {
                    __half2 hh = __halves2half2(__float2half_rn(v0), __float2half_rn(v1));
                    __half* ob = outh + (size_t)z * sC + (size_t)rr * (2 * N) + col;
                    *(__half2*)(ob)     = hh;
                    *(__half2*)(ob + N) = hh;
                } else {  // pattern 4: [h|l]
                    __half h0, l0, h1, l1;
                    split2h(v0, h0, l0);
                    split2h(v1, h1, l1);
                    __half* ob = outh + (size_t)z * sC + (size_t)rr * (2 * N) + col;
                    *(__half2*)(ob)     = __halves2half2(h0, h1);
                    *(__half2*)(ob + N) = __halves2half2(l0, l1);
                }
            }
        }
    }

    // ---------------- fused column stats (dots only) ----------------
    if (docol) {
        cp_wait<0>();
        __syncthreads();
        float* smx = (float*)dyn;
        float* ssm = (float*)dyn + 256;

        float cmax[4][2], csum[4][2];
        #pragma unroll
        for (int ni = 0; ni < 4; ni++) {
            #pragma unroll
            for (int c = 0; c < 2; c++) {
                float m = -1e30f;
                #pragma unroll
                for (int mi = 0; mi < 4; mi++)
                    #pragma unroll
                    for (int h = 0; h < 2; h++)
                        m = fmaxf(m, acc[mi][ni][h * 2 + c] * alpha);
                float s = 0.0f;
                #pragma unroll
                for (int mi = 0; mi < 4; mi++)
                    #pragma unroll
                    for (int h = 0; h < 2; h++)
                        s += __expf(acc[mi][ni][h * 2 + c] * alpha - m);
                cmax[ni][c] = m;
                csum[ni][c] = s;
            }
        }
        #pragma unroll
        for (int o = 4; o < 32; o <<= 1) {
            #pragma unroll
            for (int ni = 0; ni < 4; ni++)
                #pragma unroll
                for (int c = 0; c < 2; c++) {
                    float mo = __shfl_xor_sync(0xffffffffu, cmax[ni][c], o);
                    float so = __shfl_xor_sync(0xffffffffu, csum[ni][c], o);
                    float m = fmaxf(cmax[ni][c], mo);
                    csum[ni][c] = csum[ni][c] * __expf(cmax[ni][c] - m) +
                                  so * __expf(mo - m);
                    cmax[ni][c] = m;
                }
        }
        if ((lane >> 2) == 0) {
            #pragma unroll
            for (int ni = 0; ni < 4; ni++)
                #pragma unroll
                for (int c = 0; c < 2; c++) {
                    int col = wn * 32 + ni * 8 + (lane & 3) * 2 + c;
                    smx[wm * 128 + col] = cmax[ni][c];
                    ssm[wm * 128 + col] = csum[ni][c];
                }
        }
        __syncthreads();
        if (t < 128) {
            float m0 = smx[t], m1 = smx[128 + t];
            float s0 = ssm[t], s1 = ssm[128 + t];
            float m = fmaxf(m0, m1);
            float s = s0 * __expf(m0 - m) + s1 * __expf(m1 - m);
            size_t o = ((size_t)z * NCHUNK + blockIdx.y) * SEQ + bn + t;
            g_pm[o] = m;
            g_ps[o] = s;
        }
    }
}

// ---------------- LayerNorm + split [h|l]: out [rows, 1024] fp16 ----
__global__ void __launch_bounds__(128) ln_cat_kernel(const float* __restrict__ x,
                                                     const float* __restrict__ g,
                                                     const float* __restrict__ b,
                                                     __half* __restrict__ y) {
    int row = blockIdx.x;
    int t = threadIdx.x;
    float4 v = ((const float4*)(x + (size_t)row * DIM))[t];
    float s  = v.x + v.y + v.z + v.w;
    float ss = v.x*v.x + v.y*v.y + v.z*v.z + v.w*v.w;
    __shared__ float sh[8];
    #pragma unroll
    for (int o = 16; o > 0; o >>= 1) {
        s  += __shfl_down_sync(0xffffffffu, s, o);
        ss += __shfl_down_sync(0xffffffffu, ss, o);
    }
    if ((t & 31) == 0) { sh[t >> 5] = s; sh[4 + (t >> 5)] = ss; }
    __syncthreads();
    float fs  = sh[0] + sh[1] + sh[2] + sh[3];
    float fss = sh[4] + sh[5] + sh[6] + sh[7];
    float mu  = fs * (1.0f / DIM);
    float var = fss * (1.0f / DIM) - mu * mu;
    float rstd = rsqrtf(var + LN_EPS_F);
    float4 gv = ((const float4*)g)[t];
    float4 bv = ((const float4*)b)[t];
    float o0 = (v.x - mu) * rstd * gv.x + bv.x;
    float o1 = (v.y - mu) * rstd * gv.y + bv.y;
    float o2 = (v.z - mu) * rstd * gv.z + bv.z;
    float o3 = (v.w - mu) * rstd * gv.w + bv.w;
    __half h0,h1,h2,h3,l0,l1,l2,l3;
    split2h(o0,h0,l0); split2h(o1,h1,l1); split2h(o2,h2,l2); split2h(o3,h3,l3);
    __half* yb = y + (size_t)row * KC_QKV + t * 4;
    ((__half2*)yb)[0] = __halves2half2(h0, h1);
    ((__half2*)yb)[1] = __halves2half2(h2, h3);
    ((__half2*)(yb + DIM))[0] = __halves2half2(l0, l1);
    ((__half2*)(yb + DIM))[1] = __halves2half2(l2, l3);
}

// ---------------- weight transpose [Wh|Wh]: W[512,512] -> [512,1024] ----
__global__ void __launch_bounds__(256) tsplit_kernel(const float* __restrict__ in,
                                                     __half* __restrict__ out) {
    __shared__ float tile[32][33];
    int r0 = blockIdx.y * 32, c0 = blockIdx.x * 32;
    int tx = threadIdx.x & 31, ty = threadIdx.x >> 5;
    #pragma unroll
    for (int i = ty; i < 32; i += 8)
        tile[i][tx] = in[(size_t)(r0 + i) * DIM + c0 + tx];
    __syncthreads();
    #pragma unroll
    for (int i = ty; i < 32; i += 8) {
        __half h = __float2half_rn(tile[tx][i]);
        __half* o = out + (size_t)(c0 + i) * KC_QKV + r0 + tx;
        o[0] = h;
        o[DIM] = h;
    }
}

// ---------------- column stats combine -> colmax, 1/colsum ----------------
__global__ void __launch_bounds__(256) colstats2_kernel() {
    int j = blockIdx.x * 256 + threadIdx.x;
    int z = blockIdx.y;
    float m = -1e30f;
    #pragma unroll
    for (int c = 0; c < NCHUNK; c++)
        m = fmaxf(m, g_pm[((size_t)z * NCHUNK + c) * SEQ + j]);
    float s = 0.0f;
    #pragma unroll
    for (int c = 0; c < NCHUNK; c++)
        s += g_ps[((size_t)z * NCHUNK + c) * SEQ + j] *
             __expf(g_pm[((size_t)z * NCHUNK + c) * SEQ + j] - m);
    g_cm [(size_t)z * SEQ + j] = m;
    g_csi[(size_t)z * SEQ + j] = 1.0f / s;
}

// ---------------- row pass: Araw=softmax+EPS -> acat [Ph|Pl], rinv -----
__global__ void __launch_bounds__(256) rowpass_kernel() {
    int i = blockIdx.x;
    int z = blockIdx.y;
    int t = threadIdx.x;
    const float* row = g_dots + ((size_t)z * SEQ + i) * SEQ;
    const float* cm = g_cm  + (size_t)z * SEQ;
    const float* ci = g_csi + (size_t)z * SEQ;
    __half* ab = g_acat + ((size_t)z * SEQ + i) * KC_AV;
    float acc = 0.0f;
    #pragma unroll 2
    for (int j2 = t; j2 < SEQ / 2; j2 += 256) {
        int j = j2 * 2;
        float2 d = *(const float2*)(row + j);
        float2 m2 = *(const float2*)(cm + j);
        float2 c2 = *(const float2*)(ci + j);
        float a0 = __expf(d.x - m2.x) * c2.x + EPS_F;
        float a1 = __expf(d.y - m2.y) * c2.y + EPS_F;
        acc += a0 + a1;
        __half h0, l0, h1, l1;
        split2h(a0, h0, l0);
        split2h(a1, h1, l1);
        *(__half2*)(ab + j)       = __halves2half2(h0, h1);
        *(__half2*)(ab + SEQ + j) = __halves2half2(l0, l1);
    }
    __shared__ float sh[8];
    #pragma unroll
    for (int o = 16; o > 0; o >>= 1)
        acc += __shfl_down_sync(0xffffffffu, acc, o);
    if ((t & 31) == 0) sh[t >> 5] = acc;
    __syncthreads();
    if (t == 0) {
        float s = 0.0f;
        #pragma unroll
        for (int w = 0; w < 8; w++) s += sh[w];
        g_rinv[(size_t)z * SEQ + i] = 1.0f / (s + EPS_F);
    }
}

// ---------------- launch ----------------
extern "C" void kernel_launch(void* const* d_in, const int* in_sizes, int n_in,
                              void* d_out, int out_size) {
    const float* inputs  = (const float*)d_in[0];
    const float* context = (const float*)d_in[1];
    const float* gin  = (const float*)d_in[2];
    const float* bin  = (const float*)d_in[3];
    const float* gctx = (const float*)d_in[4];
    const float* bctx = (const float*)d_in[5];
    const float* Wq = (const float*)d_in[6];
    const float* bq = (const float*)d_in[7];
    const float* Wk = (const float*)d_in[8];
    const float* bk = (const float*)d_in[9];
    const float* Wv = (const float*)d_in[10];
    const float* bv = (const float*)d_in[11];
    float* out = (float*)d_out;

    __half *xncat, *cncat, *wqcat, *wkcat, *wvcat, *qcat, *kcat, *vtcat, *acat;
    float *dots, *rinv;
    cudaGetSymbolAddress((void**)&xncat, g_xncat);
    cudaGetSymbolAddress((void**)&cncat, g_cncat);
    cudaGetSymbolAddress((void**)&wqcat, g_wqcat);
    cudaGetSymbolAddress((void**)&wkcat, g_wkcat);
    cudaGetSymbolAddress((void**)&wvcat, g_wvcat);
    cudaGetSymbolAddress((void**)&qcat,  g_qcat);
    cudaGetSymbolAddress((void**)&kcat,  g_kcat);
    cudaGetSymbolAddress((void**)&vtcat, g_vtcat);
    cudaGetSymbolAddress((void**)&acat,  g_acat);
    cudaGetSymbolAddress((void**)&dots,  g_dots);
    cudaGetSymbolAddress((void**)&rinv,  g_rinv);

    cudaFuncSetAttribute(gemm_h, cudaFuncAttributeMaxDynamicSharedMemorySize, GEMM_DSMEM);

    // LayerNorm + split [h|l]
    ln_cat_kernel<<<BATCH * SEQ, 128>>>(inputs,  gin,  bin,  xncat);
    ln_cat_kernel<<<BATCH * SEQ, 128>>>(context, gctx, bctx, cncat);

    // weight transposes [Wh|Wh]
    {
        dim3 g(DIM / 32, DIM / 32, 1);
        tsplit_kernel<<<g, 256>>>(Wq, wqcat);
        tsplit_kernel<<<g, 256>>>(Wk, wkcat);
        tsplit_kernel<<<g, 256>>>(Wv, wvcat);
    }

    // q = LN(x)@Wq + bq -> [qh|ql] (M=16384, N=512, Kc=1024)
    {
        dim3 grid(DIM / 128, (BATCH * SEQ) / 128, 1);
        gemm_h<<<grid, 256, GEMM_DSMEM>>>(xncat, wqcat, BATCH * SEQ, DIM, KC_QKV,
                                          0, 0, 0, 1.0f, bq, nullptr, nullptr,
                                          nullptr, qcat, 4, 0);
        // k -> [kh|kh]
        gemm_h<<<grid, 256, GEMM_DSMEM>>>(cncat, wkcat, BATCH * SEQ, DIM, KC_QKV,
                                          0, 0, 0, 1.0f, bk, nullptr, nullptr,
                                          nullptr, kcat, 3, 0);
    }

    // vt[d,j] = (c@Wv + bv)^T -> [Vh|Vh] (M=512, N=2048, Kc=1024, batched)
    {
        dim3 grid(SEQ / 128, DIM / 128, BATCH);
        gemm_h<<<grid, 256, GEMM_DSMEM>>>(wvcat, cncat, DIM, SEQ, KC_QKV,
                                          0, (size_t)SEQ * KC_QKV, (size_t)DIM * KC_AV,
                                          1.0f, nullptr, bv, nullptr,
                                          nullptr, vtcat, 3, 0);
    }

    // dots = scale * q @ k^T (fp32 out, Kc=1024, batched) + fused column stats
    {
        float scale = 1.0f / sqrtf((float)DIM);
        dim3 grid(SEQ / 128, SEQ / 128, BATCH);
        gemm_h<<<grid, 256, GEMM_DSMEM>>>(qcat, kcat, SEQ, SEQ, KC_DOTS,
                                          (size_t)SEQ * KC_DOTS, (size_t)SEQ * KC_DOTS,
                                          (size_t)SEQ * SEQ, scale,
                                          nullptr, nullptr, nullptr,
                                          dots, nullptr, 0, 1);
    }

    // softmax combine + rowpass -> acat [Ph|Pl], rinv
    colstats2_kernel<<<dim3(SEQ / 256, BATCH), 256>>>();
    rowpass_kernel<<<dim3(SEQ, BATCH), 256>>>();

    // out = rinv[i] * (acat @ vtcat^T) (M=2048, N=512, Kc=4096, batched)
    {
        dim3 grid(DIM / 128, SEQ / 128, BATCH);
        gemm_h<<<grid, 256, GEMM_DSMEM>>>(acat, vtcat, SEQ, DIM, KC_AV,
                                          (size_t)SEQ * KC_AV, (size_t)DIM * KC_AV,
                                          (size_t)SEQ * DIM, 1.0f,
                                          nullptr, nullptr, rinv,
                                          out, nullptr, 0, 0);
    }
}

// round 8
// speedup vs baseline: 9.0311x; 1.6911x over previous
#include <cuda_runtime.h>
#include <cuda_fp16.h>
#include <math.h>
#include <stdint.h>

#define BATCH 8
#define SEQ   2048
#define DIM   512
#define NCHUNK 16

static const float LN_EPS_F = 1e-5f;
static const float EPS_F    = 1e-8f;

// ---------------- scratch (static device globals; no allocation) ----------------
__device__ __align__(256) __half g_xn [(size_t)BATCH * SEQ * DIM];
__device__ __align__(256) __half g_cn [(size_t)BATCH * SEQ * DIM];
__device__ __align__(256) __half g_wqt[(size_t)DIM * DIM];
__device__ __align__(256) __half g_wkt[(size_t)DIM * DIM];
__device__ __align__(256) __half g_wvt[(size_t)DIM * DIM];
__device__ __align__(256) __half g_q  [(size_t)BATCH * SEQ * DIM];
__device__ __align__(256) __half g_k  [(size_t)BATCH * SEQ * DIM];
__device__ __align__(256) __half g_vt [(size_t)BATCH * DIM * SEQ];
__device__ __align__(256) __half g_p  [(size_t)BATCH * SEQ * SEQ];
__device__ __align__(256) float  g_dots[(size_t)BATCH * SEQ * SEQ];
__device__ float g_pm  [BATCH * NCHUNK * SEQ];
__device__ float g_ps  [BATCH * NCHUNK * SEQ];
__device__ float g_cm  [BATCH * SEQ];
__device__ float g_csi [BATCH * SEQ];
__device__ float g_rinv[BATCH * SEQ];

// ---------------- PTX helpers (baseline compute_103-safe) ----------------
__device__ __forceinline__ uint32_t smem_u32(const void* p) {
    uint32_t a;
    asm("{ .reg .u64 t; cvta.to.shared.u64 t, %1; cvt.u32.u64 %0, t; }" : "=r"(a) : "l"(p));
    return a;
}
__device__ __forceinline__ void cp_async16(uint32_t d, const void* g) {
    asm volatile("cp.async.cg.shared.global [%0], [%1], 16;" :: "r"(d), "l"(g));
}
__device__ __forceinline__ void cp_commit() {
    asm volatile("cp.async.commit_group;" ::: "memory");
}
template <int N>
__device__ __forceinline__ void cp_wait() {
    asm volatile("cp.async.wait_group %0;" :: "n"(N) : "memory");
}
__device__ __forceinline__ void ldsm4(uint32_t& r0, uint32_t& r1, uint32_t& r2, uint32_t& r3,
                                      uint32_t addr) {
    asm volatile("ldmatrix.sync.aligned.m8n8.x4.shared.b16 {%0,%1,%2,%3}, [%4];"
                 : "=r"(r0), "=r"(r1), "=r"(r2), "=r"(r3) : "r"(addr));
}
__device__ __forceinline__ void mma16816(float* c, const uint32_t* a, uint32_t b0, uint32_t b1) {
    asm volatile(
        "mma.sync.aligned.m16n8k16.row.col.f32.f16.f16.f32 "
        "{%0,%1,%2,%3}, {%4,%5,%6,%7}, {%8,%9}, {%0,%1,%2,%3};"
        : "+f"(c[0]), "+f"(c[1]), "+f"(c[2]), "+f"(c[3])
        : "r"(a[0]), "r"(a[1]), "r"(a[2]), "r"(a[3]), "r"(b0), "r"(b1));
}

// ---------------- HMMA plain-fp16 GEMM ----------------
// C[M,N] = A[M,Kc] @ B[N,Kc]^T  (A,B fp16 K-major)
// pattern 0: outf = (acc*alpha + bias_col[col] + bias_row[row]) * rowscale[z*M+row]
// pattern 5: outh = fp16(acc*alpha + bias_col[col] + bias_row[row]), row length N
// docol: write per-128-row-chunk column (max, sumexp) stats into g_pm/g_ps
#define BK 32
#define STAGES 5
#define A_STAGE (128 * 40 * 2)
#define STAGE_BYTES (2 * A_STAGE)
#define GEMM_DSMEM (STAGES * STAGE_BYTES)

__global__ void __launch_bounds__(256, 2) gemm_h(
    const __half* __restrict__ A, const __half* __restrict__ B,
    int M, int N, int Kc,
    size_t sA, size_t sB, size_t sC,
    float alpha,
    const float* __restrict__ bias_col, const float* __restrict__ bias_row,
    const float* __restrict__ rowscale,
    float* __restrict__ outf, __half* __restrict__ outh, int pattern, int docol)
{
    extern __shared__ char dyn[];
    uint32_t dynb = smem_u32(dyn);

    int z = blockIdx.z;
    const __half* Ab = A + (size_t)z * sA + (size_t)(blockIdx.y * 128) * Kc;
    const __half* Bb = B + (size_t)z * sB + (size_t)(blockIdx.x * 128) * Kc;
    int bm = blockIdx.y * 128;
    int bn = blockIdx.x * 128;

    int t = threadIdx.x;
    int wid = t >> 5, lane = t & 31;
    int wm = wid & 1;        // 2 warps over M (64 rows each)
    int wn = wid >> 1;       // 4 warps over N (32 cols each)

    float acc[4][4][4];
    #pragma unroll
    for (int i = 0; i < 4; i++)
        #pragma unroll
        for (int j = 0; j < 4; j++)
            #pragma unroll
            for (int r = 0; r < 4; r++) acc[i][j][r] = 0.0f;

    int nkb = Kc / BK;

    auto issue = [&](int kb) {
        int slot = kb % STAGES;
        uint32_t sa = dynb + slot * STAGE_BYTES;
        uint32_t sb = sa + A_STAGE;
        int kh = kb * BK;
        #pragma unroll
        for (int i = 0; i < 2; i++) {
            int idx = t + 256 * i;
            int row = idx >> 2, c = idx & 3;
            cp_async16(sa + row * 80 + c * 16, Ab + (size_t)row * Kc + kh + c * 8);
        }
        #pragma unroll
        for (int i = 0; i < 2; i++) {
            int idx = t + 256 * i;
            int row = idx >> 2, c = idx & 3;
            cp_async16(sb + row * 80 + c * 16, Bb + (size_t)row * Kc + kh + c * 8);
        }
    };

    issue(0); cp_commit();
    issue(1); cp_commit();
    issue(2); cp_commit();
    issue(3); cp_commit();

    uint32_t a_lane = (uint32_t)((wm * 64 + (lane & 15)) * 80 + ((lane >> 4) * 8) * 2);
    uint32_t b_lane = (uint32_t)(A_STAGE +
                       (wn * 32 + (lane & 7) + (lane >> 4) * 8) * 80 +
                       (((lane >> 3) & 1) * 8) * 2);

    cp_wait<2>();          // slots 0 and 1 ready
    __syncthreads();

    uint32_t af[2][4][4];  // A fragments, double buffered
    uint32_t bf[2][4];     // B fragments, single buffered

    {
        uint32_t sb0 = dynb;
        #pragma unroll
        for (int mi = 0; mi < 4; mi++)
            ldsm4(af[0][mi][0], af[0][mi][1], af[0][mi][2], af[0][mi][3],
                  sb0 + a_lane + mi * (16 * 80));
    }

    int p = 0;
    for (int kb = 0; kb < nkb; kb++) {
        if (kb + 4 < nkb) issue(kb + 4);
        cp_commit();
        uint32_t scur = dynb + (kb % STAGES) * STAGE_BYTES;
        uint32_t snxt = dynb + ((kb + 1) % STAGES) * STAGE_BYTES;

        // ---- ks = 0 ----
        #pragma unroll
        for (int g = 0; g < 2; g++)
            ldsm4(bf[g][0], bf[g][1], bf[g][2], bf[g][3],
                  scur + b_lane + g * (16 * 80));
        #pragma unroll
        for (int mi = 0; mi < 4; mi++)   // prefetch A for ks=1
            ldsm4(af[p^1][mi][0], af[p^1][mi][1], af[p^1][mi][2], af[p^1][mi][3],
                  scur + a_lane + mi * (16 * 80) + 32);
        #pragma unroll
        for (int mi = 0; mi < 4; mi++)
            #pragma unroll
            for (int ni = 0; ni < 4; ni++)
                mma16816(acc[mi][ni], af[p][mi],
                         bf[ni >> 1][(ni & 1) * 2], bf[ni >> 1][(ni & 1) * 2 + 1]);
        p ^= 1;

        // ---- ks = 1 ----
        #pragma unroll
        for (int g = 0; g < 2; g++)
            ldsm4(bf[g][0], bf[g][1], bf[g][2], bf[g][3],
                  scur + b_lane + g * (16 * 80) + 32);
        if (kb + 1 < nkb) {
            #pragma unroll
            for (int mi = 0; mi < 4; mi++)  // prefetch A for next stage ks=0
                ldsm4(af[p^1][mi][0], af[p^1][mi][1], af[p^1][mi][2], af[p^1][mi][3],
                      snxt + a_lane + mi * (16 * 80));
        }
        #pragma unroll
        for (int mi = 0; mi < 4; mi++)
            #pragma unroll
            for (int ni = 0; ni < 4; ni++)
                mma16816(acc[mi][ni], af[p][mi],
                         bf[ni >> 1][(ni & 1) * 2], bf[ni >> 1][(ni & 1) * 2 + 1]);
        p ^= 1;

        cp_wait<2>();
        __syncthreads();
    }

    // ---------------- store epilogue ----------------
    int r_lane = lane >> 2;
    int c_lane = (lane & 3) * 2;
    #pragma unroll
    for (int mi = 0; mi < 4; mi++) {
        #pragma unroll
        for (int ni = 0; ni < 4; ni++) {
            int row = bm + wm * 64 + mi * 16 + r_lane;
            int col = bn + wn * 32 + ni * 8 + c_lane;
            float* a4 = acc[mi][ni];
            float bc0 = bias_col ? bias_col[col]     : 0.0f;
            float bc1 = bias_col ? bias_col[col + 1] : 0.0f;
            #pragma unroll
            for (int h = 0; h < 2; h++) {
                int rr = row + h * 8;
                float br = bias_row ? bias_row[rr] : 0.0f;
                float v0 = a4[h * 2 + 0] * alpha + bc0 + br;
                float v1 = a4[h * 2 + 1] * alpha + bc1 + br;
                if (pattern == 0) {
                    float rs = rowscale ? rowscale[(size_t)z * M + rr] : 1.0f;
                    float2 o = make_float2(v0 * rs, v1 * rs);
                    *(float2*)(outf + (size_t)z * sC + (size_t)rr * N + col) = o;
                } else {  // pattern 5: plain fp16
                    __half2 hh = __halves2half2(__float2half_rn(v0), __float2half_rn(v1));
                    *(__half2*)(outh + (size_t)z * sC + (size_t)rr * N + col) = hh;
                }
            }
        }
    }

    // ---------------- fused column stats (dots only) ----------------
    if (docol) {
        cp_wait<0>();
        __syncthreads();
        float* smx = (float*)dyn;
        float* ssm = (float*)dyn + 256;

        float cmax[4][2], csum[4][2];
        #pragma unroll
        for (int ni = 0; ni < 4; ni++) {
            #pragma unroll
            for (int c = 0; c < 2; c++) {
                float m = -1e30f;
                #pragma unroll
                for (int mi = 0; mi < 4; mi++)
                    #pragma unroll
                    for (int h = 0; h < 2; h++)
                        m = fmaxf(m, acc[mi][ni][h * 2 + c] * alpha);
                float s = 0.0f;
                #pragma unroll
                for (int mi = 0; mi < 4; mi++)
                    #pragma unroll
                    for (int h = 0; h < 2; h++)
                        s += __expf(acc[mi][ni][h * 2 + c] * alpha - m);
                cmax[ni][c] = m;
                csum[ni][c] = s;
            }
        }
        #pragma unroll
        for (int o = 4; o < 32; o <<= 1) {
            #pragma unroll
            for (int ni = 0; ni < 4; ni++)
                #pragma unroll
                for (int c = 0; c < 2; c++) {
                    float mo = __shfl_xor_sync(0xffffffffu, cmax[ni][c], o);
                    float so = __shfl_xor_sync(0xffffffffu, csum[ni][c], o);
                    float m = fmaxf(cmax[ni][c], mo);
                    csum[ni][c] = csum[ni][c] * __expf(cmax[ni][c] - m) +
                                  so * __expf(mo - m);
                    cmax[ni][c] = m;
                }
        }
        if ((lane >> 2) == 0) {
            #pragma unroll
            for (int ni = 0; ni < 4; ni++)
                #pragma unroll
                for (int c = 0; c < 2; c++) {
                    int col = wn * 32 + ni * 8 + (lane & 3) * 2 + c;
                    smx[wm * 128 + col] = cmax[ni][c];
                    ssm[wm * 128 + col] = csum[ni][c];
                }
        }
        __syncthreads();
        if (t < 128) {
            float m0 = smx[t], m1 = smx[128 + t];
            float s0 = ssm[t], s1 = ssm[128 + t];
            float m = fmaxf(m0, m1);
            float s = s0 * __expf(m0 - m) + s1 * __expf(m1 - m);
            size_t o = ((size_t)z * NCHUNK + blockIdx.y) * SEQ + bn + t;
            g_pm[o] = m;
            g_ps[o] = s;
        }
    }
}

// ---------------- LayerNorm -> fp16 [rows, 512] ----
__global__ void __launch_bounds__(128) ln_kernel(const float* __restrict__ x,
                                                 const float* __restrict__ g,
                                                 const float* __restrict__ b,
                                                 __half* __restrict__ y) {
    int row = blockIdx.x;
    int t = threadIdx.x;
    float4 v = ((const float4*)(x + (size_t)row * DIM))[t];
    float s  = v.x + v.y + v.z + v.w;
    float ss = v.x*v.x + v.y*v.y + v.z*v.z + v.w*v.w;
    __shared__ float sh[8];
    #pragma unroll
    for (int o = 16; o > 0; o >>= 1) {
        s  += __shfl_down_sync(0xffffffffu, s, o);
        ss += __shfl_down_sync(0xffffffffu, ss, o);
    }
    if ((t & 31) == 0) { sh[t >> 5] = s; sh[4 + (t >> 5)] = ss; }
    __syncthreads();
    float fs  = sh[0] + sh[1] + sh[2] + sh[3];
    float fss = sh[4] + sh[5] + sh[6] + sh[7];
    float mu  = fs * (1.0f / DIM);
    float var = fss * (1.0f / DIM) - mu * mu;
    float rstd = rsqrtf(var + LN_EPS_F);
    float4 gv = ((const float4*)g)[t];
    float4 bv = ((const float4*)b)[t];
    float o0 = (v.x - mu) * rstd * gv.x + bv.x;
    float o1 = (v.y - mu) * rstd * gv.y + bv.y;
    float o2 = (v.z - mu) * rstd * gv.z + bv.z;
    float o3 = (v.w - mu) * rstd * gv.w + bv.w;
    __half* yb = y + (size_t)row * DIM + t * 4;
    ((__half2*)yb)[0] = __halves2half2(__float2half_rn(o0), __float2half_rn(o1));
    ((__half2*)yb)[1] = __halves2half2(__float2half_rn(o2), __float2half_rn(o3));
}

// ---------------- weight transpose: W[512,512] fp32 -> Wt[512,512] fp16 ----
__global__ void __launch_bounds__(256) tsplit_kernel(const float* __restrict__ in,
                                                     __half* __restrict__ out) {
    __shared__ float tile[32][33];
    int r0 = blockIdx.y * 32, c0 = blockIdx.x * 32;
    int tx = threadIdx.x & 31, ty = threadIdx.x >> 5;
    #pragma unroll
    for (int i = ty; i < 32; i += 8)
        tile[i][tx] = in[(size_t)(r0 + i) * DIM + c0 + tx];
    __syncthreads();
    #pragma unroll
    for (int i = ty; i < 32; i += 8)
        out[(size_t)(c0 + i) * DIM + r0 + tx] = __float2half_rn(tile[tx][i]);
}

// ---------------- column stats combine -> colmax, 1/colsum ----------------
__global__ void __launch_bounds__(256) colstats2_kernel() {
    int j = blockIdx.x * 256 + threadIdx.x;
    int z = blockIdx.y;
    float m = -1e30f;
    #pragma unroll
    for (int c = 0; c < NCHUNK; c++)
        m = fmaxf(m, g_pm[((size_t)z * NCHUNK + c) * SEQ + j]);
    float s = 0.0f;
    #pragma unroll
    for (int c = 0; c < NCHUNK; c++)
        s += g_ps[((size_t)z * NCHUNK + c) * SEQ + j] *
             __expf(g_pm[((size_t)z * NCHUNK + c) * SEQ + j] - m);
    g_cm [(size_t)z * SEQ + j] = m;
    g_csi[(size_t)z * SEQ + j] = 1.0f / s;
}

// ---------------- row pass: P = softmax+EPS (fp16), rinv ----------------
__global__ void __launch_bounds__(256) rowpass_kernel() {
    int i = blockIdx.x;
    int z = blockIdx.y;
    int t = threadIdx.x;
    const float* row = g_dots + ((size_t)z * SEQ + i) * SEQ;
    const float* cm = g_cm  + (size_t)z * SEQ;
    const float* ci = g_csi + (size_t)z * SEQ;
    __half* ab = g_p + ((size_t)z * SEQ + i) * SEQ;
    float acc = 0.0f;
    #pragma unroll 2
    for (int j2 = t; j2 < SEQ / 2; j2 += 256) {
        int j = j2 * 2;
        float2 d = *(const float2*)(row + j);
        float2 m2 = *(const float2*)(cm + j);
        float2 c2 = *(const float2*)(ci + j);
        float a0 = __expf(d.x - m2.x) * c2.x + EPS_F;
        float a1 = __expf(d.y - m2.y) * c2.y + EPS_F;
        acc += a0 + a1;
        *(__half2*)(ab + j) = __halves2half2(__float2half_rn(a0), __float2half_rn(a1));
    }
    __shared__ float sh[8];
    #pragma unroll
    for (int o = 16; o > 0; o >>= 1)
        acc += __shfl_down_sync(0xffffffffu, acc, o);
    if ((t & 31) == 0) sh[t >> 5] = acc;
    __syncthreads();
    if (t == 0) {
        float s = 0.0f;
        #pragma unroll
        for (int w = 0; w < 8; w++) s += sh[w];
        g_rinv[(size_t)z * SEQ + i] = 1.0f / (s + EPS_F);
    }
}

// ---------------- launch ----------------
extern "C" void kernel_launch(void* const* d_in, const int* in_sizes, int n_in,
                              void* d_out, int out_size) {
    const float* inputs  = (const float*)d_in[0];
    const float* context = (const float*)d_in[1];
    const float* gin  = (const float*)d_in[2];
    const float* bin  = (const float*)d_in[3];
    const float* gctx = (const float*)d_in[4];
    const float* bctx = (const float*)d_in[5];
    const float* Wq = (const float*)d_in[6];
    const float* bq = (const float*)d_in[7];
    const float* Wk = (const float*)d_in[8];
    const float* bk = (const float*)d_in[9];
    const float* Wv = (const float*)d_in[10];
    const float* bv = (const float*)d_in[11];
    float* out = (float*)d_out;

    __half *xn, *cn, *wqt, *wkt, *wvt, *q, *k, *vt, *pmat;
    float *dots, *rinv;
    cudaGetSymbolAddress((void**)&xn,   g_xn);
    cudaGetSymbolAddress((void**)&cn,   g_cn);
    cudaGetSymbolAddress((void**)&wqt,  g_wqt);
    cudaGetSymbolAddress((void**)&wkt,  g_wkt);
    cudaGetSymbolAddress((void**)&wvt,  g_wvt);
    cudaGetSymbolAddress((void**)&q,    g_q);
    cudaGetSymbolAddress((void**)&k,    g_k);
    cudaGetSymbolAddress((void**)&vt,   g_vt);
    cudaGetSymbolAddress((void**)&pmat, g_p);
    cudaGetSymbolAddress((void**)&dots, g_dots);
    cudaGetSymbolAddress((void**)&rinv, g_rinv);

    cudaFuncSetAttribute(gemm_h, cudaFuncAttributeMaxDynamicSharedMemorySize, GEMM_DSMEM);

    // LayerNorm -> fp16
    ln_kernel<<<BATCH * SEQ, 128>>>(inputs,  gin,  bin,  xn);
    ln_kernel<<<BATCH * SEQ, 128>>>(context, gctx, bctx, cn);

    // weight transposes -> fp16
    {
        dim3 g(DIM / 32, DIM / 32, 1);
        tsplit_kernel<<<g, 256>>>(Wq, wqt);
        tsplit_kernel<<<g, 256>>>(Wk, wkt);
        tsplit_kernel<<<g, 256>>>(Wv, wvt);
    }

    // q = xn@Wqt^T + bq (fp16 out), k likewise (M=16384, N=512, Kc=512)
    {
        dim3 grid(DIM / 128, (BATCH * SEQ) / 128, 1);
        gemm_h<<<grid, 256, GEMM_DSMEM>>>(xn, wqt, BATCH * SEQ, DIM, DIM,
                                          0, 0, 0, 1.0f, bq, nullptr, nullptr,
                                          nullptr, q, 5, 0);
        gemm_h<<<grid, 256, GEMM_DSMEM>>>(cn, wkt, BATCH * SEQ, DIM, DIM,
                                          0, 0, 0, 1.0f, bk, nullptr, nullptr,
                                          nullptr, k, 5, 0);
    }

    // vt[d,j] = (cn@Wv + bv)^T (M=512, N=2048, Kc=512, batched)
    {
        dim3 grid(SEQ / 128, DIM / 128, BATCH);
        gemm_h<<<grid, 256, GEMM_DSMEM>>>(wvt, cn, DIM, SEQ, DIM,
                                          0, (size_t)SEQ * DIM, (size_t)DIM * SEQ,
                                          1.0f, nullptr, bv, nullptr,
                                          nullptr, vt, 5, 0);
    }

    // dots = scale * q @ k^T (fp32 out, Kc=512, batched) + fused column stats
    {
        float scale = 1.0f / sqrtf((float)DIM);
        dim3 grid(SEQ / 128, SEQ / 128, BATCH);
        gemm_h<<<grid, 256, GEMM_DSMEM>>>(q, k, SEQ, SEQ, DIM,
                                          (size_t)SEQ * DIM, (size_t)SEQ * DIM,
                                          (size_t)SEQ * SEQ, scale,
                                          nullptr, nullptr, nullptr,
                                          dots, nullptr, 0, 1);
    }

    // softmax combine + rowpass -> P (fp16), rinv
    colstats2_kernel<<<dim3(SEQ / 256, BATCH), 256>>>();
    rowpass_kernel<<<dim3(SEQ, BATCH), 256>>>();

    // out = rinv[i] * (P @ vt^T) (M=2048, N=512, Kc=2048, batched)
    {
        dim3 grid(DIM / 128, SEQ / 128, BATCH);
        gemm_h<<<grid, 256, GEMM_DSMEM>>>(pmat, vt, SEQ, DIM, SEQ,
                                          (size_t)SEQ * SEQ, (size_t)DIM * SEQ,
                                          (size_t)SEQ * DIM, 1.0f,
                                          nullptr, nullptr, rinv,
                                          out, nullptr, 0, 0);
    }
}

// round 9
// speedup vs baseline: 9.9486x; 1.1016x over previous
#include <cuda_runtime.h>
#include <cuda_fp16.h>
#include <math.h>
#include <stdint.h>

#define BATCH 8
#define SEQ   2048
#define DIM   512
#define NCHUNK 16

static const float LN_EPS_F = 1e-5f;
static const float EPS_F    = 1e-8f;

// ---------------- scratch (static device globals; no allocation) ----------------
__device__ __align__(256) __half g_xn [(size_t)BATCH * SEQ * DIM];
__device__ __align__(256) __half g_cn [(size_t)BATCH * SEQ * DIM];
__device__ __align__(256) __half g_wqt[(size_t)DIM * DIM];
__device__ __align__(256) __half g_wkt[(size_t)DIM * DIM];
__device__ __align__(256) __half g_wvt[(size_t)DIM * DIM];
__device__ __align__(256) __half g_q  [(size_t)BATCH * SEQ * DIM];
__device__ __align__(256) __half g_k  [(size_t)BATCH * SEQ * DIM];
__device__ __align__(256) __half g_vt [(size_t)BATCH * DIM * SEQ];
__device__ __align__(256) __half g_p  [(size_t)BATCH * SEQ * SEQ];
__device__ __align__(256) float  g_dots[(size_t)BATCH * SEQ * SEQ];
__device__ float g_pm  [BATCH * NCHUNK * SEQ];
__device__ float g_ps  [BATCH * NCHUNK * SEQ];
__device__ float g_cm  [BATCH * SEQ];
__device__ float g_csi [BATCH * SEQ];
__device__ float g_rinv[BATCH * SEQ];

// ---------------- PTX helpers (baseline compute_103-safe) ----------------
__device__ __forceinline__ uint32_t smem_u32(const void* p) {
    uint32_t a;
    asm("{ .reg .u64 t; cvta.to.shared.u64 t, %1; cvt.u32.u64 %0, t; }" : "=r"(a) : "l"(p));
    return a;
}
__device__ __forceinline__ void cp_async16(uint32_t d, const void* g) {
    asm volatile("cp.async.cg.shared.global [%0], [%1], 16;" :: "r"(d), "l"(g));
}
__device__ __forceinline__ void cp_commit() {
    asm volatile("cp.async.commit_group;" ::: "memory");
}
template <int N>
__device__ __forceinline__ void cp_wait() {
    asm volatile("cp.async.wait_group %0;" :: "n"(N) : "memory");
}
__device__ __forceinline__ void ldsm4(uint32_t& r0, uint32_t& r1, uint32_t& r2, uint32_t& r3,
                                      uint32_t addr) {
    asm volatile("ldmatrix.sync.aligned.m8n8.x4.shared.b16 {%0,%1,%2,%3}, [%4];"
                 : "=r"(r0), "=r"(r1), "=r"(r2), "=r"(r3) : "r"(addr));
}
__device__ __forceinline__ void mma16816(float* c, const uint32_t* a, uint32_t b0, uint32_t b1) {
    asm volatile(
        "mma.sync.aligned.m16n8k16.row.col.f32.f16.f16.f32 "
        "{%0,%1,%2,%3}, {%4,%5,%6,%7}, {%8,%9}, {%0,%1,%2,%3};"
        : "+f"(c[0]), "+f"(c[1]), "+f"(c[2]), "+f"(c[3])
        : "r"(a[0]), "r"(a[1]), "r"(a[2]), "r"(a[3]), "r"(b0), "r"(b1));
}

// ---------------- HMMA plain-fp16 GEMM ----------------
// C[M,N] = A[M,Kc] @ B[N,Kc]^T  (A,B fp16 K-major)
// pattern 0: outf = (acc*alpha + bias_col[col] + bias_row[row]) * rowscale[z*M+row]
// pattern 5: outh = fp16(acc*alpha + bias_col[col] + bias_row[row]), row length N
// docol: write per-128-row-chunk column (max, sumexp) stats into g_pm/g_ps
#define BK 32
#define STAGES 5
#define A_STAGE (128 * 40 * 2)
#define STAGE_BYTES (2 * A_STAGE)
#define GEMM_DSMEM (STAGES * STAGE_BYTES)

__global__ void __launch_bounds__(256, 2) gemm_h(
    const __half* __restrict__ A, const __half* __restrict__ B,
    int M, int N, int Kc,
    size_t sA, size_t sB, size_t sC,
    float alpha,
    const float* __restrict__ bias_col, const float* __restrict__ bias_row,
    const float* __restrict__ rowscale,
    float* __restrict__ outf, __half* __restrict__ outh, int pattern, int docol)
{
    extern __shared__ char dyn[];
    uint32_t dynb = smem_u32(dyn);

    int z = blockIdx.z;
    const __half* Ab = A + (size_t)z * sA + (size_t)(blockIdx.y * 128) * Kc;
    const __half* Bb = B + (size_t)z * sB + (size_t)(blockIdx.x * 128) * Kc;
    int bm = blockIdx.y * 128;
    int bn = blockIdx.x * 128;

    int t = threadIdx.x;
    int wid = t >> 5, lane = t & 31;
    int wm = wid & 1;        // 2 warps over M (64 rows each)
    int wn = wid >> 1;       // 4 warps over N (32 cols each)

    float acc[4][4][4];
    #pragma unroll
    for (int i = 0; i < 4; i++)
        #pragma unroll
        for (int j = 0; j < 4; j++)
            #pragma unroll
            for (int r = 0; r < 4; r++) acc[i][j][r] = 0.0f;

    int nkb = Kc / BK;

    auto issue = [&](int kb) {
        int slot = kb % STAGES;
        uint32_t sa = dynb + slot * STAGE_BYTES;
        uint32_t sb = sa + A_STAGE;
        int kh = kb * BK;
        #pragma unroll
        for (int i = 0; i < 2; i++) {
            int idx = t + 256 * i;
            int row = idx >> 2, c = idx & 3;
            cp_async16(sa + row * 80 + c * 16, Ab + (size_t)row * Kc + kh + c * 8);
        }
        #pragma unroll
        for (int i = 0; i < 2; i++) {
            int idx = t + 256 * i;
            int row = idx >> 2, c = idx & 3;
            cp_async16(sb + row * 80 + c * 16, Bb + (size_t)row * Kc + kh + c * 8);
        }
    };

    issue(0); cp_commit();
    issue(1); cp_commit();
    issue(2); cp_commit();
    issue(3); cp_commit();

    uint32_t a_lane = (uint32_t)((wm * 64 + (lane & 15)) * 80 + ((lane >> 4) * 8) * 2);
    uint32_t b_lane = (uint32_t)(A_STAGE +
                       (wn * 32 + (lane & 7) + (lane >> 4) * 8) * 80 +
                       (((lane >> 3) & 1) * 8) * 2);

    cp_wait<2>();          // slots 0 and 1 ready
    __syncthreads();

    uint32_t af[2][4][4];  // A fragments, double buffered
    uint32_t bf[2][2][4];  // B fragments, double buffered

    {
        uint32_t s0 = dynb;
        #pragma unroll
        for (int mi = 0; mi < 4; mi++)
            ldsm4(af[0][mi][0], af[0][mi][1], af[0][mi][2], af[0][mi][3],
                  s0 + a_lane + mi * (16 * 80));
        #pragma unroll
        for (int g = 0; g < 2; g++)
            ldsm4(bf[0][g][0], bf[0][g][1], bf[0][g][2], bf[0][g][3],
                  s0 + b_lane + g * (16 * 80));
    }

    int p = 0;
    for (int kb = 0; kb < nkb; kb++) {
        if (kb + 4 < nkb) issue(kb + 4);
        cp_commit();
        uint32_t scur = dynb + (kb % STAGES) * STAGE_BYTES;
        uint32_t snxt = dynb + ((kb + 1) % STAGES) * STAGE_BYTES;

        // ---- ks = 0: prefetch (kb, ks1) into p^1, mma on p ----
        #pragma unroll
        for (int mi = 0; mi < 4; mi++)
            ldsm4(af[p^1][mi][0], af[p^1][mi][1], af[p^1][mi][2], af[p^1][mi][3],
                  scur + a_lane + mi * (16 * 80) + 32);
        #pragma unroll
        for (int g = 0; g < 2; g++)
            ldsm4(bf[p^1][g][0], bf[p^1][g][1], bf[p^1][g][2], bf[p^1][g][3],
                  scur + b_lane + g * (16 * 80) + 32);
        #pragma unroll
        for (int mi = 0; mi < 4; mi++)
            #pragma unroll
            for (int ni = 0; ni < 4; ni++)
                mma16816(acc[mi][ni], af[p][mi],
                         bf[p][ni >> 1][(ni & 1) * 2], bf[p][ni >> 1][(ni & 1) * 2 + 1]);
        p ^= 1;

        // ---- ks = 1: prefetch (kb+1, ks0) into p^1, mma on p ----
        if (kb + 1 < nkb) {
            #pragma unroll
            for (int mi = 0; mi < 4; mi++)
                ldsm4(af[p^1][mi][0], af[p^1][mi][1], af[p^1][mi][2], af[p^1][mi][3],
                      snxt + a_lane + mi * (16 * 80));
            #pragma unroll
            for (int g = 0; g < 2; g++)
                ldsm4(bf[p^1][g][0], bf[p^1][g][1], bf[p^1][g][2], bf[p^1][g][3],
                      snxt + b_lane + g * (16 * 80));
        }
        #pragma unroll
        for (int mi = 0; mi < 4; mi++)
            #pragma unroll
            for (int ni = 0; ni < 4; ni++)
                mma16816(acc[mi][ni], af[p][mi],
                         bf[p][ni >> 1][(ni & 1) * 2], bf[p][ni >> 1][(ni & 1) * 2 + 1]);
        p ^= 1;

        cp_wait<2>();
        __syncthreads();
    }

    // ---------------- store epilogue ----------------
    int r_lane = lane >> 2;
    int c_lane = (lane & 3) * 2;
    #pragma unroll
    for (int mi = 0; mi < 4; mi++) {
        #pragma unroll
        for (int ni = 0; ni < 4; ni++) {
            int row = bm + wm * 64 + mi * 16 + r_lane;
            int col = bn + wn * 32 + ni * 8 + c_lane;
            float* a4 = acc[mi][ni];
            float bc0 = bias_col ? bias_col[col]     : 0.0f;
            float bc1 = bias_col ? bias_col[col + 1] : 0.0f;
            #pragma unroll
            for (int h = 0; h < 2; h++) {
                int rr = row + h * 8;
                float br = bias_row ? bias_row[rr] : 0.0f;
                float v0 = a4[h * 2 + 0] * alpha + bc0 + br;
                float v1 = a4[h * 2 + 1] * alpha + bc1 + br;
                if (pattern == 0) {
                    float rs = rowscale ? rowscale[(size_t)z * M + rr] : 1.0f;
                    float2 o = make_float2(v0 * rs, v1 * rs);
                    *(float2*)(outf + (size_t)z * sC + (size_t)rr * N + col) = o;
                } else {  // pattern 5: plain fp16
                    __half2 hh = __halves2half2(__float2half_rn(v0), __float2half_rn(v1));
                    *(__half2*)(outh + (size_t)z * sC + (size_t)rr * N + col) = hh;
                }
            }
        }
    }

    // ---------------- fused column stats (dots only) ----------------
    if (docol) {
        cp_wait<0>();
        __syncthreads();
        float* smx = (float*)dyn;
        float* ssm = (float*)dyn + 256;

        float cmax[4][2], csum[4][2];
        #pragma unroll
        for (int ni = 0; ni < 4; ni++) {
            #pragma unroll
            for (int c = 0; c < 2; c++) {
                float m = -1e30f;
                #pragma unroll
                for (int mi = 0; mi < 4; mi++)
                    #pragma unroll
                    for (int h = 0; h < 2; h++)
                        m = fmaxf(m, acc[mi][ni][h * 2 + c] * alpha);
                float s = 0.0f;
                #pragma unroll
                for (int mi = 0; mi < 4; mi++)
                    #pragma unroll
                    for (int h = 0; h < 2; h++)
                        s += __expf(acc[mi][ni][h * 2 + c] * alpha - m);
                cmax[ni][c] = m;
                csum[ni][c] = s;
            }
        }
        #pragma unroll
        for (int o = 4; o < 32; o <<= 1) {
            #pragma unroll
            for (int ni = 0; ni < 4; ni++)
                #pragma unroll
                for (int c = 0; c < 2; c++) {
                    float mo = __shfl_xor_sync(0xffffffffu, cmax[ni][c], o);
                    float so = __shfl_xor_sync(0xffffffffu, csum[ni][c], o);
                    float m = fmaxf(cmax[ni][c], mo);
                    csum[ni][c] = csum[ni][c] * __expf(cmax[ni][c] - m) +
                                  so * __expf(mo - m);
                    cmax[ni][c] = m;
                }
        }
        if ((lane >> 2) == 0) {
            #pragma unroll
            for (int ni = 0; ni < 4; ni++)
                #pragma unroll
                for (int c = 0; c < 2; c++) {
                    int col = wn * 32 + ni * 8 + (lane & 3) * 2 + c;
                    smx[wm * 128 + col] = cmax[ni][c];
                    ssm[wm * 128 + col] = csum[ni][c];
                }
        }
        __syncthreads();
        if (t < 128) {
            float m0 = smx[t], m1 = smx[128 + t];
            float s0 = ssm[t], s1 = ssm[128 + t];
            float m = fmaxf(m0, m1);
            float s = s0 * __expf(m0 - m) + s1 * __expf(m1 - m);
            size_t o = ((size_t)z * NCHUNK + blockIdx.y) * SEQ + bn + t;
            g_pm[o] = m;
            g_ps[o] = s;
        }
    }
}

// ---------------- LayerNorm -> fp16 [rows, 512] ----
__global__ void __launch_bounds__(128) ln_kernel(const float* __restrict__ x,
                                                 const float* __restrict__ g,
                                                 const float* __restrict__ b,
                                                 __half* __restrict__ y) {
    int row = blockIdx.x;
    int t = threadIdx.x;
    float4 v = ((const float4*)(x + (size_t)row * DIM))[t];
    float s  = v.x + v.y + v.z + v.w;
    float ss = v.x*v.x + v.y*v.y + v.z*v.z + v.w*v.w;
    __shared__ float sh[8];
    #pragma unroll
    for (int o = 16; o > 0; o >>= 1) {
        s  += __shfl_down_sync(0xffffffffu, s, o);
        ss += __shfl_down_sync(0xffffffffu, ss, o);
    }
    if ((t & 31) == 0) { sh[t >> 5] = s; sh[4 + (t >> 5)] = ss; }
    __syncthreads();
    float fs  = sh[0] + sh[1] + sh[2] + sh[3];
    float fss = sh[4] + sh[5] + sh[6] + sh[7];
    float mu  = fs * (1.0f / DIM);
    float var = fss * (1.0f / DIM) - mu * mu;
    float rstd = rsqrtf(var + LN_EPS_F);
    float4 gv = ((const float4*)g)[t];
    float4 bv = ((const float4*)b)[t];
    float o0 = (v.x - mu) * rstd * gv.x + bv.x;
    float o1 = (v.y - mu) * rstd * gv.y + bv.y;
    float o2 = (v.z - mu) * rstd * gv.z + bv.z;
    float o3 = (v.w - mu) * rstd * gv.w + bv.w;
    __half* yb = y + (size_t)row * DIM + t * 4;
    ((__half2*)yb)[0] = __halves2half2(__float2half_rn(o0), __float2half_rn(o1));
    ((__half2*)yb)[1] = __halves2half2(__float2half_rn(o2), __float2half_rn(o3));
}

// ---------------- weight transpose: W[512,512] fp32 -> Wt[512,512] fp16 ----
__global__ void __launch_bounds__(256) tsplit_kernel(const float* __restrict__ in,
                                                     __half* __restrict__ out) {
    __shared__ float tile[32][33];
    int r0 = blockIdx.y * 32, c0 = blockIdx.x * 32;
    int tx = threadIdx.x & 31, ty = threadIdx.x >> 5;
    #pragma unroll
    for (int i = ty; i < 32; i += 8)
        tile[i][tx] = in[(size_t)(r0 + i) * DIM + c0 + tx];
    __syncthreads();
    #pragma unroll
    for (int i = ty; i < 32; i += 8)
        out[(size_t)(c0 + i) * DIM + r0 + tx] = __float2half_rn(tile[tx][i]);
}

// ---------------- column stats combine -> colmax, 1/colsum ----------------
__global__ void __launch_bounds__(256) colstats2_kernel() {
    int j = blockIdx.x * 256 + threadIdx.x;
    int z = blockIdx.y;
    float m = -1e30f;
    #pragma unroll
    for (int c = 0; c < NCHUNK; c++)
        m = fmaxf(m, g_pm[((size_t)z * NCHUNK + c) * SEQ + j]);
    float s = 0.0f;
    #pragma unroll
    for (int c = 0; c < NCHUNK; c++)
        s += g_ps[((size_t)z * NCHUNK + c) * SEQ + j] *
             __expf(g_pm[((size_t)z * NCHUNK + c) * SEQ + j] - m);
    g_cm [(size_t)z * SEQ + j] = m;
    g_csi[(size_t)z * SEQ + j] = 1.0f / s;
}

// ---------------- row pass: P = softmax+EPS (fp16), rinv ----------------
__global__ void __launch_bounds__(256) rowpass_kernel() {
    int i = blockIdx.x;
    int z = blockIdx.y;
    int t = threadIdx.x;
    const float* row = g_dots + ((size_t)z * SEQ + i) * SEQ;
    const float* cm = g_cm  + (size_t)z * SEQ;
    const float* ci = g_csi + (size_t)z * SEQ;
    __half* ab = g_p + ((size_t)z * SEQ + i) * SEQ;
    float acc = 0.0f;
    #pragma unroll 2
    for (int j2 = t; j2 < SEQ / 2; j2 += 256) {
        int j = j2 * 2;
        float2 d = *(const float2*)(row + j);
        float2 m2 = *(const float2*)(cm + j);
        float2 c2 = *(const float2*)(ci + j);
        float a0 = __expf(d.x - m2.x) * c2.x + EPS_F;
        float a1 = __expf(d.y - m2.y) * c2.y + EPS_F;
        acc += a0 + a1;
        *(__half2*)(ab + j) = __halves2half2(__float2half_rn(a0), __float2half_rn(a1));
    }
    __shared__ float sh[8];
    #pragma unroll
    for (int o = 16; o > 0; o >>= 1)
        acc += __shfl_down_sync(0xffffffffu, acc, o);
    if ((t & 31) == 0) sh[t >> 5] = acc;
    __syncthreads();
    if (t == 0) {
        float s = 0.0f;
        #pragma unroll
        for (int w = 0; w < 8; w++) s += sh[w];
        g_rinv[(size_t)z * SEQ + i] = 1.0f / (s + EPS_F);
    }
}

// ---------------- launch ----------------
extern "C" void kernel_launch(void* const* d_in, const int* in_sizes, int n_in,
                              void* d_out, int out_size) {
    const float* inputs  = (const float*)d_in[0];
    const float* context = (const float*)d_in[1];
    const float* gin  = (const float*)d_in[2];
    const float* bin  = (const float*)d_in[3];
    const float* gctx = (const float*)d_in[4];
    const float* bctx = (const float*)d_in[5];
    const float* Wq = (const float*)d_in[6];
    const float* bq = (const float*)d_in[7];
    const float* Wk = (const float*)d_in[8];
    const float* bk = (const float*)d_in[9];
    const float* Wv = (const float*)d_in[10];
    const float* bv = (const float*)d_in[11];
    float* out = (float*)d_out;

    __half *xn, *cn, *wqt, *wkt, *wvt, *q, *k, *vt, *pmat;
    float *dots, *rinv;
    cudaGetSymbolAddress((void**)&xn,   g_xn);
    cudaGetSymbolAddress((void**)&cn,   g_cn);
    cudaGetSymbolAddress((void**)&wqt,  g_wqt);
    cudaGetSymbolAddress((void**)&wkt,  g_wkt);
    cudaGetSymbolAddress((void**)&wvt,  g_wvt);
    cudaGetSymbolAddress((void**)&q,    g_q);
    cudaGetSymbolAddress((void**)&k,    g_k);
    cudaGetSymbolAddress((void**)&vt,   g_vt);
    cudaGetSymbolAddress((void**)&pmat, g_p);
    cudaGetSymbolAddress((void**)&dots, g_dots);
    cudaGetSymbolAddress((void**)&rinv, g_rinv);

    cudaFuncSetAttribute(gemm_h, cudaFuncAttributeMaxDynamicSharedMemorySize, GEMM_DSMEM);

    // LayerNorm -> fp16
    ln_kernel<<<BATCH * SEQ, 128>>>(inputs,  gin,  bin,  xn);
    ln_kernel<<<BATCH * SEQ, 128>>>(context, gctx, bctx, cn);

    // weight transposes -> fp16
    {
        dim3 g(DIM / 32, DIM / 32, 1);
        tsplit_kernel<<<g, 256>>>(Wq, wqt);
        tsplit_kernel<<<g, 256>>>(Wk, wkt);
        tsplit_kernel<<<g, 256>>>(Wv, wvt);
    }

    // q = xn@Wqt^T + bq (fp16 out), k likewise (M=16384, N=512, Kc=512)
    {
        dim3 grid(DIM / 128, (BATCH * SEQ) / 128, 1);
        gemm_h<<<grid, 256, GEMM_DSMEM>>>(xn, wqt, BATCH * SEQ, DIM, DIM,
                                          0, 0, 0, 1.0f, bq, nullptr, nullptr,
                                          nullptr, q, 5, 0);
        gemm_h<<<grid, 256, GEMM_DSMEM>>>(cn, wkt, BATCH * SEQ, DIM, DIM,
                                          0, 0, 0, 1.0f, bk, nullptr, nullptr,
                                          nullptr, k, 5, 0);
    }

    // vt[d,j] = (cn@Wv + bv)^T (M=512, N=2048, Kc=512, batched)
    {
        dim3 grid(SEQ / 128, DIM / 128, BATCH);
        gemm_h<<<grid, 256, GEMM_DSMEM>>>(wvt, cn, DIM, SEQ, DIM,
                                          0, (size_t)SEQ * DIM, (size_t)DIM * SEQ,
                                          1.0f, nullptr, bv, nullptr,
                                          nullptr, vt, 5, 0);
    }

    // dots = scale * q @ k^T (fp32 out, Kc=512, batched) + fused column stats
    {
        float scale = 1.0f / sqrtf((float)DIM);
        dim3 grid(SEQ / 128, SEQ / 128, BATCH);
        gemm_h<<<grid, 256, GEMM_DSMEM>>>(q, k, SEQ, SEQ, DIM,
                                          (size_t)SEQ * DIM, (size_t)SEQ * DIM,
                                          (size_t)SEQ * SEQ, scale,
                                          nullptr, nullptr, nullptr,
                                          dots, nullptr, 0, 1);
    }

    // softmax combine + rowpass -> P (fp16), rinv
    colstats2_kernel<<<dim3(SEQ / 256, BATCH), 256>>>();
    rowpass_kernel<<<dim3(SEQ, BATCH), 256>>>();

    // out = rinv[i] * (P @ vt^T) (M=2048, N=512, Kc=2048, batched)
    {
        dim3 grid(DIM / 128, SEQ / 128, BATCH);
        gemm_h<<<grid, 256, GEMM_DSMEM>>>(pmat, vt, SEQ, DIM, SEQ,
                                          (size_t)SEQ * SEQ, (size_t)DIM * SEQ,
                                          (size_t)SEQ * DIM, 1.0f,
                                          nullptr, nullptr, rinv,
                                          out, nullptr, 0, 0);
    }
}

// round 10
// speedup vs baseline: 10.8758x; 1.0932x over previous
#include <cuda_runtime.h>
#include <cuda_fp16.h>
#include <math.h>
#include <stdint.h>

#define BATCH 8
#define SEQ   2048
#define DIM   512
#define NCHUNK 8          // 256-row chunks of SEQ

static const float LN_EPS_F = 1e-5f;
static const float EPS_F    = 1e-8f;

// ---------------- scratch (static device globals; no allocation) ----------------
__device__ __align__(256) __half g_xn [(size_t)BATCH * SEQ * DIM];
__device__ __align__(256) __half g_cn [(size_t)BATCH * SEQ * DIM];
__device__ __align__(256) __half g_wqt[(size_t)DIM * DIM];
__device__ __align__(256) __half g_wkt[(size_t)DIM * DIM];
__device__ __align__(256) __half g_wvt[(size_t)DIM * DIM];
__device__ __align__(256) __half g_q  [(size_t)BATCH * SEQ * DIM];
__device__ __align__(256) __half g_k  [(size_t)BATCH * SEQ * DIM];
__device__ __align__(256) __half g_vt [(size_t)BATCH * DIM * SEQ];
__device__ __align__(256) __half g_p  [(size_t)BATCH * SEQ * SEQ];
__device__ __align__(256) float  g_dots[(size_t)BATCH * SEQ * SEQ];
__device__ float g_pm  [BATCH * NCHUNK * SEQ];
__device__ float g_ps  [BATCH * NCHUNK * SEQ];
__device__ float g_cm  [BATCH * SEQ];
__device__ float g_csi [BATCH * SEQ];
__device__ float g_rinv[BATCH * SEQ];

// ---------------- PTX helpers (baseline compute_103-safe) ----------------
__device__ __forceinline__ uint32_t smem_u32(const void* p) {
    uint32_t a;
    asm("{ .reg .u64 t; cvta.to.shared.u64 t, %1; cvt.u32.u64 %0, t; }" : "=r"(a) : "l"(p));
    return a;
}
__device__ __forceinline__ void cp_async16(uint32_t d, const void* g) {
    asm volatile("cp.async.cg.shared.global [%0], [%1], 16;" :: "r"(d), "l"(g));
}
__device__ __forceinline__ void cp_commit() {
    asm volatile("cp.async.commit_group;" ::: "memory");
}
template <int N>
__device__ __forceinline__ void cp_wait() {
    asm volatile("cp.async.wait_group %0;" :: "n"(N) : "memory");
}
__device__ __forceinline__ void ldsm4(uint32_t& r0, uint32_t& r1, uint32_t& r2, uint32_t& r3,
                                      uint32_t addr) {
    asm volatile("ldmatrix.sync.aligned.m8n8.x4.shared.b16 {%0,%1,%2,%3}, [%4];"
                 : "=r"(r0), "=r"(r1), "=r"(r2), "=r"(r3) : "r"(addr));
}
__device__ __forceinline__ void mma16816(float* c, const uint32_t* a, uint32_t b0, uint32_t b1) {
    asm volatile(
        "mma.sync.aligned.m16n8k16.row.col.f32.f16.f16.f32 "
        "{%0,%1,%2,%3}, {%4,%5,%6,%7}, {%8,%9}, {%0,%1,%2,%3};"
        : "+f"(c[0]), "+f"(c[1]), "+f"(c[2]), "+f"(c[3])
        : "r"(a[0]), "r"(a[1]), "r"(a[2]), "r"(a[3]), "r"(b0), "r"(b1));
}

// ---------------- HMMA plain-fp16 GEMM, CTA tile 256x128, warp tile 64x64 ----
// C[M,N] = A[M,Kc] @ B[N,Kc]^T  (A,B fp16 K-major); M%256==0, N%128==0, Kc%32==0
// pattern 0: outf = (acc*alpha + bias_col[col] + bias_row[row]) * rowscale[z*M+row]
// pattern 5: outh = fp16(acc*alpha + bias_col[col] + bias_row[row])
// docol: per-256-row-chunk column (max, sumexp) stats into g_pm/g_ps
#define BK 32
#define STAGES 5
#define A_STAGE (256 * 80)
#define B_STAGE (128 * 80)
#define STAGE_BYTES (A_STAGE + B_STAGE)
#define GEMM_DSMEM (STAGES * STAGE_BYTES)

__global__ void __launch_bounds__(256, 1) gemm_h(
    const __half* __restrict__ A, const __half* __restrict__ B,
    int M, int N, int Kc,
    size_t sA, size_t sB, size_t sC,
    float alpha,
    const float* __restrict__ bias_col, const float* __restrict__ bias_row,
    const float* __restrict__ rowscale,
    float* __restrict__ outf, __half* __restrict__ outh, int pattern, int docol)
{
    extern __shared__ char dyn[];
    uint32_t dynb = smem_u32(dyn);

    int z = blockIdx.z;
    const __half* Ab = A + (size_t)z * sA + (size_t)(blockIdx.y * 256) * Kc;
    const __half* Bb = B + (size_t)z * sB + (size_t)(blockIdx.x * 128) * Kc;
    int bm = blockIdx.y * 256;
    int bn = blockIdx.x * 128;

    int t = threadIdx.x;
    int wid = t >> 5, lane = t & 31;
    int wm = wid & 3;        // 4 warps over M (64 rows each)
    int wn = wid >> 2;       // 2 warps over N (64 cols each)

    float acc[4][8][4];
    #pragma unroll
    for (int i = 0; i < 4; i++)
        #pragma unroll
        for (int j = 0; j < 8; j++)
            #pragma unroll
            for (int r = 0; r < 4; r++) acc[i][j][r] = 0.0f;

    int nkb = Kc / BK;

    auto issue = [&](int kb) {
        int slot = kb % STAGES;
        uint32_t sa = dynb + slot * STAGE_BYTES;
        uint32_t sb = sa + A_STAGE;
        int kh = kb * BK;
        #pragma unroll
        for (int i = 0; i < 4; i++) {           // A: 256 rows x 32 k
            int idx = t + 256 * i;
            int row = idx >> 2, c = idx & 3;
            cp_async16(sa + row * 80 + c * 16, Ab + (size_t)row * Kc + kh + c * 8);
        }
        #pragma unroll
        for (int i = 0; i < 2; i++) {           // B: 128 rows x 32 k
            int idx = t + 256 * i;
            int row = idx >> 2, c = idx & 3;
            cp_async16(sb + row * 80 + c * 16, Bb + (size_t)row * Kc + kh + c * 8);
        }
    };

    issue(0); cp_commit();
    issue(1); cp_commit();
    issue(2); cp_commit();
    issue(3); cp_commit();

    uint32_t a_lane = (uint32_t)((wm * 64 + (lane & 15)) * 80 + ((lane >> 4) * 8) * 2);
    uint32_t b_lane = (uint32_t)(A_STAGE +
                       (wn * 64 + (lane & 7) + (lane >> 4) * 8) * 80 +
                       (((lane >> 3) & 1) * 8) * 2);

    cp_wait<2>();          // slots 0 and 1 ready
    __syncthreads();

    uint32_t af[2][4][4];  // A fragments, double buffered (4 x m16)
    uint32_t bf[2][4][4];  // B fragments, double buffered (4 x n16)

    {
        uint32_t s0 = dynb;
        #pragma unroll
        for (int mi = 0; mi < 4; mi++)
            ldsm4(af[0][mi][0], af[0][mi][1], af[0][mi][2], af[0][mi][3],
                  s0 + a_lane + mi * (16 * 80));
        #pragma unroll
        for (int g = 0; g < 4; g++)
            ldsm4(bf[0][g][0], bf[0][g][1], bf[0][g][2], bf[0][g][3],
                  s0 + b_lane + g * (16 * 80));
    }

    int p = 0;
    for (int kb = 0; kb < nkb; kb++) {
        if (kb + 4 < nkb) issue(kb + 4);
        cp_commit();
        uint32_t scur = dynb + (kb % STAGES) * STAGE_BYTES;
        uint32_t snxt = dynb + ((kb + 1) % STAGES) * STAGE_BYTES;

        // ---- ks = 0: prefetch (kb, ks1) into p^1, mma on p ----
        #pragma unroll
        for (int mi = 0; mi < 4; mi++)
            ldsm4(af[p^1][mi][0], af[p^1][mi][1], af[p^1][mi][2], af[p^1][mi][3],
                  scur + a_lane + mi * (16 * 80) + 32);
        #pragma unroll
        for (int g = 0; g < 4; g++)
            ldsm4(bf[p^1][g][0], bf[p^1][g][1], bf[p^1][g][2], bf[p^1][g][3],
                  scur + b_lane + g * (16 * 80) + 32);
        #pragma unroll
        for (int mi = 0; mi < 4; mi++)
            #pragma unroll
            for (int ni = 0; ni < 8; ni++)
                mma16816(acc[mi][ni], af[p][mi],
                         bf[p][ni >> 1][(ni & 1) * 2], bf[p][ni >> 1][(ni & 1) * 2 + 1]);
        p ^= 1;

        // ---- ks = 1: prefetch (kb+1, ks0) into p^1, mma on p ----
        if (kb + 1 < nkb) {
            #pragma unroll
            for (int mi = 0; mi < 4; mi++)
                ldsm4(af[p^1][mi][0], af[p^1][mi][1], af[p^1][mi][2], af[p^1][mi][3],
                      snxt + a_lane + mi * (16 * 80));
            #pragma unroll
            for (int g = 0; g < 4; g++)
                ldsm4(bf[p^1][g][0], bf[p^1][g][1], bf[p^1][g][2], bf[p^1][g][3],
                      snxt + b_lane + g * (16 * 80));
        }
        #pragma unroll
        for (int mi = 0; mi < 4; mi++)
            #pragma unroll
            for (int ni = 0; ni < 8; ni++)
                mma16816(acc[mi][ni], af[p][mi],
                         bf[p][ni >> 1][(ni & 1) * 2], bf[p][ni >> 1][(ni & 1) * 2 + 1]);
        p ^= 1;

        cp_wait<2>();
        __syncthreads();
    }

    // ---------------- store epilogue ----------------
    int r_lane = lane >> 2;
    int c_lane = (lane & 3) * 2;
    #pragma unroll
    for (int mi = 0; mi < 4; mi++) {
        #pragma unroll
        for (int ni = 0; ni < 8; ni++) {
            int row = bm + wm * 64 + mi * 16 + r_lane;
            int col = bn + wn * 64 + ni * 8 + c_lane;
            float* a4 = acc[mi][ni];
            float bc0 = bias_col ? bias_col[col]     : 0.0f;
            float bc1 = bias_col ? bias_col[col + 1] : 0.0f;
            #pragma unroll
            for (int h = 0; h < 2; h++) {
                int rr = row + h * 8;
                float br = bias_row ? bias_row[rr] : 0.0f;
                float v0 = a4[h * 2 + 0] * alpha + bc0 + br;
                float v1 = a4[h * 2 + 1] * alpha + bc1 + br;
                if (pattern == 0) {
                    float rs = rowscale ? rowscale[(size_t)z * M + rr] : 1.0f;
                    float2 o = make_float2(v0 * rs, v1 * rs);
                    *(float2*)(outf + (size_t)z * sC + (size_t)rr * N + col) = o;
                } else {  // pattern 5: plain fp16
                    __half2 hh = __halves2half2(__float2half_rn(v0), __float2half_rn(v1));
                    *(__half2*)(outh + (size_t)z * sC + (size_t)rr * N + col) = hh;
                }
            }
        }
    }

    // ---------------- fused column stats (dots only) ----------------
    if (docol) {
        cp_wait<0>();
        __syncthreads();
        float* smx = (float*)dyn;           // [4][128]
        float* ssm = (float*)dyn + 512;     // [4][128]

        float cmax[8][2], csum[8][2];
        #pragma unroll
        for (int ni = 0; ni < 8; ni++) {
            #pragma unroll
            for (int c = 0; c < 2; c++) {
                float m = -1e30f;
                #pragma unroll
                for (int mi = 0; mi < 4; mi++)
                    #pragma unroll
                    for (int h = 0; h < 2; h++)
                        m = fmaxf(m, acc[mi][ni][h * 2 + c] * alpha);
                float s = 0.0f;
                #pragma unroll
                for (int mi = 0; mi < 4; mi++)
                    #pragma unroll
                    for (int h = 0; h < 2; h++)
                        s += __expf(acc[mi][ni][h * 2 + c] * alpha - m);
                cmax[ni][c] = m;
                csum[ni][c] = s;
            }
        }
        // reduce across the 8 lane-rows (lanes differing in bits 2..4)
        #pragma unroll
        for (int o = 4; o < 32; o <<= 1) {
            #pragma unroll
            for (int ni = 0; ni < 8; ni++)
                #pragma unroll
                for (int c = 0; c < 2; c++) {
                    float mo = __shfl_xor_sync(0xffffffffu, cmax[ni][c], o);
                    float so = __shfl_xor_sync(0xffffffffu, csum[ni][c], o);
                    float m = fmaxf(cmax[ni][c], mo);
                    csum[ni][c] = csum[ni][c] * __expf(cmax[ni][c] - m) +
                                  so * __expf(mo - m);
                    cmax[ni][c] = m;
                }
        }
        if ((lane >> 2) == 0) {
            #pragma unroll
            for (int ni = 0; ni < 8; ni++)
                #pragma unroll
                for (int c = 0; c < 2; c++) {
                    int col = wn * 64 + ni * 8 + (lane & 3) * 2 + c;
                    smx[wm * 128 + col] = cmax[ni][c];
                    ssm[wm * 128 + col] = csum[ni][c];
                }
        }
        __syncthreads();
        if (t < 128) {
            float m = smx[t];
            #pragma unroll
            for (int w = 1; w < 4; w++) m = fmaxf(m, smx[w * 128 + t]);
            float s = 0.0f;
            #pragma unroll
            for (int w = 0; w < 4; w++)
                s += ssm[w * 128 + t] * __expf(smx[w * 128 + t] - m);
            size_t o = ((size_t)z * NCHUNK + blockIdx.y) * SEQ + bn + t;
            g_pm[o] = m;
            g_ps[o] = s;
        }
    }
}

// ---------------- LayerNorm -> fp16 [rows, 512] ----
__global__ void __launch_bounds__(128) ln_kernel(const float* __restrict__ x,
                                                 const float* __restrict__ g,
                                                 const float* __restrict__ b,
                                                 __half* __restrict__ y) {
    int row = blockIdx.x;
    int t = threadIdx.x;
    float4 v = ((const float4*)(x + (size_t)row * DIM))[t];
    float s  = v.x + v.y + v.z + v.w;
    float ss = v.x*v.x + v.y*v.y + v.z*v.z + v.w*v.w;
    __shared__ float sh[8];
    #pragma unroll
    for (int o = 16; o > 0; o >>= 1) {
        s  += __shfl_down_sync(0xffffffffu, s, o);
        ss += __shfl_down_sync(0xffffffffu, ss, o);
    }
    if ((t & 31) == 0) { sh[t >> 5] = s; sh[4 + (t >> 5)] = ss; }
    __syncthreads();
    float fs  = sh[0] + sh[1] + sh[2] + sh[3];
    float fss = sh[4] + sh[5] + sh[6] + sh[7];
    float mu  = fs * (1.0f / DIM);
    float var = fss * (1.0f / DIM) - mu * mu;
    float rstd = rsqrtf(var + LN_EPS_F);
    float4 gv = ((const float4*)g)[t];
    float4 bv = ((const float4*)b)[t];
    float o0 = (v.x - mu) * rstd * gv.x + bv.x;
    float o1 = (v.y - mu) * rstd * gv.y + bv.y;
    float o2 = (v.z - mu) * rstd * gv.z + bv.z;
    float o3 = (v.w - mu) * rstd * gv.w + bv.w;
    __half* yb = y + (size_t)row * DIM + t * 4;
    ((__half2*)yb)[0] = __halves2half2(__float2half_rn(o0), __float2half_rn(o1));
    ((__half2*)yb)[1] = __halves2half2(__float2half_rn(o2), __float2half_rn(o3));
}

// ---------------- weight transpose: W[512,512] fp32 -> Wt[512,512] fp16 ----
__global__ void __launch_bounds__(256) tsplit_kernel(const float* __restrict__ in,
                                                     __half* __restrict__ out) {
    __shared__ float tile[32][33];
    int r0 = blockIdx.y * 32, c0 = blockIdx.x * 32;
    int tx = threadIdx.x & 31, ty = threadIdx.x >> 5;
    #pragma unroll
    for (int i = ty; i < 32; i += 8)
        tile[i][tx] = in[(size_t)(r0 + i) * DIM + c0 + tx];
    __syncthreads();
    #pragma unroll
    for (int i = ty; i < 32; i += 8)
        out[(size_t)(c0 + i) * DIM + r0 + tx] = __float2half_rn(tile[tx][i]);
}

// ---------------- column stats combine -> colmax, 1/colsum ----------------
__global__ void __launch_bounds__(256) colstats2_kernel() {
    int j = blockIdx.x * 256 + threadIdx.x;
    int z = blockIdx.y;
    float m = -1e30f;
    #pragma unroll
    for (int c = 0; c < NCHUNK; c++)
        m = fmaxf(m, g_pm[((size_t)z * NCHUNK + c) * SEQ + j]);
    float s = 0.0f;
    #pragma unroll
    for (int c = 0; c < NCHUNK; c++)
        s += g_ps[((size_t)z * NCHUNK + c) * SEQ + j] *
             __expf(g_pm[((size_t)z * NCHUNK + c) * SEQ + j] - m);
    g_cm [(size_t)z * SEQ + j] = m;
    g_csi[(size_t)z * SEQ + j] = 1.0f / s;
}

// ---------------- row pass: P = softmax+EPS (fp16), rinv ----------------
__global__ void __launch_bounds__(256) rowpass_kernel() {
    int i = blockIdx.x;
    int z = blockIdx.y;
    int t = threadIdx.x;
    const float* row = g_dots + ((size_t)z * SEQ + i) * SEQ;
    const float* cm = g_cm  + (size_t)z * SEQ;
    const float* ci = g_csi + (size_t)z * SEQ;
    __half* ab = g_p + ((size_t)z * SEQ + i) * SEQ;
    float acc = 0.0f;
    #pragma unroll 2
    for (int j2 = t; j2 < SEQ / 2; j2 += 256) {
        int j = j2 * 2;
        float2 d = *(const float2*)(row + j);
        float2 m2 = *(const float2*)(cm + j);
        float2 c2 = *(const float2*)(ci + j);
        float a0 = __expf(d.x - m2.x) * c2.x + EPS_F;
        float a1 = __expf(d.y - m2.y) * c2.y + EPS_F;
        acc += a0 + a1;
        *(__half2*)(ab + j) = __halves2half2(__float2half_rn(a0), __float2half_rn(a1));
    }
    __shared__ float sh[8];
    #pragma unroll
    for (int o = 16; o > 0; o >>= 1)
        acc += __shfl_down_sync(0xffffffffu, acc, o);
    if ((t & 31) == 0) sh[t >> 5] = acc;
    __syncthreads();
    if (t == 0) {
        float s = 0.0f;
        #pragma unroll
        for (int w = 0; w < 8; w++) s += sh[w];
        g_rinv[(size_t)z * SEQ + i] = 1.0f / (s + EPS_F);
    }
}

// ---------------- launch ----------------
extern "C" void kernel_launch(void* const* d_in, const int* in_sizes, int n_in,
                              void* d_out, int out_size) {
    const float* inputs  = (const float*)d_in[0];
    const float* context = (const float*)d_in[1];
    const float* gin  = (const float*)d_in[2];
    const float* bin  = (const float*)d_in[3];
    const float* gctx = (const float*)d_in[4];
    const float* bctx = (const float*)d_in[5];
    const float* Wq = (const float*)d_in[6];
    const float* bq = (const float*)d_in[7];
    const float* Wk = (const float*)d_in[8];
    const float* bk = (const float*)d_in[9];
    const float* Wv = (const float*)d_in[10];
    const float* bv = (const float*)d_in[11];
    float* out = (float*)d_out;

    __half *xn, *cn, *wqt, *wkt, *wvt, *q, *k, *vt, *pmat;
    float *dots, *rinv;
    cudaGetSymbolAddress((void**)&xn,   g_xn);
    cudaGetSymbolAddress((void**)&cn,   g_cn);
    cudaGetSymbolAddress((void**)&wqt,  g_wqt);
    cudaGetSymbolAddress((void**)&wkt,  g_wkt);
    cudaGetSymbolAddress((void**)&wvt,  g_wvt);
    cudaGetSymbolAddress((void**)&q,    g_q);
    cudaGetSymbolAddress((void**)&k,    g_k);
    cudaGetSymbolAddress((void**)&vt,   g_vt);
    cudaGetSymbolAddress((void**)&pmat, g_p);
    cudaGetSymbolAddress((void**)&dots, g_dots);
    cudaGetSymbolAddress((void**)&rinv, g_rinv);

    cudaFuncSetAttribute(gemm_h, cudaFuncAttributeMaxDynamicSharedMemorySize, GEMM_DSMEM);

    // LayerNorm -> fp16
    ln_kernel<<<BATCH * SEQ, 128>>>(inputs,  gin,  bin,  xn);
    ln_kernel<<<BATCH * SEQ, 128>>>(context, gctx, bctx, cn);

    // weight transposes -> fp16
    {
        dim3 g(DIM / 32, DIM / 32, 1);
        tsplit_kernel<<<g, 256>>>(Wq, wqt);
        tsplit_kernel<<<g, 256>>>(Wk, wkt);
        tsplit_kernel<<<g, 256>>>(Wv, wvt);
    }

    // q = xn@Wqt^T + bq (fp16 out), k likewise (M=16384, N=512, Kc=512)
    {
        dim3 grid(DIM / 128, (BATCH * SEQ) / 256, 1);
        gemm_h<<<grid, 256, GEMM_DSMEM>>>(xn, wqt, BATCH * SEQ, DIM, DIM,
                                          0, 0, 0, 1.0f, bq, nullptr, nullptr,
                                          nullptr, q, 5, 0);
        gemm_h<<<grid, 256, GEMM_DSMEM>>>(cn, wkt, BATCH * SEQ, DIM, DIM,
                                          0, 0, 0, 1.0f, bk, nullptr, nullptr,
                                          nullptr, k, 5, 0);
    }

    // vt[d,j] = (cn@Wv + bv)^T (M=512, N=2048, Kc=512, batched)
    {
        dim3 grid(SEQ / 128, DIM / 256, BATCH);
        gemm_h<<<grid, 256, GEMM_DSMEM>>>(wvt, cn, DIM, SEQ, DIM,
                                          0, (size_t)SEQ * DIM, (size_t)DIM * SEQ,
                                          1.0f, nullptr, bv, nullptr,
                                          nullptr, vt, 5, 0);
    }

    // dots = scale * q @ k^T (fp32 out, Kc=512, batched) + fused column stats
    {
        float scale = 1.0f / sqrtf((float)DIM);
        dim3 grid(SEQ / 128, SEQ / 256, BATCH);
        gemm_h<<<grid, 256, GEMM_DSMEM>>>(q, k, SEQ, SEQ, DIM,
                                          (size_t)SEQ * DIM, (size_t)SEQ * DIM,
                                          (size_t)SEQ * SEQ, scale,
                                          nullptr, nullptr, nullptr,
                                          dots, nullptr, 0, 1);
    }

    // softmax combine + rowpass -> P (fp16), rinv
    colstats2_kernel<<<dim3(SEQ / 256, BATCH), 256>>>();
    rowpass_kernel<<<dim3(SEQ, BATCH), 256>>>();

    // out = rinv[i] * (P @ vt^T) (M=2048, N=512, Kc=2048, batched)
    {
        dim3 grid(DIM / 128, SEQ / 256, BATCH);
        gemm_h<<<grid, 256, GEMM_DSMEM>>>(pmat, vt, SEQ, DIM, SEQ,
                                          (size_t)SEQ * SEQ, (size_t)DIM * SEQ,
                                          (size_t)SEQ * DIM, 1.0f,
                                          nullptr, nullptr, rinv,
                                          out, nullptr, 0, 0);
    }
}

// round 11
// speedup vs baseline: 11.9404x; 1.0979x over previous
#include <cuda_runtime.h>
#include <cuda_fp16.h>
#include <math.h>
#include <stdint.h>

#define BATCH 8
#define SEQ   2048
#define DIM   512
#define NCHUNK 8          // 256-row chunks of SEQ (dots M-tiles)
#define NR    (BATCH * SEQ)

static const float LN_EPS_F = 1e-5f;
static const float EPS_F    = 1e-8f;

// ---------------- scratch (static device globals; no allocation) ----------------
__device__ __align__(256) __half g_xc [(size_t)2 * NR * DIM];   // [xn | cn]
__device__ __align__(256) __half g_wqk[(size_t)2 * DIM * DIM];  // [Wq^T | Wk^T]
__device__ __align__(256) __half g_wvt[(size_t)DIM * DIM];
__device__ __align__(256) __half g_qk [(size_t)2 * NR * DIM];   // [q | k]
__device__ __align__(256) __half g_vt [(size_t)BATCH * DIM * SEQ];
__device__ __align__(256) __half g_e  [(size_t)BATCH * SEQ * SEQ];  // E then P in place
__device__ float g_ps  [BATCH * NCHUNK * SEQ];
__device__ float g_csi [BATCH * SEQ];
__device__ float g_rinv[BATCH * SEQ];
__device__ float g_bqk [2 * DIM];

// ---------------- PTX helpers (baseline compute_103-safe) ----------------
__device__ __forceinline__ uint32_t smem_u32(const void* p) {
    uint32_t a;
    asm("{ .reg .u64 t; cvta.to.shared.u64 t, %1; cvt.u32.u64 %0, t; }" : "=r"(a) : "l"(p));
    return a;
}
__device__ __forceinline__ void cp_async16(uint32_t d, const void* g) {
    asm volatile("cp.async.cg.shared.global [%0], [%1], 16;" :: "r"(d), "l"(g));
}
__device__ __forceinline__ void cp_commit() {
    asm volatile("cp.async.commit_group;" ::: "memory");
}
template <int N>
__device__ __forceinline__ void cp_wait() {
    asm volatile("cp.async.wait_group %0;" :: "n"(N) : "memory");
}
__device__ __forceinline__ void ldsm4(uint32_t& r0, uint32_t& r1, uint32_t& r2, uint32_t& r3,
                                      uint32_t addr) {
    asm volatile("ldmatrix.sync.aligned.m8n8.x4.shared.b16 {%0,%1,%2,%3}, [%4];"
                 : "=r"(r0), "=r"(r1), "=r"(r2), "=r"(r3) : "r"(addr));
}
__device__ __forceinline__ void mma16816(float* c, const uint32_t* a, uint32_t b0, uint32_t b1) {
    asm volatile(
        "mma.sync.aligned.m16n8k16.row.col.f32.f16.f16.f32 "
        "{%0,%1,%2,%3}, {%4,%5,%6,%7}, {%8,%9}, {%0,%1,%2,%3};"
        : "+f"(c[0]), "+f"(c[1]), "+f"(c[2]), "+f"(c[3])
        : "r"(a[0]), "r"(a[1]), "r"(a[2]), "r"(a[3]), "r"(b0), "r"(b1));
}

// ---------------- HMMA plain-fp16 GEMM, CTA tile 256x128, warp tile 64x64 ----
// C[M,N] = A[M,Kc] @ B[N,Kc]^T  (A,B fp16 K-major); M%256==0, N%128==0, Kc%32==0
// pattern 0: outf = (acc*alpha + bias_col + bias_row) * rowscale[z*M+row]
// pattern 5: outh = fp16(acc*alpha + bias_col + bias_row)
// pattern 6: outh = fp16(exp(acc*alpha)); fused column sums -> g_ps (per 256-row chunk)
// bias_col indexed as bias_col[z*bias_zs + col]
#define BK 32
#define STAGES 5
#define A_STAGE (256 * 80)
#define B_STAGE (128 * 80)
#define STAGE_BYTES (A_STAGE + B_STAGE)
#define GEMM_DSMEM (STAGES * STAGE_BYTES)

__global__ void __launch_bounds__(256, 1) gemm_h(
    const __half* __restrict__ A, const __half* __restrict__ B,
    int M, int N, int Kc,
    size_t sA, size_t sB, size_t sC,
    float alpha,
    const float* __restrict__ bias_col, int bias_zs,
    const float* __restrict__ bias_row,
    const float* __restrict__ rowscale,
    float* __restrict__ outf, __half* __restrict__ outh, int pattern)
{
    extern __shared__ char dyn[];
    uint32_t dynb = smem_u32(dyn);

    int z = blockIdx.z;
    const __half* Ab = A + (size_t)z * sA + (size_t)(blockIdx.y * 256) * Kc;
    const __half* Bb = B + (size_t)z * sB + (size_t)(blockIdx.x * 128) * Kc;
    int bm = blockIdx.y * 256;
    int bn = blockIdx.x * 128;

    int t = threadIdx.x;
    int wid = t >> 5, lane = t & 31;
    int wm = wid & 3;        // 4 warps over M (64 rows each)
    int wn = wid >> 2;       // 2 warps over N (64 cols each)

    float acc[4][8][4];
    #pragma unroll
    for (int i = 0; i < 4; i++)
        #pragma unroll
        for (int j = 0; j < 8; j++)
            #pragma unroll
            for (int r = 0; r < 4; r++) acc[i][j][r] = 0.0f;

    int nkb = Kc / BK;

    auto issue = [&](int kb) {
        int slot = kb % STAGES;
        uint32_t sa = dynb + slot * STAGE_BYTES;
        uint32_t sb = sa + A_STAGE;
        int kh = kb * BK;
        #pragma unroll
        for (int i = 0; i < 4; i++) {           // A: 256 rows x 32 k
            int idx = t + 256 * i;
            int row = idx >> 2, c = idx & 3;
            cp_async16(sa + row * 80 + c * 16, Ab + (size_t)row * Kc + kh + c * 8);
        }
        #pragma unroll
        for (int i = 0; i < 2; i++) {           // B: 128 rows x 32 k
            int idx = t + 256 * i;
            int row = idx >> 2, c = idx & 3;
            cp_async16(sb + row * 80 + c * 16, Bb + (size_t)row * Kc + kh + c * 8);
        }
    };

    issue(0); cp_commit();
    issue(1); cp_commit();
    issue(2); cp_commit();
    issue(3); cp_commit();

    uint32_t a_lane = (uint32_t)((wm * 64 + (lane & 15)) * 80 + ((lane >> 4) * 8) * 2);
    uint32_t b_lane = (uint32_t)(A_STAGE +
                       (wn * 64 + (lane & 7) + (lane >> 4) * 8) * 80 +
                       (((lane >> 3) & 1) * 8) * 2);

    cp_wait<2>();          // slots 0 and 1 ready
    __syncthreads();

    uint32_t af[2][4][4];  // A fragments, double buffered (4 x m16)
    uint32_t bf[2][4][4];  // B fragments, double buffered (4 x n16)

    {
        uint32_t s0 = dynb;
        #pragma unroll
        for (int mi = 0; mi < 4; mi++)
            ldsm4(af[0][mi][0], af[0][mi][1], af[0][mi][2], af[0][mi][3],
                  s0 + a_lane + mi * (16 * 80));
        #pragma unroll
        for (int g = 0; g < 4; g++)
            ldsm4(bf[0][g][0], bf[0][g][1], bf[0][g][2], bf[0][g][3],
                  s0 + b_lane + g * (16 * 80));
    }

    int p = 0;
    for (int kb = 0; kb < nkb; kb++) {
        if (kb + 4 < nkb) issue(kb + 4);
        cp_commit();
        uint32_t scur = dynb + (kb % STAGES) * STAGE_BYTES;
        uint32_t snxt = dynb + ((kb + 1) % STAGES) * STAGE_BYTES;

        // ---- ks = 0: prefetch (kb, ks1) into p^1, mma on p ----
        #pragma unroll
        for (int mi = 0; mi < 4; mi++)
            ldsm4(af[p^1][mi][0], af[p^1][mi][1], af[p^1][mi][2], af[p^1][mi][3],
                  scur + a_lane + mi * (16 * 80) + 32);
        #pragma unroll
        for (int g = 0; g < 4; g++)
            ldsm4(bf[p^1][g][0], bf[p^1][g][1], bf[p^1][g][2], bf[p^1][g][3],
                  scur + b_lane + g * (16 * 80) + 32);
        #pragma unroll
        for (int mi = 0; mi < 4; mi++)
            #pragma unroll
            for (int ni = 0; ni < 8; ni++)
                mma16816(acc[mi][ni], af[p][mi],
                         bf[p][ni >> 1][(ni & 1) * 2], bf[p][ni >> 1][(ni & 1) * 2 + 1]);
        p ^= 1;

        // ---- ks = 1: prefetch (kb+1, ks0) into p^1, mma on p ----
        if (kb + 1 < nkb) {
            #pragma unroll
            for (int mi = 0; mi < 4; mi++)
                ldsm4(af[p^1][mi][0], af[p^1][mi][1], af[p^1][mi][2], af[p^1][mi][3],
                      snxt + a_lane + mi * (16 * 80));
            #pragma unroll
            for (int g = 0; g < 4; g++)
                ldsm4(bf[p^1][g][0], bf[p^1][g][1], bf[p^1][g][2], bf[p^1][g][3],
                      snxt + b_lane + g * (16 * 80));
        }
        #pragma unroll
        for (int mi = 0; mi < 4; mi++)
            #pragma unroll
            for (int ni = 0; ni < 8; ni++)
                mma16816(acc[mi][ni], af[p][mi],
                         bf[p][ni >> 1][(ni & 1) * 2], bf[p][ni >> 1][(ni & 1) * 2 + 1]);
        p ^= 1;

        cp_wait<2>();
        __syncthreads();
    }

    // ---------------- store epilogue ----------------
    int r_lane = lane >> 2;
    int c_lane = (lane & 3) * 2;

    if (pattern == 6) {
        float csum[8][2];
        #pragma unroll
        for (int ni = 0; ni < 8; ni++) { csum[ni][0] = 0.0f; csum[ni][1] = 0.0f; }

        #pragma unroll
        for (int mi = 0; mi < 4; mi++) {
            #pragma unroll
            for (int ni = 0; ni < 8; ni++) {
                int row = bm + wm * 64 + mi * 16 + r_lane;
                int col = bn + wn * 64 + ni * 8 + c_lane;
                float* a4 = acc[mi][ni];
                #pragma unroll
                for (int h = 0; h < 2; h++) {
                    int rr = row + h * 8;
                    float e0 = __expf(a4[h * 2 + 0] * alpha);
                    float e1 = __expf(a4[h * 2 + 1] * alpha);
                    csum[ni][0] += e0;
                    csum[ni][1] += e1;
                    __half2 hh = __halves2half2(__float2half_rn(e0), __float2half_rn(e1));
                    *(__half2*)(outh + (size_t)z * sC + (size_t)rr * N + col) = hh;
                }
            }
        }
        // reduce over the 8 lane-rows (lane bits 2..4)
        #pragma unroll
        for (int o = 4; o < 32; o <<= 1)
            #pragma unroll
            for (int ni = 0; ni < 8; ni++) {
                csum[ni][0] += __shfl_xor_sync(0xffffffffu, csum[ni][0], o);
                csum[ni][1] += __shfl_xor_sync(0xffffffffu, csum[ni][1], o);
            }
        cp_wait<0>();
        __syncthreads();
        float* ssm = (float*)dyn;            // [4][128]
        if ((lane >> 2) == 0) {
            #pragma unroll
            for (int ni = 0; ni < 8; ni++) {
                int col = wn * 64 + ni * 8 + (lane & 3) * 2;
                ssm[wm * 128 + col]     = csum[ni][0];
                ssm[wm * 128 + col + 1] = csum[ni][1];
            }
        }
        __syncthreads();
        if (t < 128) {
            float s = ssm[t] + ssm[128 + t] + ssm[256 + t] + ssm[384 + t];
            g_ps[((size_t)z * NCHUNK + blockIdx.y) * SEQ + bn + t] = s;
        }
        return;
    }

    #pragma unroll
    for (int mi = 0; mi < 4; mi++) {
        #pragma unroll
        for (int ni = 0; ni < 8; ni++) {
            int row = bm + wm * 64 + mi * 16 + r_lane;
            int col = bn + wn * 64 + ni * 8 + c_lane;
            float* a4 = acc[mi][ni];
            float bc0 = bias_col ? bias_col[z * bias_zs + col]     : 0.0f;
            float bc1 = bias_col ? bias_col[z * bias_zs + col + 1] : 0.0f;
            #pragma unroll
            for (int h = 0; h < 2; h++) {
                int rr = row + h * 8;
                float br = bias_row ? bias_row[rr] : 0.0f;
                float v0 = a4[h * 2 + 0] * alpha + bc0 + br;
                float v1 = a4[h * 2 + 1] * alpha + bc1 + br;
                if (pattern == 0) {
                    float rs = rowscale ? rowscale[(size_t)z * M + rr] : 1.0f;
                    float2 o = make_float2(v0 * rs, v1 * rs);
                    *(float2*)(outf + (size_t)z * sC + (size_t)rr * N + col) = o;
                } else {  // pattern 5: plain fp16
                    __half2 hh = __halves2half2(__float2half_rn(v0), __float2half_rn(v1));
                    *(__half2*)(outh + (size_t)z * sC + (size_t)rr * N + col) = hh;
                }
            }
        }
    }
}

// ---------------- merged LayerNorm (x then c) -> fp16 g_xc ----
__global__ void __launch_bounds__(128) ln_kernel(const float* __restrict__ xin,
                                                 const float* __restrict__ cin,
                                                 const float* __restrict__ gx,
                                                 const float* __restrict__ bx,
                                                 const float* __restrict__ gc,
                                                 const float* __restrict__ bc) {
    int row = blockIdx.x;
    const float* x;
    const float* g;
    const float* b;
    __half* y;
    if (row < NR) {
        x = xin + (size_t)row * DIM; g = gx; b = bx;
        y = g_xc + (size_t)row * DIM;
    } else {
        int r2 = row - NR;
        x = cin + (size_t)r2 * DIM; g = gc; b = bc;
        y = g_xc + (size_t)NR * DIM + (size_t)r2 * DIM;
    }
    int t = threadIdx.x;
    float4 v = ((const float4*)x)[t];
    float s  = v.x + v.y + v.z + v.w;
    float ss = v.x*v.x + v.y*v.y + v.z*v.z + v.w*v.w;
    __shared__ float sh[8];
    #pragma unroll
    for (int o = 16; o > 0; o >>= 1) {
        s  += __shfl_down_sync(0xffffffffu, s, o);
        ss += __shfl_down_sync(0xffffffffu, ss, o);
    }
    if ((t & 31) == 0) { sh[t >> 5] = s; sh[4 + (t >> 5)] = ss; }
    __syncthreads();
    float fs  = sh[0] + sh[1] + sh[2] + sh[3];
    float fss = sh[4] + sh[5] + sh[6] + sh[7];
    float mu  = fs * (1.0f / DIM);
    float var = fss * (1.0f / DIM) - mu * mu;
    float rstd = rsqrtf(var + LN_EPS_F);
    float4 gv = ((const float4*)g)[t];
    float4 bv = ((const float4*)b)[t];
    float o0 = (v.x - mu) * rstd * gv.x + bv.x;
    float o1 = (v.y - mu) * rstd * gv.y + bv.y;
    float o2 = (v.z - mu) * rstd * gv.z + bv.z;
    float o3 = (v.w - mu) * rstd * gv.w + bv.w;
    ((__half2*)(y + t * 4))[0] = __halves2half2(__float2half_rn(o0), __float2half_rn(o1));
    ((__half2*)(y + t * 4))[1] = __halves2half2(__float2half_rn(o2), __float2half_rn(o3));
}

// ---------------- weight transpose: W[512,512] fp32 -> Wt[512,512] fp16 ----
__global__ void __launch_bounds__(256) tsplit_kernel(const float* __restrict__ in,
                                                     __half* __restrict__ out) {
    __shared__ float tile[32][33];
    int r0 = blockIdx.y * 32, c0 = blockIdx.x * 32;
    int tx = threadIdx.x & 31, ty = threadIdx.x >> 5;
    #pragma unroll
    for (int i = ty; i < 32; i += 8)
        tile[i][tx] = in[(size_t)(r0 + i) * DIM + c0 + tx];
    __syncthreads();
    #pragma unroll
    for (int i = ty; i < 32; i += 8)
        out[(size_t)(c0 + i) * DIM + r0 + tx] = __float2half_rn(tile[tx][i]);
}

// ---------------- pack q/k biases into one buffer ----------------
__global__ void __launch_bounds__(512) packbias_kernel(const float* __restrict__ bq,
                                                       const float* __restrict__ bk) {
    int t = threadIdx.x;
    g_bqk[t] = bq[t];
    g_bqk[DIM + t] = bk[t];
}

// ---------------- column sums combine -> 1/colsum ----------------
__global__ void __launch_bounds__(256) colstats2_kernel() {
    int j = blockIdx.x * 256 + threadIdx.x;
    int z = blockIdx.y;
    float s = 0.0f;
    #pragma unroll
    for (int c = 0; c < NCHUNK; c++)
        s += g_ps[((size_t)z * NCHUNK + c) * SEQ + j];
    g_csi[(size_t)z * SEQ + j] = 1.0f / s;
}

// ---------------- row pass (in place): P = E*csi + EPS (fp16), rinv ----------------
__global__ void __launch_bounds__(256) rowpass_kernel() {
    int i = blockIdx.x;
    int z = blockIdx.y;
    int t = threadIdx.x;
    __half* row = g_e + ((size_t)z * SEQ + i) * SEQ;
    const float* ci = g_csi + (size_t)z * SEQ;
    float acc = 0.0f;
    #pragma unroll 2
    for (int j2 = t; j2 < SEQ / 2; j2 += 256) {
        int j = j2 * 2;
        __half2 e2 = *(__half2*)(row + j);
        float2 c2 = *(const float2*)(ci + j);
        float a0 = __half2float(__low2half(e2))  * c2.x + EPS_F;
        float a1 = __half2float(__high2half(e2)) * c2.y + EPS_F;
        acc += a0 + a1;
        *(__half2*)(row + j) = __halves2half2(__float2half_rn(a0), __float2half_rn(a1));
    }
    __shared__ float sh[8];
    #pragma unroll
    for (int o = 16; o > 0; o >>= 1)
        acc += __shfl_down_sync(0xffffffffu, acc, o);
    if ((t & 31) == 0) sh[t >> 5] = acc;
    __syncthreads();
    if (t == 0) {
        float s = 0.0f;
        #pragma unroll
        for (int w = 0; w < 8; w++) s += sh[w];
        g_rinv[(size_t)z * SEQ + i] = 1.0f / (s + EPS_F);
    }
}

// ---------------- launch ----------------
extern "C" void kernel_launch(void* const* d_in, const int* in_sizes, int n_in,
                              void* d_out, int out_size) {
    const float* inputs  = (const float*)d_in[0];
    const float* context = (const float*)d_in[1];
    const float* gin  = (const float*)d_in[2];
    const float* bin  = (const float*)d_in[3];
    const float* gctx = (const float*)d_in[4];
    const float* bctx = (const float*)d_in[5];
    const float* Wq = (const float*)d_in[6];
    const float* bq = (const float*)d_in[7];
    const float* Wk = (const float*)d_in[8];
    const float* bk = (const float*)d_in[9];
    const float* Wv = (const float*)d_in[10];
    const float* bv = (const float*)d_in[11];
    float* out = (float*)d_out;

    __half *xc, *wqk, *wvt, *qk, *vt, *e;
    float *rinv, *bqk;
    cudaGetSymbolAddress((void**)&xc,   g_xc);
    cudaGetSymbolAddress((void**)&wqk,  g_wqk);
    cudaGetSymbolAddress((void**)&wvt,  g_wvt);
    cudaGetSymbolAddress((void**)&qk,   g_qk);
    cudaGetSymbolAddress((void**)&vt,   g_vt);
    cudaGetSymbolAddress((void**)&e,    g_e);
    cudaGetSymbolAddress((void**)&rinv, g_rinv);
    cudaGetSymbolAddress((void**)&bqk,  g_bqk);

    cudaFuncSetAttribute(gemm_h, cudaFuncAttributeMaxDynamicSharedMemorySize, GEMM_DSMEM);

    // LayerNorms (merged) + bias pack + weight transposes
    packbias_kernel<<<1, 512>>>(bq, bk);
    ln_kernel<<<2 * NR, 128>>>(inputs, context, gin, bin, gctx, bctx);
    {
        dim3 g(DIM / 32, DIM / 32, 1);
        tsplit_kernel<<<g, 256>>>(Wq, wqk);
        tsplit_kernel<<<g, 256>>>(Wk, wqk + (size_t)DIM * DIM);
        tsplit_kernel<<<g, 256>>>(Wv, wvt);
    }

    // q & k in one batched GEMM: z=0 -> q(xn,Wq,bq), z=1 -> k(cn,Wk,bk)
    {
        dim3 grid(DIM / 128, NR / 256, 2);
        gemm_h<<<grid, 256, GEMM_DSMEM>>>(xc, wqk, NR, DIM, DIM,
                                          (size_t)NR * DIM, (size_t)DIM * DIM,
                                          (size_t)NR * DIM,
                                          1.0f, bqk, DIM, nullptr, nullptr,
                                          nullptr, qk, 5);
    }

    // vt[d,j] = (cn@Wv + bv)^T (M=512, N=2048, Kc=512, batched over b)
    {
        dim3 grid(SEQ / 128, DIM / 256, BATCH);
        gemm_h<<<grid, 256, GEMM_DSMEM>>>(wvt, xc + (size_t)NR * DIM, DIM, SEQ, DIM,
                                          0, (size_t)SEQ * DIM, (size_t)DIM * SEQ,
                                          1.0f, nullptr, 0, bv, nullptr,
                                          nullptr, vt, 5);
    }

    // E = exp(scale * q @ k^T) fp16 + fused column sums
    {
        float scale = 1.0f / sqrtf((float)DIM);
        dim3 grid(SEQ / 128, SEQ / 256, BATCH);
        gemm_h<<<grid, 256, GEMM_DSMEM>>>(qk, qk + (size_t)NR * DIM, SEQ, SEQ, DIM,
                                          (size_t)SEQ * DIM, (size_t)SEQ * DIM,
                                          (size_t)SEQ * SEQ, scale,
                                          nullptr, 0, nullptr, nullptr,
                                          nullptr, e, 6);
    }

    // csi = 1/colsum ; P = E*csi + EPS (in place), rinv
    colstats2_kernel<<<dim3(SEQ / 256, BATCH), 256>>>();
    rowpass_kernel<<<dim3(SEQ, BATCH), 256>>>();

    // out = rinv[i] * (P @ vt^T) (M=2048, N=512, Kc=2048, batched)
    {
        dim3 grid(DIM / 128, SEQ / 256, BATCH);
        gemm_h<<<grid, 256, GEMM_DSMEM>>>(e, vt, SEQ, DIM, SEQ,
                                          (size_t)SEQ * SEQ, (size_t)DIM * SEQ,
                                          (size_t)SEQ * DIM, 1.0f,
                                          nullptr, 0, nullptr, rinv,
                                          out, nullptr, 0);
    }
}

// round 12
// speedup vs baseline: 12.0741x; 1.0112x over previous
#include <cuda_runtime.h>
#include <cuda_fp16.h>
#include <math.h>
#include <stdint.h>

#define BATCH 8
#define SEQ   2048
#define DIM   512
#define NCHUNK 8          // 256-row chunks of SEQ (dots M-tiles)
#define NR    (BATCH * SEQ)

static const float LN_EPS_F = 1e-5f;

// ---------------- scratch (static device globals; no allocation) ----------------
__device__ __align__(256) __half g_xc [(size_t)2 * NR * DIM];   // [xn | cn]
__device__ __align__(256) __half g_wqk[(size_t)2 * DIM * DIM];  // [Wq^T | Wk^T]
__device__ __align__(256) __half g_wvt[(size_t)DIM * DIM];
__device__ __align__(256) __half g_qk [(size_t)2 * NR * DIM];   // [q | k]
__device__ __align__(256) __half g_vt [(size_t)BATCH * DIM * SEQ];  // vt' = vt * csi
__device__ __align__(256) __half g_e  [(size_t)BATCH * SEQ * SEQ];  // E = exp(dots*scale)
__device__ float g_ps  [BATCH * NCHUNK * SEQ];
__device__ float g_csi [BATCH * SEQ];
__device__ float g_rinv[BATCH * SEQ];
__device__ float g_bqk [2 * DIM];

// ---------------- PTX helpers (baseline compute_103-safe) ----------------
__device__ __forceinline__ uint32_t smem_u32(const void* p) {
    uint32_t a;
    asm("{ .reg .u64 t; cvta.to.shared.u64 t, %1; cvt.u32.u64 %0, t; }" : "=r"(a) : "l"(p));
    return a;
}
__device__ __forceinline__ void cp_async16(uint32_t d, const void* g) {
    asm volatile("cp.async.cg.shared.global [%0], [%1], 16;" :: "r"(d), "l"(g));
}
__device__ __forceinline__ void cp_commit() {
    asm volatile("cp.async.commit_group;" ::: "memory");
}
template <int N>
__device__ __forceinline__ void cp_wait() {
    asm volatile("cp.async.wait_group %0;" :: "n"(N) : "memory");
}
__device__ __forceinline__ void ldsm4(uint32_t& r0, uint32_t& r1, uint32_t& r2, uint32_t& r3,
                                      uint32_t addr) {
    asm volatile("ldmatrix.sync.aligned.m8n8.x4.shared.b16 {%0,%1,%2,%3}, [%4];"
                 : "=r"(r0), "=r"(r1), "=r"(r2), "=r"(r3) : "r"(addr));
}
__device__ __forceinline__ void mma16816(float* c, const uint32_t* a, uint32_t b0, uint32_t b1) {
    asm volatile(
        "mma.sync.aligned.m16n8k16.row.col.f32.f16.f16.f32 "
        "{%0,%1,%2,%3}, {%4,%5,%6,%7}, {%8,%9}, {%0,%1,%2,%3};"
        : "+f"(c[0]), "+f"(c[1]), "+f"(c[2]), "+f"(c[3])
        : "r"(a[0]), "r"(a[1]), "r"(a[2]), "r"(a[3]), "r"(b0), "r"(b1));
}

// ---------------- HMMA plain-fp16 GEMM, CTA tile 256x128, warp tile 64x64 ----
// C[M,N] = A[M,Kc] @ B[N,Kc]^T  (A,B fp16 K-major); M%256==0, N%128==0, Kc%32==0
// pattern 0: outf = (acc*alpha + bias_col + bias_row) * rowscale[z*M+row]
// pattern 5: outh = fp16((acc*alpha + bias_col + bias_row) * colscale)
// pattern 6: outh = fp16(exp(acc*alpha)); fused column sums -> g_ps (per 256-row chunk)
// bias_col[z*bias_zs + col]; colscale[z*cs_zs + col]
#define BK 32
#define STAGES 5
#define A_STAGE (256 * 80)
#define B_STAGE (128 * 80)
#define STAGE_BYTES (A_STAGE + B_STAGE)
#define GEMM_DSMEM (STAGES * STAGE_BYTES)

__global__ void __launch_bounds__(256, 1) gemm_h(
    const __half* __restrict__ A, const __half* __restrict__ B,
    int M, int N, int Kc,
    size_t sA, size_t sB, size_t sC,
    float alpha,
    const float* __restrict__ bias_col, int bias_zs,
    const float* __restrict__ bias_row,
    const float* __restrict__ rowscale,
    const float* __restrict__ colscale, int cs_zs,
    float* __restrict__ outf, __half* __restrict__ outh, int pattern)
{
    extern __shared__ char dyn[];
    uint32_t dynb = smem_u32(dyn);

    int z = blockIdx.z;
    const __half* Ab = A + (size_t)z * sA + (size_t)(blockIdx.y * 256) * Kc;
    const __half* Bb = B + (size_t)z * sB + (size_t)(blockIdx.x * 128) * Kc;
    int bm = blockIdx.y * 256;
    int bn = blockIdx.x * 128;

    int t = threadIdx.x;
    int wid = t >> 5, lane = t & 31;
    int wm = wid & 3;        // 4 warps over M (64 rows each)
    int wn = wid >> 2;       // 2 warps over N (64 cols each)

    float acc[4][8][4];
    #pragma unroll
    for (int i = 0; i < 4; i++)
        #pragma unroll
        for (int j = 0; j < 8; j++)
            #pragma unroll
            for (int r = 0; r < 4; r++) acc[i][j][r] = 0.0f;

    int nkb = Kc / BK;

    auto issue = [&](int kb) {
        int slot = kb % STAGES;
        uint32_t sa = dynb + slot * STAGE_BYTES;
        uint32_t sb = sa + A_STAGE;
        int kh = kb * BK;
        #pragma unroll
        for (int i = 0; i < 4; i++) {           // A: 256 rows x 32 k
            int idx = t + 256 * i;
            int row = idx >> 2, c = idx & 3;
            cp_async16(sa + row * 80 + c * 16, Ab + (size_t)row * Kc + kh + c * 8);
        }
        #pragma unroll
        for (int i = 0; i < 2; i++) {           // B: 128 rows x 32 k
            int idx = t + 256 * i;
            int row = idx >> 2, c = idx & 3;
            cp_async16(sb + row * 80 + c * 16, Bb + (size_t)row * Kc + kh + c * 8);
        }
    };

    issue(0); cp_commit();
    issue(1); cp_commit();
    issue(2); cp_commit();
    issue(3); cp_commit();

    uint32_t a_lane = (uint32_t)((wm * 64 + (lane & 15)) * 80 + ((lane >> 4) * 8) * 2);
    uint32_t b_lane = (uint32_t)(A_STAGE +
                       (wn * 64 + (lane & 7) + (lane >> 4) * 8) * 80 +
                       (((lane >> 3) & 1) * 8) * 2);

    cp_wait<2>();          // slots 0 and 1 ready
    __syncthreads();

    uint32_t af[2][4][4];  // A fragments, double buffered (4 x m16)
    uint32_t bf[2][4][4];  // B fragments, double buffered (4 x n16)

    {
        uint32_t s0 = dynb;
        #pragma unroll
        for (int mi = 0; mi < 4; mi++)
            ldsm4(af[0][mi][0], af[0][mi][1], af[0][mi][2], af[0][mi][3],
                  s0 + a_lane + mi * (16 * 80));
        #pragma unroll
        for (int g = 0; g < 4; g++)
            ldsm4(bf[0][g][0], bf[0][g][1], bf[0][g][2], bf[0][g][3],
                  s0 + b_lane + g * (16 * 80));
    }

    int p = 0;
    for (int kb = 0; kb < nkb; kb++) {
        if (kb + 4 < nkb) issue(kb + 4);
        cp_commit();
        uint32_t scur = dynb + (kb % STAGES) * STAGE_BYTES;
        uint32_t snxt = dynb + ((kb + 1) % STAGES) * STAGE_BYTES;

        // ---- ks = 0: prefetch (kb, ks1) into p^1, mma on p ----
        #pragma unroll
        for (int mi = 0; mi < 4; mi++)
            ldsm4(af[p^1][mi][0], af[p^1][mi][1], af[p^1][mi][2], af[p^1][mi][3],
                  scur + a_lane + mi * (16 * 80) + 32);
        #pragma unroll
        for (int g = 0; g < 4; g++)
            ldsm4(bf[p^1][g][0], bf[p^1][g][1], bf[p^1][g][2], bf[p^1][g][3],
                  scur + b_lane + g * (16 * 80) + 32);
        #pragma unroll
        for (int mi = 0; mi < 4; mi++)
            #pragma unroll
            for (int ni = 0; ni < 8; ni++)
                mma16816(acc[mi][ni], af[p][mi],
                         bf[p][ni >> 1][(ni & 1) * 2], bf[p][ni >> 1][(ni & 1) * 2 + 1]);
        p ^= 1;

        // ---- ks = 1: prefetch (kb+1, ks0) into p^1, mma on p ----
        if (kb + 1 < nkb) {
            #pragma unroll
            for (int mi = 0; mi < 4; mi++)
                ldsm4(af[p^1][mi][0], af[p^1][mi][1], af[p^1][mi][2], af[p^1][mi][3],
                      snxt + a_lane + mi * (16 * 80));
            #pragma unroll
            for (int g = 0; g < 4; g++)
                ldsm4(bf[p^1][g][0], bf[p^1][g][1], bf[p^1][g][2], bf[p^1][g][3],
                      snxt + b_lane + g * (16 * 80));
        }
        #pragma unroll
        for (int mi = 0; mi < 4; mi++)
            #pragma unroll
            for (int ni = 0; ni < 8; ni++)
                mma16816(acc[mi][ni], af[p][mi],
                         bf[p][ni >> 1][(ni & 1) * 2], bf[p][ni >> 1][(ni & 1) * 2 + 1]);
        p ^= 1;

        cp_wait<2>();
        __syncthreads();
    }

    // ---------------- store epilogue ----------------
    int r_lane = lane >> 2;
    int c_lane = (lane & 3) * 2;

    if (pattern == 6) {
        float csum[8][2];
        #pragma unroll
        for (int ni = 0; ni < 8; ni++) { csum[ni][0] = 0.0f; csum[ni][1] = 0.0f; }

        #pragma unroll
        for (int mi = 0; mi < 4; mi++) {
            #pragma unroll
            for (int ni = 0; ni < 8; ni++) {
                int row = bm + wm * 64 + mi * 16 + r_lane;
                int col = bn + wn * 64 + ni * 8 + c_lane;
                float* a4 = acc[mi][ni];
                #pragma unroll
                for (int h = 0; h < 2; h++) {
                    int rr = row + h * 8;
                    float e0 = __expf(a4[h * 2 + 0] * alpha);
                    float e1 = __expf(a4[h * 2 + 1] * alpha);
                    csum[ni][0] += e0;
                    csum[ni][1] += e1;
                    __half2 hh = __halves2half2(__float2half_rn(e0), __float2half_rn(e1));
                    *(__half2*)(outh + (size_t)z * sC + (size_t)rr * N + col) = hh;
                }
            }
        }
        // reduce over the 8 lane-rows (lane bits 2..4)
        #pragma unroll
        for (int o = 4; o < 32; o <<= 1)
            #pragma unroll
            for (int ni = 0; ni < 8; ni++) {
                csum[ni][0] += __shfl_xor_sync(0xffffffffu, csum[ni][0], o);
                csum[ni][1] += __shfl_xor_sync(0xffffffffu, csum[ni][1], o);
            }
        cp_wait<0>();
        __syncthreads();
        float* ssm = (float*)dyn;            // [4][128]
        if ((lane >> 2) == 0) {
            #pragma unroll
            for (int ni = 0; ni < 8; ni++) {
                int col = wn * 64 + ni * 8 + (lane & 3) * 2;
                ssm[wm * 128 + col]     = csum[ni][0];
                ssm[wm * 128 + col + 1] = csum[ni][1];
            }
        }
        __syncthreads();
        if (t < 128) {
            float s = ssm[t] + ssm[128 + t] + ssm[256 + t] + ssm[384 + t];
            g_ps[((size_t)z * NCHUNK + blockIdx.y) * SEQ + bn + t] = s;
        }
        return;
    }

    #pragma unroll
    for (int mi = 0; mi < 4; mi++) {
        #pragma unroll
        for (int ni = 0; ni < 8; ni++) {
            int row = bm + wm * 64 + mi * 16 + r_lane;
            int col = bn + wn * 64 + ni * 8 + c_lane;
            float* a4 = acc[mi][ni];
            float bc0 = bias_col ? bias_col[z * bias_zs + col]     : 0.0f;
            float bc1 = bias_col ? bias_col[z * bias_zs + col + 1] : 0.0f;
            float cs0 = colscale ? colscale[z * cs_zs + col]       : 1.0f;
            float cs1 = colscale ? colscale[z * cs_zs + col + 1]   : 1.0f;
            #pragma unroll
            for (int h = 0; h < 2; h++) {
                int rr = row + h * 8;
                float br = bias_row ? bias_row[rr] : 0.0f;
                float v0 = (a4[h * 2 + 0] * alpha + bc0 + br) * cs0;
                float v1 = (a4[h * 2 + 1] * alpha + bc1 + br) * cs1;
                if (pattern == 0) {
                    float rs = rowscale ? rowscale[(size_t)z * M + rr] : 1.0f;
                    float2 o = make_float2(v0 * rs, v1 * rs);
                    *(float2*)(outf + (size_t)z * sC + (size_t)rr * N + col) = o;
                } else {  // pattern 5: plain fp16
                    __half2 hh = __halves2half2(__float2half_rn(v0), __float2half_rn(v1));
                    *(__half2*)(outh + (size_t)z * sC + (size_t)rr * N + col) = hh;
                }
            }
        }
    }
}

// ---------------- merged LayerNorm (x then c) -> fp16 g_xc ----
__global__ void __launch_bounds__(128) ln_kernel(const float* __restrict__ xin,
                                                 const float* __restrict__ cin,
                                                 const float* __restrict__ gx,
                                                 const float* __restrict__ bx,
                                                 const float* __restrict__ gc,
                                                 const float* __restrict__ bc) {
    int row = blockIdx.x;
    const float* x;
    const float* g;
    const float* b;
    __half* y;
    if (row < NR) {
        x = xin + (size_t)row * DIM; g = gx; b = bx;
        y = g_xc + (size_t)row * DIM;
    } else {
        int r2 = row - NR;
        x = cin + (size_t)r2 * DIM; g = gc; b = bc;
        y = g_xc + (size_t)NR * DIM + (size_t)r2 * DIM;
    }
    int t = threadIdx.x;
    float4 v = ((const float4*)x)[t];
    float s  = v.x + v.y + v.z + v.w;
    float ss = v.x*v.x + v.y*v.y + v.z*v.z + v.w*v.w;
    __shared__ float sh[8];
    #pragma unroll
    for (int o = 16; o > 0; o >>= 1) {
        s  += __shfl_down_sync(0xffffffffu, s, o);
        ss += __shfl_down_sync(0xffffffffu, ss, o);
    }
    if ((t & 31) == 0) { sh[t >> 5] = s; sh[4 + (t >> 5)] = ss; }
    __syncthreads();
    float fs  = sh[0] + sh[1] + sh[2] + sh[3];
    float fss = sh[4] + sh[5] + sh[6] + sh[7];
    float mu  = fs * (1.0f / DIM);
    float var = fss * (1.0f / DIM) - mu * mu;
    float rstd = rsqrtf(var + LN_EPS_F);
    float4 gv = ((const float4*)g)[t];
    float4 bv = ((const float4*)b)[t];
    float o0 = (v.x - mu) * rstd * gv.x + bv.x;
    float o1 = (v.y - mu) * rstd * gv.y + bv.y;
    float o2 = (v.z - mu) * rstd * gv.z + bv.z;
    float o3 = (v.w - mu) * rstd * gv.w + bv.w;
    ((__half2*)(y + t * 4))[0] = __halves2half2(__float2half_rn(o0), __float2half_rn(o1));
    ((__half2*)(y + t * 4))[1] = __halves2half2(__float2half_rn(o2), __float2half_rn(o3));
}

// ---------------- weight transpose: W[512,512] fp32 -> Wt[512,512] fp16 ----
__global__ void __launch_bounds__(256) tsplit_kernel(const float* __restrict__ in,
                                                     __half* __restrict__ out) {
    __shared__ float tile[32][33];
    int r0 = blockIdx.y * 32, c0 = blockIdx.x * 32;
    int tx = threadIdx.x & 31, ty = threadIdx.x >> 5;
    #pragma unroll
    for (int i = ty; i < 32; i += 8)
        tile[i][tx] = in[(size_t)(r0 + i) * DIM + c0 + tx];
    __syncthreads();
    #pragma unroll
    for (int i = ty; i < 32; i += 8)
        out[(size_t)(c0 + i) * DIM + r0 + tx] = __float2half_rn(tile[tx][i]);
}

// ---------------- pack q/k biases into one buffer ----------------
__global__ void __launch_bounds__(512) packbias_kernel(const float* __restrict__ bq,
                                                       const float* __restrict__ bk) {
    int t = threadIdx.x;
    g_bqk[t] = bq[t];
    g_bqk[DIM + t] = bk[t];
}

// ---------------- column sums combine -> 1/colsum ----------------
__global__ void __launch_bounds__(256) colstats2_kernel() {
    int j = blockIdx.x * 256 + threadIdx.x;
    int z = blockIdx.y;
    float s = 0.0f;
    #pragma unroll
    for (int c = 0; c < NCHUNK; c++)
        s += g_ps[((size_t)z * NCHUNK + c) * SEQ + j];
    g_csi[(size_t)z * SEQ + j] = 1.0f / s;
}

// ---------------- rowsum: rinv[i] = 1 / sum_j E[i,j]*csi[j] (read-only over E) ----
__global__ void __launch_bounds__(256) rowsum_kernel() {
    int i = blockIdx.x;
    int z = blockIdx.y;
    int t = threadIdx.x;
    const __half* row = g_e + ((size_t)z * SEQ + i) * SEQ;
    const float* ci = g_csi + (size_t)z * SEQ;
    float acc = 0.0f;
    #pragma unroll
    for (int j2 = t; j2 < SEQ / 2; j2 += 256) {
        int j = j2 * 2;
        __half2 e2 = *(const __half2*)(row + j);
        float2 c2 = *(const float2*)(ci + j);
        acc += __half2float(__low2half(e2))  * c2.x
             + __half2float(__high2half(e2)) * c2.y;
    }
    __shared__ float sh[8];
    #pragma unroll
    for (int o = 16; o > 0; o >>= 1)
        acc += __shfl_down_sync(0xffffffffu, acc, o);
    if ((t & 31) == 0) sh[t >> 5] = acc;
    __syncthreads();
    if (t == 0) {
        float s = 0.0f;
        #pragma unroll
        for (int w = 0; w < 8; w++) s += sh[w];
        g_rinv[(size_t)z * SEQ + i] = 1.0f / s;
    }
}

// ---------------- launch ----------------
extern "C" void kernel_launch(void* const* d_in, const int* in_sizes, int n_in,
                              void* d_out, int out_size) {
    const float* inputs  = (const float*)d_in[0];
    const float* context = (const float*)d_in[1];
    const float* gin  = (const float*)d_in[2];
    const float* bin  = (const float*)d_in[3];
    const float* gctx = (const float*)d_in[4];
    const float* bctx = (const float*)d_in[5];
    const float* Wq = (const float*)d_in[6];
    const float* bq = (const float*)d_in[7];
    const float* Wk = (const float*)d_in[8];
    const float* bk = (const float*)d_in[9];
    const float* Wv = (const float*)d_in[10];
    const float* bv = (const float*)d_in[11];
    float* out = (float*)d_out;

    __half *xc, *wqk, *wvt, *qk, *vt, *e;
    float *rinv, *bqk, *csi;
    cudaGetSymbolAddress((void**)&xc,   g_xc);
    cudaGetSymbolAddress((void**)&wqk,  g_wqk);
    cudaGetSymbolAddress((void**)&wvt,  g_wvt);
    cudaGetSymbolAddress((void**)&qk,   g_qk);
    cudaGetSymbolAddress((void**)&vt,   g_vt);
    cudaGetSymbolAddress((void**)&e,    g_e);
    cudaGetSymbolAddress((void**)&rinv, g_rinv);
    cudaGetSymbolAddress((void**)&bqk,  g_bqk);
    cudaGetSymbolAddress((void**)&csi,  g_csi);

    cudaFuncSetAttribute(gemm_h, cudaFuncAttributeMaxDynamicSharedMemorySize, GEMM_DSMEM);

    // LayerNorms (merged) + bias pack + weight transposes
    packbias_kernel<<<1, 512>>>(bq, bk);
    ln_kernel<<<2 * NR, 128>>>(inputs, context, gin, bin, gctx, bctx);
    {
        dim3 g(DIM / 32, DIM / 32, 1);
        tsplit_kernel<<<g, 256>>>(Wq, wqk);
        tsplit_kernel<<<g, 256>>>(Wk, wqk + (size_t)DIM * DIM);
        tsplit_kernel<<<g, 256>>>(Wv, wvt);
    }

    // q & k in one batched GEMM: z=0 -> q(xn,Wq,bq), z=1 -> k(cn,Wk,bk)
    {
        dim3 grid(DIM / 128, NR / 256, 2);
        gemm_h<<<grid, 256, GEMM_DSMEM>>>(xc, wqk, NR, DIM, DIM,
                                          (size_t)NR * DIM, (size_t)DIM * DIM,
                                          (size_t)NR * DIM,
                                          1.0f, bqk, DIM, nullptr, nullptr,
                                          nullptr, 0, nullptr, qk, 5);
    }

    // E = exp(scale * q @ k^T) fp16 + fused column sums
    {
        float scale = 1.0f / sqrtf((float)DIM);
        dim3 grid(SEQ / 128, SEQ / 256, BATCH);
        gemm_h<<<grid, 256, GEMM_DSMEM>>>(qk, qk + (size_t)NR * DIM, SEQ, SEQ, DIM,
                                          (size_t)SEQ * DIM, (size_t)SEQ * DIM,
                                          (size_t)SEQ * SEQ, scale,
                                          nullptr, 0, nullptr, nullptr,
                                          nullptr, 0, nullptr, e, 6);
    }

    // csi = 1/colsum
    colstats2_kernel<<<dim3(SEQ / 256, BATCH), 256>>>();

    // vt'[d,j] = (cn@Wv + bv)^T * csi[z,j] (M=512, N=2048, Kc=512, batched over b)
    {
        dim3 grid(SEQ / 128, DIM / 256, BATCH);
        gemm_h<<<grid, 256, GEMM_DSMEM>>>(wvt, xc + (size_t)NR * DIM, DIM, SEQ, DIM,
                                          0, (size_t)SEQ * DIM, (size_t)DIM * SEQ,
                                          1.0f, nullptr, 0, bv, nullptr,
                                          csi, SEQ, nullptr, vt, 5);
    }

    // rinv[i] = 1 / sum_j E[i,j]*csi[j]
    rowsum_kernel<<<dim3(SEQ, BATCH), 256>>>();

    // out = rinv[i] * (E @ vt'^T) (M=2048, N=512, Kc=2048, batched)
    {
        dim3 grid(DIM / 128, SEQ / 256, BATCH);
        gemm_h<<<grid, 256, GEMM_DSMEM>>>(e, vt, SEQ, DIM, SEQ,
                                          (size_t)SEQ * SEQ, (size_t)DIM * SEQ,
                                          (size_t)SEQ * DIM, 1.0f,
                                          nullptr, 0, nullptr, rinv,
                                          nullptr, 0, out, nullptr, 0);
    }
}

// round 13
// speedup vs baseline: 12.5261x; 1.0374x over previous
#include <cuda_runtime.h>
#include <cuda_fp16.h>
#include <math.h>
#include <stdint.h>

#define BATCH 8
#define SEQ   2048
#define DIM   512
#define NCHUNK 8          // 256-row chunks of SEQ (dots M-tiles)
#define NR    (BATCH * SEQ)
#define LN_BLOCKS (NR)            // 2*NR rows, 2 rows per block
#define TS_BLOCKS 768             // 3 weights x 256 tiles

static const float LN_EPS_F = 1e-5f;

// ---------------- scratch (static device globals; no allocation) ----------------
__device__ __align__(256) __half g_xc [(size_t)2 * NR * DIM];   // [xn | cn]
__device__ __align__(256) __half g_wqk[(size_t)2 * DIM * DIM];  // [Wq^T | Wk^T]
__device__ __align__(256) __half g_wvt[(size_t)DIM * DIM];
__device__ __align__(256) __half g_qk [(size_t)2 * NR * DIM];   // [q | k]
__device__ __align__(256) __half g_vt [(size_t)BATCH * DIM * SEQ];  // vt' = vt * csi
__device__ __align__(256) __half g_e  [(size_t)BATCH * SEQ * SEQ];  // E = exp(dots*scale)
__device__ float g_ps  [BATCH * NCHUNK * SEQ];
__device__ float g_csi [BATCH * SEQ];
__device__ float g_rinv[BATCH * SEQ];
__device__ float g_bqk [2 * DIM];

// ---------------- PTX helpers (baseline compute_103-safe) ----------------
__device__ __forceinline__ uint32_t smem_u32(const void* p) {
    uint32_t a;
    asm("{ .reg .u64 t; cvta.to.shared.u64 t, %1; cvt.u32.u64 %0, t; }" : "=r"(a) : "l"(p));
    return a;
}
__device__ __forceinline__ void cp_async16(uint32_t d, const void* g) {
    asm volatile("cp.async.cg.shared.global [%0], [%1], 16;" :: "r"(d), "l"(g));
}
__device__ __forceinline__ void cp_commit() {
    asm volatile("cp.async.commit_group;" ::: "memory");
}
template <int N>
__device__ __forceinline__ void cp_wait() {
    asm volatile("cp.async.wait_group %0;" :: "n"(N) : "memory");
}
__device__ __forceinline__ void ldsm4(uint32_t& r0, uint32_t& r1, uint32_t& r2, uint32_t& r3,
                                      uint32_t addr) {
    asm volatile("ldmatrix.sync.aligned.m8n8.x4.shared.b16 {%0,%1,%2,%3}, [%4];"
                 : "=r"(r0), "=r"(r1), "=r"(r2), "=r"(r3) : "r"(addr));
}
__device__ __forceinline__ void mma16816(float* c, const uint32_t* a, uint32_t b0, uint32_t b1) {
    asm volatile(
        "mma.sync.aligned.m16n8k16.row.col.f32.f16.f16.f32 "
        "{%0,%1,%2,%3}, {%4,%5,%6,%7}, {%8,%9}, {%0,%1,%2,%3};"
        : "+f"(c[0]), "+f"(c[1]), "+f"(c[2]), "+f"(c[3])
        : "r"(a[0]), "r"(a[1]), "r"(a[2]), "r"(a[3]), "r"(b0), "r"(b1));
}

// ---------------- HMMA plain-fp16 GEMM, CTA tile 256x128, warp tile 64x64 ----
// C[M,N] = A[M,Kc] @ B[N,Kc]^T  (A,B fp16 K-major); M%256==0, N%128==0, Kc%32==0
// pattern 0: outf = (acc*alpha + bias_col + bias_row) * rowscale[z*M+row]
// pattern 5: outh = fp16((acc*alpha + bias_col + bias_row) * colscale)
// pattern 6: outh = fp16(exp(acc*alpha)); fused column sums -> g_ps (per 256-row chunk)
// bias_col[z*bias_zs + col]; colscale[z*cs_zs + col]
#define BK 32
#define STAGES 5
#define A_STAGE (256 * 80)
#define B_STAGE (128 * 80)
#define STAGE_BYTES (A_STAGE + B_STAGE)
#define GEMM_DSMEM (STAGES * STAGE_BYTES)

__global__ void __launch_bounds__(256, 1) gemm_h(
    const __half* __restrict__ A, const __half* __restrict__ B,
    int M, int N, int Kc,
    size_t sA, size_t sB, size_t sC,
    float alpha,
    const float* __restrict__ bias_col, int bias_zs,
    const float* __restrict__ bias_row,
    const float* __restrict__ rowscale,
    const float* __restrict__ colscale, int cs_zs,
    float* __restrict__ outf, __half* __restrict__ outh, int pattern)
{
    extern __shared__ char dyn[];
    uint32_t dynb = smem_u32(dyn);

    int z = blockIdx.z;
    const __half* Ab = A + (size_t)z * sA + (size_t)(blockIdx.y * 256) * Kc;
    const __half* Bb = B + (size_t)z * sB + (size_t)(blockIdx.x * 128) * Kc;
    int bm = blockIdx.y * 256;
    int bn = blockIdx.x * 128;

    int t = threadIdx.x;
    int wid = t >> 5, lane = t & 31;
    int wm = wid & 3;        // 4 warps over M (64 rows each)
    int wn = wid >> 2;       // 2 warps over N (64 cols each)

    float acc[4][8][4];
    #pragma unroll
    for (int i = 0; i < 4; i++)
        #pragma unroll
        for (int j = 0; j < 8; j++)
            #pragma unroll
            for (int r = 0; r < 4; r++) acc[i][j][r] = 0.0f;

    int nkb = Kc / BK;

    auto issue = [&](int kb) {
        int slot = kb % STAGES;
        uint32_t sa = dynb + slot * STAGE_BYTES;
        uint32_t sb = sa + A_STAGE;
        int kh = kb * BK;
        #pragma unroll
        for (int i = 0; i < 4; i++) {           // A: 256 rows x 32 k
            int idx = t + 256 * i;
            int row = idx >> 2, c = idx & 3;
            cp_async16(sa + row * 80 + c * 16, Ab + (size_t)row * Kc + kh + c * 8);
        }
        #pragma unroll
        for (int i = 0; i < 2; i++) {           // B: 128 rows x 32 k
            int idx = t + 256 * i;
            int row = idx >> 2, c = idx & 3;
            cp_async16(sb + row * 80 + c * 16, Bb + (size_t)row * Kc + kh + c * 8);
        }
    };

    issue(0); cp_commit();
    issue(1); cp_commit();
    issue(2); cp_commit();
    issue(3); cp_commit();

    uint32_t a_lane = (uint32_t)((wm * 64 + (lane & 15)) * 80 + ((lane >> 4) * 8) * 2);
    uint32_t b_lane = (uint32_t)(A_STAGE +
                       (wn * 64 + (lane & 7) + (lane >> 4) * 8) * 80 +
                       (((lane >> 3) & 1) * 8) * 2);

    cp_wait<2>();          // slots 0 and 1 ready
    __syncthreads();

    uint32_t af[2][4][4];  // A fragments, double buffered (4 x m16)
    uint32_t bf[2][4][4];  // B fragments, double buffered (4 x n16)

    {
        uint32_t s0 = dynb;
        #pragma unroll
        for (int mi = 0; mi < 4; mi++)
            ldsm4(af[0][mi][0], af[0][mi][1], af[0][mi][2], af[0][mi][3],
                  s0 + a_lane + mi * (16 * 80));
        #pragma unroll
        for (int g = 0; g < 4; g++)
            ldsm4(bf[0][g][0], bf[0][g][1], bf[0][g][2], bf[0][g][3],
                  s0 + b_lane + g * (16 * 80));
    }

    int p = 0;
    for (int kb = 0; kb < nkb; kb++) {
        if (kb + 4 < nkb) issue(kb + 4);
        cp_commit();
        uint32_t scur = dynb + (kb % STAGES) * STAGE_BYTES;
        uint32_t snxt = dynb + ((kb + 1) % STAGES) * STAGE_BYTES;

        // ---- ks = 0: prefetch (kb, ks1) into p^1, mma on p ----
        #pragma unroll
        for (int mi = 0; mi < 4; mi++)
            ldsm4(af[p^1][mi][0], af[p^1][mi][1], af[p^1][mi][2], af[p^1][mi][3],
                  scur + a_lane + mi * (16 * 80) + 32);
        #pragma unroll
        for (int g = 0; g < 4; g++)
            ldsm4(bf[p^1][g][0], bf[p^1][g][1], bf[p^1][g][2], bf[p^1][g][3],
                  scur + b_lane + g * (16 * 80) + 32);
        #pragma unroll
        for (int mi = 0; mi < 4; mi++)
            #pragma unroll
            for (int ni = 0; ni < 8; ni++)
                mma16816(acc[mi][ni], af[p][mi],
                         bf[p][ni >> 1][(ni & 1) * 2], bf[p][ni >> 1][(ni & 1) * 2 + 1]);
        p ^= 1;

        // ---- ks = 1: prefetch (kb+1, ks0) into p^1, mma on p ----
        if (kb + 1 < nkb) {
            #pragma unroll
            for (int mi = 0; mi < 4; mi++)
                ldsm4(af[p^1][mi][0], af[p^1][mi][1], af[p^1][mi][2], af[p^1][mi][3],
                      snxt + a_lane + mi * (16 * 80));
            #pragma unroll
            for (int g = 0; g < 4; g++)
                ldsm4(bf[p^1][g][0], bf[p^1][g][1], bf[p^1][g][2], bf[p^1][g][3],
                      snxt + b_lane + g * (16 * 80));
        }
        #pragma unroll
        for (int mi = 0; mi < 4; mi++)
            #pragma unroll
            for (int ni = 0; ni < 8; ni++)
                mma16816(acc[mi][ni], af[p][mi],
                         bf[p][ni >> 1][(ni & 1) * 2], bf[p][ni >> 1][(ni & 1) * 2 + 1]);
        p ^= 1;

        cp_wait<2>();
        __syncthreads();
    }

    // ---------------- store epilogue ----------------
    int r_lane = lane >> 2;
    int c_lane = (lane & 3) * 2;

    if (pattern == 6) {
        float csum[8][2];
        #pragma unroll
        for (int ni = 0; ni < 8; ni++) { csum[ni][0] = 0.0f; csum[ni][1] = 0.0f; }

        #pragma unroll
        for (int mi = 0; mi < 4; mi++) {
            #pragma unroll
            for (int ni = 0; ni < 8; ni++) {
                int row = bm + wm * 64 + mi * 16 + r_lane;
                int col = bn + wn * 64 + ni * 8 + c_lane;
                float* a4 = acc[mi][ni];
                #pragma unroll
                for (int h = 0; h < 2; h++) {
                    int rr = row + h * 8;
                    float e0 = __expf(a4[h * 2 + 0] * alpha);
                    float e1 = __expf(a4[h * 2 + 1] * alpha);
                    csum[ni][0] += e0;
                    csum[ni][1] += e1;
                    __half2 hh = __halves2half2(__float2half_rn(e0), __float2half_rn(e1));
                    *(__half2*)(outh + (size_t)z * sC + (size_t)rr * N + col) = hh;
                }
            }
        }
        // reduce over the 8 lane-rows (lane bits 2..4)
        #pragma unroll
        for (int o = 4; o < 32; o <<= 1)
            #pragma unroll
            for (int ni = 0; ni < 8; ni++) {
                csum[ni][0] += __shfl_xor_sync(0xffffffffu, csum[ni][0], o);
                csum[ni][1] += __shfl_xor_sync(0xffffffffu, csum[ni][1], o);
            }
        cp_wait<0>();
        __syncthreads();
        float* ssm = (float*)dyn;            // [4][128]
        if ((lane >> 2) == 0) {
            #pragma unroll
            for (int ni = 0; ni < 8; ni++) {
                int col = wn * 64 + ni * 8 + (lane & 3) * 2;
                ssm[wm * 128 + col]     = csum[ni][0];
                ssm[wm * 128 + col + 1] = csum[ni][1];
            }
        }
        __syncthreads();
        if (t < 128) {
            float s = ssm[t] + ssm[128 + t] + ssm[256 + t] + ssm[384 + t];
            g_ps[((size_t)z * NCHUNK + blockIdx.y) * SEQ + bn + t] = s;
        }
        return;
    }

    #pragma unroll
    for (int mi = 0; mi < 4; mi++) {
        #pragma unroll
        for (int ni = 0; ni < 8; ni++) {
            int row = bm + wm * 64 + mi * 16 + r_lane;
            int col = bn + wn * 64 + ni * 8 + c_lane;
            float* a4 = acc[mi][ni];
            float bc0 = bias_col ? bias_col[z * bias_zs + col]     : 0.0f;
            float bc1 = bias_col ? bias_col[z * bias_zs + col + 1] : 0.0f;
            float cs0 = colscale ? colscale[z * cs_zs + col]       : 1.0f;
            float cs1 = colscale ? colscale[z * cs_zs + col + 1]   : 1.0f;
            #pragma unroll
            for (int h = 0; h < 2; h++) {
                int rr = row + h * 8;
                float br = bias_row ? bias_row[rr] : 0.0f;
                float v0 = (a4[h * 2 + 0] * alpha + bc0 + br) * cs0;
                float v1 = (a4[h * 2 + 1] * alpha + bc1 + br) * cs1;
                if (pattern == 0) {
                    float rs = rowscale ? rowscale[(size_t)z * M + rr] : 1.0f;
                    float2 o = make_float2(v0 * rs, v1 * rs);
                    *(float2*)(outf + (size_t)z * sC + (size_t)rr * N + col) = o;
                } else {  // pattern 5: plain fp16
                    __half2 hh = __halves2half2(__float2half_rn(v0), __float2half_rn(v1));
                    *(__half2*)(outh + (size_t)z * sC + (size_t)rr * N + col) = hh;
                }
            }
        }
    }
}

// ---------------- unified prep: LN (2 rows/block) + 3 weight transposes + bias pack ----
__global__ void __launch_bounds__(256) prep_kernel(
    const float* __restrict__ xin, const float* __restrict__ cin,
    const float* __restrict__ gx, const float* __restrict__ bx,
    const float* __restrict__ gc, const float* __restrict__ bc,
    const float* __restrict__ Wq, const float* __restrict__ Wk,
    const float* __restrict__ Wv,
    const float* __restrict__ bq, const float* __restrict__ bk)
{
    int blk = blockIdx.x;
    if (blk < LN_BLOCKS) {
        // two LN rows per block: rows 2*blk, 2*blk+1 of combined [x | c]
        __shared__ float sh[2][8];
        int half = threadIdx.x >> 7;      // 0 or 1
        int t = threadIdx.x & 127;
        int row = blk * 2 + half;         // 0 .. 2*NR-1
        const float* x;
        const float* g;
        const float* b;
        __half* y;
        if (row < NR) {
            x = xin + (size_t)row * DIM; g = gx; b = bx;
            y = g_xc + (size_t)row * DIM;
        } else {
            int r2 = row - NR;
            x = cin + (size_t)r2 * DIM; g = gc; b = bc;
            y = g_xc + (size_t)NR * DIM + (size_t)r2 * DIM;
        }
        float4 v = ((const float4*)x)[t];
        float s  = v.x + v.y + v.z + v.w;
        float ss = v.x*v.x + v.y*v.y + v.z*v.z + v.w*v.w;
        #pragma unroll
        for (int o = 16; o > 0; o >>= 1) {
            s  += __shfl_down_sync(0xffffffffu, s, o);
            ss += __shfl_down_sync(0xffffffffu, ss, o);
        }
        if ((t & 31) == 0) { sh[half][t >> 5] = s; sh[half][4 + (t >> 5)] = ss; }
        __syncthreads();
        float fs  = sh[half][0] + sh[half][1] + sh[half][2] + sh[half][3];
        float fss = sh[half][4] + sh[half][5] + sh[half][6] + sh[half][7];
        float mu  = fs * (1.0f / DIM);
        float var = fss * (1.0f / DIM) - mu * mu;
        float rstd = rsqrtf(var + LN_EPS_F);
        float4 gv = ((const float4*)g)[t];
        float4 bv = ((const float4*)b)[t];
        float o0 = (v.x - mu) * rstd * gv.x + bv.x;
        float o1 = (v.y - mu) * rstd * gv.y + bv.y;
        float o2 = (v.z - mu) * rstd * gv.z + bv.z;
        float o3 = (v.w - mu) * rstd * gv.w + bv.w;
        ((__half2*)(y + t * 4))[0] = __halves2half2(__float2half_rn(o0), __float2half_rn(o1));
        ((__half2*)(y + t * 4))[1] = __halves2half2(__float2half_rn(o2), __float2half_rn(o3));
    } else if (blk < LN_BLOCKS + TS_BLOCKS) {
        // weight transpose tiles
        __shared__ float tile[32][33];
        int idx = blk - LN_BLOCKS;
        int which = idx >> 8;      // 0..2
        int tl = idx & 255;        // 16x16 tiles
        const float* in = (which == 0) ? Wq : (which == 1) ? Wk : Wv;
        __half* out = (which == 0) ? g_wqk
                    : (which == 1) ? (g_wqk + (size_t)DIM * DIM) : g_wvt;
        int r0 = (tl >> 4) * 32, c0 = (tl & 15) * 32;
        int tx = threadIdx.x & 31, ty = threadIdx.x >> 5;
        #pragma unroll
        for (int i = ty; i < 32; i += 8)
            tile[i][tx] = in[(size_t)(r0 + i) * DIM + c0 + tx];
        __syncthreads();
        #pragma unroll
        for (int i = ty; i < 32; i += 8)
            out[(size_t)(c0 + i) * DIM + r0 + tx] = __float2half_rn(tile[tx][i]);
    } else {
        // bias pack
        for (int t = threadIdx.x; t < DIM; t += 256) {
            g_bqk[t] = bq[t];
            g_bqk[DIM + t] = bk[t];
        }
    }
}

// ---------------- column sums combine -> 1/colsum ----------------
__global__ void __launch_bounds__(256) colstats2_kernel() {
    int j = blockIdx.x * 256 + threadIdx.x;
    int z = blockIdx.y;
    float s = 0.0f;
    #pragma unroll
    for (int c = 0; c < NCHUNK; c++)
        s += g_ps[((size_t)z * NCHUNK + c) * SEQ + j];
    g_csi[(size_t)z * SEQ + j] = 1.0f / s;
}

// ---------------- rowsum: rinv[i] = 1 / sum_j E[i,j]*csi[j] (read-only over E) ----
__global__ void __launch_bounds__(256) rowsum_kernel() {
    int i = blockIdx.x;
    int z = blockIdx.y;
    int t = threadIdx.x;
    const __half* row = g_e + ((size_t)z * SEQ + i) * SEQ;
    const float* ci = g_csi + (size_t)z * SEQ;
    float acc = 0.0f;
    #pragma unroll
    for (int j2 = t; j2 < SEQ / 2; j2 += 256) {
        int j = j2 * 2;
        __half2 e2 = *(const __half2*)(row + j);
        float2 c2 = *(const float2*)(ci + j);
        acc += __half2float(__low2half(e2))  * c2.x
             + __half2float(__high2half(e2)) * c2.y;
    }
    __shared__ float sh[8];
    #pragma unroll
    for (int o = 16; o > 0; o >>= 1)
        acc += __shfl_down_sync(0xffffffffu, acc, o);
    if ((t & 31) == 0) sh[t >> 5] = acc;
    __syncthreads();
    if (t == 0) {
        float s = 0.0f;
        #pragma unroll
        for (int w = 0; w < 8; w++) s += sh[w];
        g_rinv[(size_t)z * SEQ + i] = 1.0f / s;
    }
}

// ---------------- launch ----------------
extern "C" void kernel_launch(void* const* d_in, const int* in_sizes, int n_in,
                              void* d_out, int out_size) {
    const float* inputs  = (const float*)d_in[0];
    const float* context = (const float*)d_in[1];
    const float* gin  = (const float*)d_in[2];
    const float* bin  = (const float*)d_in[3];
    const float* gctx = (const float*)d_in[4];
    const float* bctx = (const float*)d_in[5];
    const float* Wq = (const float*)d_in[6];
    const float* bq = (const float*)d_in[7];
    const float* Wk = (const float*)d_in[8];
    const float* bk = (const float*)d_in[9];
    const float* Wv = (const float*)d_in[10];
    const float* bv = (const float*)d_in[11];
    float* out = (float*)d_out;

    __half *xc, *wqk, *wvt, *qk, *vt, *e;
    float *rinv, *bqk, *csi;
    cudaGetSymbolAddress((void**)&xc,   g_xc);
    cudaGetSymbolAddress((void**)&wqk,  g_wqk);
    cudaGetSymbolAddress((void**)&wvt,  g_wvt);
    cudaGetSymbolAddress((void**)&qk,   g_qk);
    cudaGetSymbolAddress((void**)&vt,   g_vt);
    cudaGetSymbolAddress((void**)&e,    g_e);
    cudaGetSymbolAddress((void**)&rinv, g_rinv);
    cudaGetSymbolAddress((void**)&bqk,  g_bqk);
    cudaGetSymbolAddress((void**)&csi,  g_csi);

    cudaFuncSetAttribute(gemm_h, cudaFuncAttributeMaxDynamicSharedMemorySize, GEMM_DSMEM);

    // one-time stream/event creation (host-side resources only; no device memory)
    static cudaStream_t s2 = nullptr;
    static cudaEvent_t evFork = nullptr, evJoin = nullptr;
    if (!s2) {
        cudaStreamCreateWithFlags(&s2, cudaStreamNonBlocking);
        cudaEventCreateWithFlags(&evFork, cudaEventDisableTiming);
        cudaEventCreateWithFlags(&evJoin, cudaEventDisableTiming);
    }

    // unified prep: LN + weight transposes + bias pack
    prep_kernel<<<LN_BLOCKS + TS_BLOCKS + 1, 256>>>(
        inputs, context, gin, bin, gctx, bctx, Wq, Wk, Wv, bq, bk);

    // q & k in one batched GEMM: z=0 -> q(xn,Wq,bq), z=1 -> k(cn,Wk,bk)
    {
        dim3 grid(DIM / 128, NR / 256, 2);
        gemm_h<<<grid, 256, GEMM_DSMEM>>>(xc, wqk, NR, DIM, DIM,
                                          (size_t)NR * DIM, (size_t)DIM * DIM,
                                          (size_t)NR * DIM,
                                          1.0f, bqk, DIM, nullptr, nullptr,
                                          nullptr, 0, nullptr, qk, 5);
    }

    // E = exp(scale * q @ k^T) fp16 + fused column sums
    {
        float scale = 1.0f / sqrtf((float)DIM);
        dim3 grid(SEQ / 128, SEQ / 256, BATCH);
        gemm_h<<<grid, 256, GEMM_DSMEM>>>(qk, qk + (size_t)NR * DIM, SEQ, SEQ, DIM,
                                          (size_t)SEQ * DIM, (size_t)SEQ * DIM,
                                          (size_t)SEQ * SEQ, scale,
                                          nullptr, 0, nullptr, nullptr,
                                          nullptr, 0, nullptr, e, 6);
    }

    // csi = 1/colsum
    colstats2_kernel<<<dim3(SEQ / 256, BATCH), 256>>>();

    // fork: vt' GEMM on s2 concurrent with rowsum on main stream
    cudaEventRecord(evFork, 0);
    cudaStreamWaitEvent(s2, evFork, 0);
    {
        dim3 grid(SEQ / 128, DIM / 256, BATCH);
        gemm_h<<<grid, 256, GEMM_DSMEM, s2>>>(wvt, xc + (size_t)NR * DIM, DIM, SEQ, DIM,
                                              0, (size_t)SEQ * DIM, (size_t)DIM * SEQ,
                                              1.0f, nullptr, 0, bv, nullptr,
                                              csi, SEQ, nullptr, vt, 5);
    }
    cudaEventRecord(evJoin, s2);

    // rinv[i] = 1 / sum_j E[i,j]*csi[j]  (main stream, concurrent with vt')
    rowsum_kernel<<<dim3(SEQ, BATCH), 256>>>();

    cudaStreamWaitEvent(0, evJoin, 0);

    // out = rinv[i] * (E @ vt'^T) (M=2048, N=512, Kc=2048, batched)
    {
        dim3 grid(DIM / 128, SEQ / 256, BATCH);
        gemm_h<<<grid, 256, GEMM_DSMEM>>>(e, vt, SEQ, DIM, SEQ,
                                          (size_t)SEQ * SEQ, (size_t)DIM * SEQ,
                                          (size_t)SEQ * DIM, 1.0f,
                                          nullptr, 0, nullptr, rinv,
                                          nullptr, 0, out, nullptr, 0);
    }
}